// round 9
// baseline (speedup 1.0000x reference)
#include <cuda_runtime.h>
#include <math.h>

#define Bn 256
#define Tn 100
#define Fn 256
#define Hn 512
#define NB 128
#define NT 256
#define BT (Bn * Tn)
#define STW 8192                   // stage words: A 4096 + B 4096
#define NSTG 4
#define EPIT 68
#define SMEM_WORDS (NSTG * STW + 256)
#define SMEM_BYTES (SMEM_WORDS * 4)
#define BTF ((size_t)Bn * Tn * Fn)

// ---------------- global scratch (allocation-free rule) ----------------
__device__ unsigned g_dtq[(size_t)400 * 4 * 4096];   // deltas quads, bt-tiles
__device__ unsigned g_gxmq[(size_t)400 * 8 * 4096];  // [gamma_x | mask] quads
__device__ unsigned g_Wtdhq[8 * 4 * 4096];
__device__ unsigned g_Wcombq[4 * 8 * 4096];
__device__ unsigned g_Whistq[8 * 8 * 2048];
__device__ unsigned g_Wfeatq[8 * 4 * 2048];
__device__ unsigned g_Wgq[32 * 16 * 4096];           // gates W, rows j*4+gate, k [ih|hh]
__device__ float    g_gate_base[(size_t)BT * 2048];  // mask@Wm^T + biases (hoisted)
__device__ unsigned g_hq[2 * 4 * 8 * 4096];          // h_dec quads (double buffer)
__device__ unsigned g_xcq[4 * 4 * 4096];
__device__ unsigned g_ccq[4 * 4 * 4096];
__device__ float g_gamma_h[(size_t)BT * Hn];
__device__ float g_alpha[(size_t)BT * Fn];
__device__ float g_bg[4 * Hn];
__device__ float g_xh[Bn * Fn];
__device__ float g_cst[Bn * Hn];
__device__ float g_l1[Tn * 32], g_l2[Tn * 32], g_l3[Tn * 32], g_den[Tn * 32];
__device__ unsigned g_cnt, g_sense;
__device__ unsigned g_cnt_h[4], g_cnt_xh[4], g_cnt_cc[4];

__device__ __forceinline__ float sigmoidf_(float x) { return 1.0f / (1.0f + expf(-x)); }

__device__ __forceinline__ unsigned f2tf(float f) {
    unsigned u;
    asm("cvt.rna.tf32.f32 %0, %1;" : "=r"(u) : "f"(f));
    return u;
}

// quad layouts (validated in rounds 7/8)
__device__ __forceinline__ int o_A(int r, int k) {
    return ((r >> 4) * 8 + (k >> 3)) * 128 + ((r & 7) * 4 + (k & 3)) * 4 +
           ((k & 4) >> 1) + ((r & 8) >> 3);
}
__device__ __forceinline__ int o_B(int n, int k) {
    return ((n >> 4) * 8 + (k >> 3)) * 128 + ((n & 7) * 4 + (k & 3)) * 4 +
           ((n >> 3) & 1) * 2 + ((k >> 2) & 1);
}

#define MMA(d, A0, A1, A2, A3, B0, B1)                                          \
    asm volatile("mma.sync.aligned.m16n8k8.row.col.f32.tf32.tf32.f32 "          \
                 "{%0,%1,%2,%3},{%4,%5,%6,%7},{%8,%9},{%0,%1,%2,%3};"           \
                 : "+f"(d[0]), "+f"(d[1]), "+f"(d[2]), "+f"(d[3])               \
                 : "r"(A0), "r"(A1), "r"(A2), "r"(A3), "r"(B0), "r"(B1))

#define CPA(boff, p)                                                            \
    asm volatile("cp.async.cg.shared.global [%0], [%1], 16;"                    \
                 :: "r"(sbase + (unsigned)(boff)), "l"(p) : "memory")
#define CMT   asm volatile("cp.async.commit_group;" ::: "memory")
#define WAIT2 asm volatile("cp.async.wait_group 2;" ::: "memory")

// 64x64 stage: A 4096 + B 4096 words, linear copy (256 thr -> 8 CP16 each)
#define LOADQ64(pA, pB, s) do {                                                 \
    unsigned _off = (unsigned)((s) * STW * 4);                                  \
    _Pragma("unroll")                                                           \
    for (int _j = 0; _j < 4; _j++) { int _c = tid + _j * 256;                   \
        CPA(_off + (unsigned)_c * 16u, (pA) + _c * 4);                          \
        CPA(_off + 16384u + (unsigned)_c * 16u, (pB) + _c * 4); }               \
} while (0)
// 64x32 stage: A 4096 + B 2048 words
#define LOADQ32(pA, pB, s) do {                                                 \
    unsigned _off = (unsigned)((s) * STW * 4);                                  \
    _Pragma("unroll")                                                           \
    for (int _j = 0; _j < 4; _j++) { int _c = tid + _j * 256;                   \
        CPA(_off + (unsigned)_c * 16u, (pA) + _c * 4); }                        \
    _Pragma("unroll")                                                           \
    for (int _j = 0; _j < 2; _j++) { int _c = tid + _j * 256;                   \
        CPA(_off + 16384u + (unsigned)_c * 16u, (pB) + _c * 4); }               \
} while (0)

// ---------------- sync primitives (proven) ----------------
__device__ __forceinline__ void gsync(unsigned& sense) {
    __threadfence();
    __syncthreads();
    unsigned target = sense ^ 1u;
    if (threadIdx.x == 0) {
        unsigned old = atomicAdd(&g_cnt, 1u);
        if (old == NB - 1) {
            g_cnt = 0;
            __threadfence();
            atomicExch(&g_sense, target);
        } else {
            while (atomicAdd(&g_sense, 0u) != target) { __nanosleep(128); }
        }
        __threadfence();
    }
    sense = target;
    __syncthreads();
}
__device__ __forceinline__ void wait_ge(unsigned* cnt, unsigned target) {
    if (threadIdx.x == 0) {
        while (atomicAdd(cnt, 0u) < target) { __nanosleep(64); }
        __threadfence();
    }
    __syncthreads();
}
__device__ __forceinline__ void arrive(unsigned* cnt) {
    __threadfence();
    __syncthreads();
    if (threadIdx.x == 0) atomicAdd(cnt, 1u);
}
__device__ __forceinline__ float wredsum(float v) {
#pragma unroll
    for (int o = 16; o; o >>= 1) v += __shfl_xor_sync(0xffffffffu, v, o);
    return v;
}

// ---------------- 32x32-warp-tile MMA bodies with k-split ----------------
// 64x64 CTA tile: warp quad (wm,wn) in 2x2, kw in {0,1}: ks = kw*4+kk
__device__ __forceinline__ void mmaK2(const unsigned* As, const unsigned* Bs,
                                      float acc[2][4][4], int wm, int wn, int kw, int lane) {
#pragma unroll
    for (int kk = 0; kk < 4; kk++) {
        int ks = kw * 4 + kk;
        uint4 a0 = *(const uint4*)&As[(((wm * 2 + 0) * 8 + ks) * 32 + lane) * 4];
        uint4 a1 = *(const uint4*)&As[(((wm * 2 + 1) * 8 + ks) * 32 + lane) * 4];
        uint4 b0 = *(const uint4*)&Bs[(((wn * 2 + 0) * 8 + ks) * 32 + lane) * 4];
        uint4 b1 = *(const uint4*)&Bs[(((wn * 2 + 1) * 8 + ks) * 32 + lane) * 4];
        MMA(acc[0][0], a0.x, a0.y, a0.z, a0.w, b0.x, b0.y);
        MMA(acc[0][1], a0.x, a0.y, a0.z, a0.w, b0.z, b0.w);
        MMA(acc[0][2], a0.x, a0.y, a0.z, a0.w, b1.x, b1.y);
        MMA(acc[0][3], a0.x, a0.y, a0.z, a0.w, b1.z, b1.w);
        MMA(acc[1][0], a1.x, a1.y, a1.z, a1.w, b0.x, b0.y);
        MMA(acc[1][1], a1.x, a1.y, a1.z, a1.w, b0.z, b0.w);
        MMA(acc[1][2], a1.x, a1.y, a1.z, a1.w, b1.x, b1.y);
        MMA(acc[1][3], a1.x, a1.y, a1.z, a1.w, b1.z, b1.w);
    }
}
// 64x32 CTA tile: tm in {0,1}, kw in {0..3}: ks = kw*2+kk
__device__ __forceinline__ void mmaK4(const unsigned* As, const unsigned* Bs,
                                      float acc[2][4][4], int tm, int kw, int lane) {
#pragma unroll
    for (int kk = 0; kk < 2; kk++) {
        int ks = kw * 2 + kk;
        uint4 a0 = *(const uint4*)&As[(((tm * 2 + 0) * 8 + ks) * 32 + lane) * 4];
        uint4 a1 = *(const uint4*)&As[(((tm * 2 + 1) * 8 + ks) * 32 + lane) * 4];
        uint4 b0 = *(const uint4*)&Bs[((0 * 8 + ks) * 32 + lane) * 4];
        uint4 b1 = *(const uint4*)&Bs[((1 * 8 + ks) * 32 + lane) * 4];
        MMA(acc[0][0], a0.x, a0.y, a0.z, a0.w, b0.x, b0.y);
        MMA(acc[0][1], a0.x, a0.y, a0.z, a0.w, b0.z, b0.w);
        MMA(acc[0][2], a0.x, a0.y, a0.z, a0.w, b1.x, b1.y);
        MMA(acc[0][3], a0.x, a0.y, a0.z, a0.w, b1.z, b1.w);
        MMA(acc[1][0], a1.x, a1.y, a1.z, a1.w, b0.x, b0.y);
        MMA(acc[1][1], a1.x, a1.y, a1.z, a1.w, b0.z, b0.w);
        MMA(acc[1][2], a1.x, a1.y, a1.z, a1.w, b1.x, b1.y);
        MMA(acc[1][3], a1.x, a1.y, a1.z, a1.w, b1.z, b1.w);
    }
}

// k-split reductions through smem (stages are dead by the first sync)
__device__ __forceinline__ void reduce2(float acc[2][4][4], float* buf,
                                        int tileid, int kw, int lane) {
    __syncthreads();
    if (kw == 1) {
        float* p = buf + tileid * 1024 + lane * 32;
#pragma unroll
        for (int mi = 0; mi < 2; mi++)
#pragma unroll
            for (int nf = 0; nf < 4; nf++)
#pragma unroll
                for (int e = 0; e < 4; e++) p[mi * 16 + nf * 4 + e] = acc[mi][nf][e];
    }
    __syncthreads();
    if (kw == 0) {
        const float* p = buf + tileid * 1024 + lane * 32;
#pragma unroll
        for (int mi = 0; mi < 2; mi++)
#pragma unroll
            for (int nf = 0; nf < 4; nf++)
#pragma unroll
                for (int e = 0; e < 4; e++) acc[mi][nf][e] += p[mi * 16 + nf * 4 + e];
    }
    __syncthreads();
}
__device__ __forceinline__ void reduce4(float acc[2][4][4], float* buf,
                                        int tm, int kw, int lane) {
    __syncthreads();
    if (kw > 0) {
        float* p = buf + ((kw - 1) * 2 + tm) * 1024 + lane * 32;
#pragma unroll
        for (int mi = 0; mi < 2; mi++)
#pragma unroll
            for (int nf = 0; nf < 4; nf++)
#pragma unroll
                for (int e = 0; e < 4; e++) p[mi * 16 + nf * 4 + e] = acc[mi][nf][e];
    }
    __syncthreads();
    if (kw == 0) {
#pragma unroll
        for (int q = 0; q < 3; q++) {
            const float* p = buf + (q * 2 + tm) * 1024 + lane * 32;
#pragma unroll
            for (int mi = 0; mi < 2; mi++)
#pragma unroll
                for (int nf = 0; nf < 4; nf++)
#pragma unroll
                    for (int e = 0; e < 4; e++) acc[mi][nf][e] += p[mi * 16 + nf * 4 + e];
        }
    }
    __syncthreads();
}

__device__ __forceinline__ const unsigned* pcA(int g, int t, int par, int kc) {
    if (kc < 4) return g_ccq + ((size_t)g * 4 + kc) * 4096;
    return g_hq + (((size_t)par * 4 + g) * 8 + (kc - 4)) * 4096;
}

__global__ void __launch_bounds__(NT, 1) rits_kernel(
    const float* __restrict__ values, const float* __restrict__ masks,
    const float* __restrict__ deltas,
    const float* __restrict__ W_td_h, const float* __restrict__ b_td_h,
    const float* __restrict__ W_td_x, const float* __restrict__ b_td_x,
    const float* __restrict__ W_hist, const float* __restrict__ b_hist,
    const float* __restrict__ W_feat, const float* __restrict__ b_feat,
    const float* __restrict__ W_comb, const float* __restrict__ b_comb,
    const float* __restrict__ W_ih, const float* __restrict__ W_hh,
    const float* __restrict__ b_ih, const float* __restrict__ b_hh,
    float* __restrict__ out)
{
    extern __shared__ unsigned SHu[];
    float* RED = (float*)(SHu + NSTG * STW);
    unsigned sbase = (unsigned)__cvta_generic_to_shared(SHu);

    const int tid = threadIdx.x;
    const int cta = blockIdx.x;
    const int wid = tid >> 5;
    const int lane = tid & 31;
    const int gid = lane >> 2;
    const int tg = lane & 3;
    // 64x64 phases: warp quad + 2-way k-split
    const int wm = wid & 1, wn = (wid >> 1) & 1, kw2 = wid >> 2;
    // 64x32 phases: tile row + 4-way k-split
    const int tm = wid & 1, kw4 = wid >> 1;

    const int g = cta >> 5;
    const int cg = cta & 31;
    const int b0 = g * 64;

    unsigned sense = *((volatile unsigned*)&g_sense);

    // =================== init: state + tf32 quad pre-conversion ===================
    for (int i = cta * NT + tid; i < Bn * Hn; i += NB * NT) g_cst[i] = 0.0f;
    for (int i = cta * NT + tid; i < 2 * 4 * 8 * 4096; i += NB * NT) g_hq[i] = 0u;

    for (int i4 = cta * NT + tid; i4 < BT * Fn / 4; i4 += NB * NT) {
        int bt = i4 >> 6;
        int f0 = (i4 & 63) * 4;
        float4 d = ((const float4*)deltas)[i4];
        float4 mk = ((const float4*)masks)[i4];
        int u = bt >> 6, r = bt & 63;
        float dv[4] = {d.x, d.y, d.z, d.w};
        float mv[4] = {mk.x, mk.y, mk.z, mk.w};
#pragma unroll
        for (int q = 0; q < 4; q++) {
            int f = f0 + q;
            int kc = f >> 6, k = f & 63;
            int oa = o_A(r, k);
            float gx = expf(-fmaxf(fmaf(dv[q], W_td_x[f * Fn + f], b_td_x[f]), 0.f));
            g_dtq[((size_t)u * 4 + kc) * 4096 + oa] = f2tf(dv[q]);
            g_gxmq[((size_t)u * 8 + kc) * 4096 + oa] = f2tf(gx);
            g_gxmq[((size_t)u * 8 + 4 + kc) * 4096 + oa] = f2tf(mv[q]);
        }
    }
    for (int i = cta * NT + tid; i < 512 * 256; i += NB * NT) {
        int n = i >> 8, k = i & 255;
        g_Wtdhq[((n >> 6) * 4 + (k >> 6)) * 4096 + o_B(n & 63, k & 63)] = f2tf(W_td_h[i]);
    }
    for (int i = cta * NT + tid; i < 256 * 512; i += NB * NT) {
        int n = i >> 9, k = i & 511;
        g_Wcombq[((n >> 6) * 8 + (k >> 6)) * 4096 + o_B(n & 63, k & 63)] = f2tf(W_comb[i]);
        g_Whistq[((n >> 5) * 8 + (k >> 6)) * 2048 + o_B(n & 31, k & 63)] = f2tf(W_hist[i]);
    }
    for (int i = cta * NT + tid; i < 256 * 256; i += NB * NT) {
        int n = i >> 8, k = i & 255;
        float w = (n == k) ? 0.0f : W_feat[i];
        g_Wfeatq[((n >> 5) * 4 + (k >> 6)) * 2048 + o_B(n & 31, k & 63)] = f2tf(w);
    }
    for (int i = cta * NT + tid; i < 2048 * 1024; i += NB * NT) {
        int np = i >> 10, k = i & 1023;
        int j = np >> 2, gate = np & 3;
        float w = (k < 512) ? W_ih[(size_t)(gate * Hn + j) * 512 + k]
                            : W_hh[(size_t)(gate * Hn + j) * 512 + (k - 512)];
        g_Wgq[((np >> 6) * 16 + (k >> 6)) * 4096 + o_B(np & 63, k & 63)] = f2tf(w);
    }
    for (int i = cta * NT + tid; i < 4 * Hn; i += NB * NT) {
        int j = i >> 2, gate = i & 3;
        g_bg[i] = b_ih[gate * Hn + j] + b_hh[gate * Hn + j];
    }
    gsync(sense);

    // ========== precompute: gamma_h (3200) + alpha (1600) + mask-gates (12800) ==========
    for (int tt = cta; tt < 17600; tt += NB) {
        float acc[2][4][4];
#pragma unroll
        for (int mi = 0; mi < 2; mi++)
#pragma unroll
            for (int nf = 0; nf < 4; nf++)
#pragma unroll
                for (int e = 0; e < 4; e++) acc[mi][nf][e] = 0.0f;

        int kind, ut, nt, NI;
        const unsigned *Asrc, *Bsrc;
        if (tt < 3200) {
            kind = 0; ut = tt >> 3; nt = tt & 7; NI = 4;
            Asrc = g_dtq + (size_t)ut * 4 * 4096;
            Bsrc = g_Wtdhq + (size_t)nt * 4 * 4096;
        } else if (tt < 4800) {
            int u = tt - 3200;
            kind = 1; ut = u >> 2; nt = u & 3; NI = 8;
            Asrc = g_gxmq + (size_t)ut * 8 * 4096;
            Bsrc = g_Wcombq + (size_t)nt * 8 * 4096;
        } else {
            int u = tt - 4800;
            kind = 2; ut = u >> 5; nt = u & 31; NI = 4;
            Asrc = g_gxmq + (size_t)ut * 8 * 4096 + 4 * 4096;    // mask chunks
            Bsrc = g_Wgq + ((size_t)nt * 16 + 4) * 4096;         // W_ih[:,256:512]
        }
        const int m0 = ut * 64, n0 = nt * 64;

        LOADQ64(Asrc, Bsrc, 0); CMT;
        LOADQ64(Asrc + 4096, Bsrc + 4096, 1); CMT;
        LOADQ64(Asrc + 8192, Bsrc + 8192, 2); CMT;
        for (int i = 0; i < NI; i++) {
            WAIT2;
            __syncthreads();
            if (i + 3 < NI)
                LOADQ64(Asrc + (size_t)(i + 3) * 4096, Bsrc + (size_t)(i + 3) * 4096, (i + 3) & 3);
            CMT;
            int s = i & 3;
            mmaK2(SHu + s * STW, SHu + s * STW + 4096, acc, wm, wn, kw2, lane);
        }
        reduce2(acc, (float*)SHu, wm * 2 + wn, kw2, lane);
        if (kw2 == 0) {
#pragma unroll
            for (int mi = 0; mi < 2; mi++) {
#pragma unroll
                for (int nf = 0; nf < 4; nf++) {
#pragma unroll
                    for (int e = 0; e < 4; e++) {
                        int bt = m0 + wm * 32 + mi * 16 + gid + ((e >> 1) << 3);
                        int n = n0 + wn * 32 + nf * 8 + 2 * tg + (e & 1);
                        float v = acc[mi][nf][e];
                        if (kind == 0)
                            g_gamma_h[(size_t)bt * Hn + n] = expf(-fmaxf(v + b_td_h[n], 0.f));
                        else if (kind == 1)
                            g_alpha[(size_t)bt * Fn + n] = sigmoidf_(v + b_comb[n]);
                        else
                            g_gate_base[(size_t)bt * 2048 + n] = v + g_bg[n];
                    }
                }
            }
        }
        __syncthreads();
    }
    gsync(sense);

    // =================== sequential recurrence (dataflow-synced, 4 groups) ===================
    for (int t = 0; t < Tn; t++) {
        const int par = t & 1, nxt = (t + 1) & 1;

        // ===== P_a: x_h = h_dec @ W_hist^T  (tile 64x32, K=512), CTAs cg<8 =====
        if (cg < 8) {
            const int n0 = cg * 32;
            wait_ge(&g_cnt_h[g], 32u * (unsigned)t);
            const unsigned* Ah = g_hq + (((size_t)par * 4 + g) * 8) * 4096;
            const unsigned* Bw = g_Whistq + (size_t)cg * 8 * 2048;
            float acc[2][4][4];
#pragma unroll
            for (int mi = 0; mi < 2; mi++)
#pragma unroll
                for (int nf = 0; nf < 4; nf++)
#pragma unroll
                    for (int e = 0; e < 4; e++) acc[mi][nf][e] = 0.0f;
            LOADQ32(Ah, Bw, 0); CMT;
            LOADQ32(Ah + 4096, Bw + 2048, 1); CMT;
            LOADQ32(Ah + 8192, Bw + 4096, 2); CMT;
            for (int i = 0; i < 8; i++) {
                WAIT2;
                __syncthreads();
                if (i + 3 < 8)
                    LOADQ32(Ah + (size_t)(i + 3) * 4096, Bw + (size_t)(i + 3) * 2048, (i + 3) & 3);
                CMT;
                int s = i & 3;
                mmaK4(SHu + s * STW, SHu + s * STW + 4096, acc, tm, kw4, lane);
            }
            reduce4(acc, (float*)SHu, tm, kw4, lane);
            if (kw4 == 0) {
                float ls = 0.0f;
#pragma unroll
                for (int mi = 0; mi < 2; mi++) {
#pragma unroll
                    for (int nf = 0; nf < 4; nf++) {
#pragma unroll
                        for (int e = 0; e < 4; e++) {
                            int r = tm * 32 + mi * 16 + gid + ((e >> 1) << 3);
                            int b = b0 + r;
                            int f = n0 + nf * 8 + 2 * tg + (e & 1);
                            float xh = acc[mi][nf][e] + b_hist[f];
                            g_xh[b * Fn + f] = xh;
                            size_t vi = ((size_t)b * Tn + t) * Fn + f;
                            float x = values[vi], m = masks[vi];
                            ls += fabsf(xh - x) * m;
                            g_xcq[((size_t)g * 4 + (f >> 6)) * 4096 + o_A(r, f & 63)] =
                                f2tf(m * x + (1.0f - m) * xh);
                        }
                    }
                }
                ls = wredsum(ls);
                if (lane == 0) RED[wid] = ls;
            }
            __syncthreads();
            if (tid == 0) g_l1[t * 32 + g * 8 + cg] = RED[0] + RED[1];
            arrive(&g_cnt_xh[g]);
        }

        // ===== P_b: z_h = relu(x_c @ Wf^T) (tile 64x32, K=256) + epilogue =====
        if (cg < 8) {
            const int n0 = cg * 32;
            wait_ge(&g_cnt_xh[g], 8u * (unsigned)(t + 1));
            const unsigned* Ax = g_xcq + (size_t)g * 4 * 4096;
            const unsigned* Bf = g_Wfeatq + (size_t)cg * 4 * 2048;
            float acc[2][4][4];
#pragma unroll
            for (int mi = 0; mi < 2; mi++)
#pragma unroll
                for (int nf = 0; nf < 4; nf++)
#pragma unroll
                    for (int e = 0; e < 4; e++) acc[mi][nf][e] = 0.0f;
            LOADQ32(Ax, Bf, 0); CMT;
            LOADQ32(Ax + 4096, Bf + 2048, 1); CMT;
            LOADQ32(Ax + 8192, Bf + 4096, 2); CMT;
            for (int i = 0; i < 4; i++) {
                WAIT2;
                __syncthreads();
                if (i + 3 < 4)
                    LOADQ32(Ax + (size_t)(i + 3) * 4096, Bf + (size_t)(i + 3) * 2048, (i + 3) & 3);
                CMT;
                int s = i & 3;
                mmaK4(SHu + s * STW, SHu + s * STW + 4096, acc, tm, kw4, lane);
            }
            reduce4(acc, (float*)SHu, tm, kw4, lane);
            if (kw4 == 0) {
                float l2s = 0.f, l3s = 0.f, dns = 0.f;
#pragma unroll
                for (int mi = 0; mi < 2; mi++) {
#pragma unroll
                    for (int nf = 0; nf < 4; nf++) {
#pragma unroll
                        for (int e = 0; e < 4; e++) {
                            int r = tm * 32 + mi * 16 + gid + ((e >> 1) << 3);
                            int b = b0 + r;
                            int f = n0 + nf * 8 + 2 * tg + (e & 1);
                            size_t vi = ((size_t)b * Tn + t) * Fn + f;
                            float z = fmaxf(acc[mi][nf][e] + b_feat[f], 0.0f);
                            float al = g_alpha[vi];
                            float xh = g_xh[b * Fn + f];
                            float x = values[vi], m = masks[vi];
                            float ch = al * z + (1.0f - al) * xh;
                            float cc = m * x + (1.0f - m) * ch;
                            out[vi] = cc;
                            g_ccq[((size_t)g * 4 + (f >> 6)) * 4096 + o_A(r, f & 63)] = f2tf(cc);
                            l2s += fabsf(z - x) * m;
                            l3s += fabsf(ch - x) * m;
                            dns += m;
                        }
                    }
                }
                l2s = wredsum(l2s); l3s = wredsum(l3s); dns = wredsum(dns);
                if (lane == 0) { RED[wid] = l2s; RED[2 + wid] = l3s; RED[4 + wid] = dns; }
            }
            __syncthreads();
            if (tid == 0) {
                int slot = t * 32 + g * 8 + cg;
                g_l2[slot] = RED[0] + RED[1];
                g_l3[slot] = RED[2] + RED[3];
                g_den[slot] = RED[4] + RED[5];
            }
            arrive(&g_cnt_cc[g]);
        }

        // ===== P_c: gates (tile 64x64 virt, K=768) + fused LSTM, all 32 CTAs =====
        {
            wait_ge(&g_cnt_cc[g], 8u * (unsigned)(t + 1));
            float acc[2][4][4];
#pragma unroll
            for (int mi = 0; mi < 2; mi++)
#pragma unroll
                for (int nf = 0; nf < 4; nf++)
#pragma unroll
                    for (int e = 0; e < 4; e++) acc[mi][nf][e] = 0.0f;
#define PCB(kc) (g_Wgq + ((size_t)cg * 16 + (((kc) < 4) ? (kc) : (kc) + 4)) * 4096)
            LOADQ64(pcA(g, t, par, 0), PCB(0), 0); CMT;
            LOADQ64(pcA(g, t, par, 1), PCB(1), 1); CMT;
            LOADQ64(pcA(g, t, par, 2), PCB(2), 2); CMT;
            for (int i = 0; i < 12; i++) {
                WAIT2;
                __syncthreads();
                if (i + 3 < 12)
                    LOADQ64(pcA(g, t, par, i + 3), PCB(i + 3), (i + 3) & 3);
                CMT;
                int s = i & 3;
                mmaK2(SHu + s * STW, SHu + s * STW + 4096, acc, wm, wn, kw2, lane);
            }
            reduce2(acc, (float*)SHu, wm * 2 + wn, kw2, lane);
            float* EP = (float*)SHu;
            if (kw2 == 0) {
#pragma unroll
                for (int mi = 0; mi < 2; mi++)
#pragma unroll
                    for (int nf = 0; nf < 4; nf++)
#pragma unroll
                        for (int e = 0; e < 4; e++) {
                            int r = wm * 32 + mi * 16 + gid + ((e >> 1) << 3);
                            int cL = wn * 32 + nf * 8 + 2 * tg + (e & 1);
                            EP[r * EPIT + cL] = acc[mi][nf][e];
                        }
            }
            __syncthreads();
#pragma unroll
            for (int q = 0; q < 4; q++) {
                int idx = tid + q * 256;
                int r = idx >> 4, jl = idx & 15;
                int b = b0 + r;
                int j = cg * 16 + jl;
                float4 base = *(const float4*)&g_gate_base[((size_t)b * Tn + t) * 2048 + (size_t)j * 4];
                float ia = EP[r * EPIT + jl * 4 + 0] + base.x;
                float fa = EP[r * EPIT + jl * 4 + 1] + base.y;
                float ga = EP[r * EPIT + jl * 4 + 2] + base.z;
                float oa = EP[r * EPIT + jl * 4 + 3] + base.w;
                int ci = b * Hn + j;
                float cn = sigmoidf_(fa) * g_cst[ci] + sigmoidf_(ia) * tanhf(ga);
                float hn = sigmoidf_(oa) * tanhf(cn);
                g_cst[ci] = cn;
                if (t + 1 < Tn) {
                    float hd = hn * g_gamma_h[((size_t)b * Tn + t + 1) * Hn + j];
                    g_hq[(((size_t)nxt * 4 + g) * 8 + (j >> 6)) * 4096 + o_A(r, j & 63)] = f2tf(hd);
                } else {
                    out[BTF + ci] = hn;
                }
            }
            arrive(&g_cnt_h[g]);
        }
    }

    gsync(sense);

    // =================== final deterministic loss reduction + counter reset ===================
    if (cta == 0) {
        float v = 0.0f;
        if (tid < Tn) {
            float den = 1e-9f, n1 = 0.f, n2 = 0.f, n3 = 0.f;
            for (int c2 = 0; c2 < 32; c2++) {
                den += g_den[tid * 32 + c2];
                n1 += g_l1[tid * 32 + c2];
                n2 += g_l2[tid * 32 + c2];
                n3 += g_l3[tid * 32 + c2];
            }
            v = (n1 + n2 + n3) / den;
        }
        __syncthreads();
        RED[tid] = v;
        __syncthreads();
#pragma unroll
        for (int s = 128; s > 0; s >>= 1) {
            if (tid < s) RED[tid] += RED[tid + s];
            __syncthreads();
        }
        if (tid == 0) {
            out[BTF + Bn * Hn] = RED[0] / (3.0f * Tn);
#pragma unroll
            for (int i = 0; i < 4; i++) { g_cnt_h[i] = 0u; g_cnt_xh[i] = 0u; g_cnt_cc[i] = 0u; }
            __threadfence();
        }
    }
}

extern "C" void kernel_launch(void* const* d_in, const int* in_sizes, int n_in,
                              void* d_out, int out_size) {
    (void)in_sizes; (void)n_in; (void)out_size;
    static int configured = 0;
    if (!configured) {
        cudaFuncSetAttribute(rits_kernel, cudaFuncAttributeMaxDynamicSharedMemorySize,
                             SMEM_BYTES);
        configured = 1;
    }
    rits_kernel<<<NB, NT, SMEM_BYTES>>>(
        (const float*)d_in[0],  (const float*)d_in[1],  (const float*)d_in[2],
        (const float*)d_in[3],  (const float*)d_in[4],  (const float*)d_in[5],
        (const float*)d_in[6],  (const float*)d_in[7],  (const float*)d_in[8],
        (const float*)d_in[9],  (const float*)d_in[10], (const float*)d_in[11],
        (const float*)d_in[12], (const float*)d_in[13], (const float*)d_in[14],
        (const float*)d_in[15], (const float*)d_in[16],
        (float*)d_out);
}

// round 10
// speedup vs baseline: 1.2673x; 1.2673x over previous
#include <cuda_runtime.h>
#include <math.h>

#define Bn 256
#define Tn 100
#define Fn 256
#define Hn 512
#define NB 128
#define NT 256
#define BT (Bn * Tn)
#define STW 8192                   // stage words: A 4096 + B 4096
#define NSTG 4
#define EPIT 68
#define SMEM_WORDS (NSTG * STW + 256 + 16384)   // stages + RED + resident A
#define SMEM_BYTES (SMEM_WORDS * 4)
#define BTF ((size_t)Bn * Tn * Fn)

// ---------------- global scratch (allocation-free rule) ----------------
__device__ unsigned g_dtq[(size_t)400 * 4 * 4096];   // deltas quads, bt-tiles
__device__ unsigned g_gxmq[(size_t)400 * 8 * 4096];  // [gamma_x | mask] quads
__device__ unsigned g_Wtdhq[8 * 4 * 4096];
__device__ unsigned g_Wcombq[4 * 8 * 4096];
__device__ unsigned g_Whistq[8 * 8 * 2048];
__device__ unsigned g_Wfeatq[8 * 4 * 2048];
__device__ unsigned g_Wgq[32 * 16 * 4096];           // gates W, rows j*4+gate, k [ih|hh]
__device__ float    g_gate_base[(size_t)BT * 2048];  // mask@Wm^T + biases (hoisted)
__device__ unsigned g_hq[2 * 4 * 8 * 4096];          // h_dec quads (double buffer)
__device__ unsigned g_xcq[4 * 4 * 4096];
__device__ unsigned g_ccq[4 * 4 * 4096];
__device__ float g_gamma_h[(size_t)BT * Hn];
__device__ float g_alpha[(size_t)BT * Fn];
__device__ float g_bg[4 * Hn];
__device__ float g_xh[Bn * Fn];
__device__ float g_cst[Bn * Hn];
__device__ float g_l1[Tn * 32], g_l2[Tn * 32], g_l3[Tn * 32], g_den[Tn * 32];
__device__ unsigned g_cnt, g_sense;
__device__ unsigned g_cnt_h[4], g_cnt_xh[4], g_cnt_cc[4];

__device__ __forceinline__ float sigmoidf_(float x) { return 1.0f / (1.0f + expf(-x)); }

__device__ __forceinline__ unsigned f2tf(float f) {
    unsigned u;
    asm("cvt.rna.tf32.f32 %0, %1;" : "=r"(u) : "f"(f));
    return u;
}

// quad layouts (validated rounds 7-9)
__device__ __forceinline__ int o_A(int r, int k) {
    return ((r >> 4) * 8 + (k >> 3)) * 128 + ((r & 7) * 4 + (k & 3)) * 4 +
           ((k & 4) >> 1) + ((r & 8) >> 3);
}
__device__ __forceinline__ int o_B(int n, int k) {
    return ((n >> 4) * 8 + (k >> 3)) * 128 + ((n & 7) * 4 + (k & 3)) * 4 +
           ((n >> 3) & 1) * 2 + ((k >> 2) & 1);
}

#define MMA(d, A0, A1, A2, A3, B0, B1)                                          \
    asm volatile("mma.sync.aligned.m16n8k8.row.col.f32.tf32.tf32.f32 "          \
                 "{%0,%1,%2,%3},{%4,%5,%6,%7},{%8,%9},{%0,%1,%2,%3};"           \
                 : "+f"(d[0]), "+f"(d[1]), "+f"(d[2]), "+f"(d[3])               \
                 : "r"(A0), "r"(A1), "r"(A2), "r"(A3), "r"(B0), "r"(B1))

#define CPA(boff, p)                                                            \
    asm volatile("cp.async.cg.shared.global [%0], [%1], 16;"                    \
                 :: "r"(sbase + (unsigned)(boff)), "l"(p) : "memory")
#define CMT   asm volatile("cp.async.commit_group;" ::: "memory")
#define WAIT2 asm volatile("cp.async.wait_group 2;" ::: "memory")

// 64x64 stage: A 4096 + B 4096 words, linear copy (256 thr -> 8 CP16 each)
#define LOADQ64(pA, pB, s) do {                                                 \
    unsigned _off = (unsigned)((s) * STW * 4);                                  \
    _Pragma("unroll")                                                           \
    for (int _j = 0; _j < 4; _j++) { int _c = tid + _j * 256;                   \
        CPA(_off + (unsigned)_c * 16u, (pA) + _c * 4);                          \
        CPA(_off + 16384u + (unsigned)_c * 16u, (pB) + _c * 4); }               \
} while (0)
// 64x32 stage: A 4096 + B 2048 words
#define LOADQ32(pA, pB, s) do {                                                 \
    unsigned _off = (unsigned)((s) * STW * 4);                                  \
    _Pragma("unroll")                                                           \
    for (int _j = 0; _j < 4; _j++) { int _c = tid + _j * 256;                   \
        CPA(_off + (unsigned)_c * 16u, (pA) + _c * 4); }                        \
    _Pragma("unroll")                                                           \
    for (int _j = 0; _j < 2; _j++) { int _c = tid + _j * 256;                   \
        CPA(_off + 16384u + (unsigned)_c * 16u, (pB) + _c * 4); }               \
} while (0)
// B-only stage (4096 words) for the streaming mask-gate GEMM
#define LOADB(pB, s) do {                                                       \
    unsigned _off = (unsigned)((s) * STW * 4);                                  \
    _Pragma("unroll")                                                           \
    for (int _j = 0; _j < 4; _j++) { int _c = tid + _j * 256;                   \
        CPA(_off + (unsigned)_c * 16u, (pB) + _c * 4); }                        \
} while (0)

// ---------------- sync primitives (proven) ----------------
__device__ __forceinline__ void gsync(unsigned& sense) {
    __threadfence();
    __syncthreads();
    unsigned target = sense ^ 1u;
    if (threadIdx.x == 0) {
        unsigned old = atomicAdd(&g_cnt, 1u);
        if (old == NB - 1) {
            g_cnt = 0;
            __threadfence();
            atomicExch(&g_sense, target);
        } else {
            while (atomicAdd(&g_sense, 0u) != target) { __nanosleep(128); }
        }
        __threadfence();
    }
    sense = target;
    __syncthreads();
}
__device__ __forceinline__ void wait_ge(unsigned* cnt, unsigned target) {
    if (threadIdx.x == 0) {
        while (atomicAdd(cnt, 0u) < target) { __nanosleep(64); }
        __threadfence();
    }
    __syncthreads();
}
__device__ __forceinline__ void arrive(unsigned* cnt) {
    __threadfence();
    __syncthreads();
    if (threadIdx.x == 0) atomicAdd(cnt, 1u);
}
__device__ __forceinline__ float wredsum(float v) {
#pragma unroll
    for (int o = 16; o; o >>= 1) v += __shfl_xor_sync(0xffffffffu, v, o);
    return v;
}

// ---------------- quad MMA bodies (R7, proven) ----------------
// 64x64 tile: warps 4(M)x2(N), warp tile 16x32
__device__ __forceinline__ void mma64q(const unsigned* As, const unsigned* Bs,
                                       float acc[4][4], int wm, int wn, int lane) {
#pragma unroll
    for (int ks = 0; ks < 8; ks++) {
        uint4 a = *(const uint4*)&As[((wm * 8 + ks) * 32 + lane) * 4];
        uint4 b0 = *(const uint4*)&Bs[(((wn * 2 + 0) * 8 + ks) * 32 + lane) * 4];
        uint4 b1 = *(const uint4*)&Bs[(((wn * 2 + 1) * 8 + ks) * 32 + lane) * 4];
        MMA(acc[0], a.x, a.y, a.z, a.w, b0.x, b0.y);
        MMA(acc[1], a.x, a.y, a.z, a.w, b0.z, b0.w);
        MMA(acc[2], a.x, a.y, a.z, a.w, b1.x, b1.y);
        MMA(acc[3], a.x, a.y, a.z, a.w, b1.z, b1.w);
    }
}
// 64x32 tile: warps 4(M)x2(N), warp tile 16x16
__device__ __forceinline__ void mma32q(const unsigned* As, const unsigned* Bs,
                                       float acc[2][4], int wm, int wn, int lane) {
#pragma unroll
    for (int ks = 0; ks < 8; ks++) {
        uint4 a = *(const uint4*)&As[((wm * 8 + ks) * 32 + lane) * 4];
        uint4 b = *(const uint4*)&Bs[((wn * 8 + ks) * 32 + lane) * 4];
        MMA(acc[0], a.x, a.y, a.z, a.w, b.x, b.y);
        MMA(acc[1], a.x, a.y, a.z, a.w, b.z, b.w);
    }
}

// P_c A chunks: 0-3 = c_c, 4-11 = h_dec (mask block hoisted into g_gate_base)
__device__ __forceinline__ const unsigned* pcA(int g, int t, int par, int kc) {
    (void)t;
    if (kc < 4) return g_ccq + ((size_t)g * 4 + kc) * 4096;
    return g_hq + (((size_t)par * 4 + g) * 8 + (kc - 4)) * 4096;
}

__global__ void __launch_bounds__(NT, 1) rits_kernel(
    const float* __restrict__ values, const float* __restrict__ masks,
    const float* __restrict__ deltas,
    const float* __restrict__ W_td_h, const float* __restrict__ b_td_h,
    const float* __restrict__ W_td_x, const float* __restrict__ b_td_x,
    const float* __restrict__ W_hist, const float* __restrict__ b_hist,
    const float* __restrict__ W_feat, const float* __restrict__ b_feat,
    const float* __restrict__ W_comb, const float* __restrict__ b_comb,
    const float* __restrict__ W_ih, const float* __restrict__ W_hh,
    const float* __restrict__ b_ih, const float* __restrict__ b_hh,
    float* __restrict__ out)
{
    extern __shared__ unsigned SHu[];
    float* RED = (float*)(SHu + NSTG * STW);
    unsigned* Ares = SHu + NSTG * STW + 256;   // resident A (16384 words)
    unsigned sbase = (unsigned)__cvta_generic_to_shared(SHu);

    const int tid = threadIdx.x;
    const int cta = blockIdx.x;
    const int wid = tid >> 5;
    const int lane = tid & 31;
    const int gid = lane >> 2;
    const int tg = lane & 3;
    const int wm = wid & 3, wn = wid >> 2;

    const int g = cta >> 5;
    const int cg = cta & 31;
    const int b0 = g * 64;

    unsigned sense = *((volatile unsigned*)&g_sense);

    // =================== init: state + tf32 quad pre-conversion ===================
    for (int i = cta * NT + tid; i < Bn * Hn; i += NB * NT) g_cst[i] = 0.0f;
    for (int i = cta * NT + tid; i < 2 * 4 * 8 * 4096; i += NB * NT) g_hq[i] = 0u;

    for (int i4 = cta * NT + tid; i4 < BT * Fn / 4; i4 += NB * NT) {
        int bt = i4 >> 6;
        int f0 = (i4 & 63) * 4;
        float4 d = ((const float4*)deltas)[i4];
        float4 mk = ((const float4*)masks)[i4];
        int u = bt >> 6, r = bt & 63;
        float dv[4] = {d.x, d.y, d.z, d.w};
        float mv[4] = {mk.x, mk.y, mk.z, mk.w};
#pragma unroll
        for (int q = 0; q < 4; q++) {
            int f = f0 + q;
            int kc = f >> 6, k = f & 63;
            int oa = o_A(r, k);
            float gx = expf(-fmaxf(fmaf(dv[q], W_td_x[f * Fn + f], b_td_x[f]), 0.f));
            g_dtq[((size_t)u * 4 + kc) * 4096 + oa] = f2tf(dv[q]);
            g_gxmq[((size_t)u * 8 + kc) * 4096 + oa] = f2tf(gx);
            g_gxmq[((size_t)u * 8 + 4 + kc) * 4096 + oa] = f2tf(mv[q]);
        }
    }
    for (int i = cta * NT + tid; i < 512 * 256; i += NB * NT) {
        int n = i >> 8, k = i & 255;
        g_Wtdhq[((n >> 6) * 4 + (k >> 6)) * 4096 + o_B(n & 63, k & 63)] = f2tf(W_td_h[i]);
    }
    for (int i = cta * NT + tid; i < 256 * 512; i += NB * NT) {
        int n = i >> 9, k = i & 511;
        g_Wcombq[((n >> 6) * 8 + (k >> 6)) * 4096 + o_B(n & 63, k & 63)] = f2tf(W_comb[i]);
        g_Whistq[((n >> 5) * 8 + (k >> 6)) * 2048 + o_B(n & 31, k & 63)] = f2tf(W_hist[i]);
    }
    for (int i = cta * NT + tid; i < 256 * 256; i += NB * NT) {
        int n = i >> 8, k = i & 255;
        float w = (n == k) ? 0.0f : W_feat[i];
        g_Wfeatq[((n >> 5) * 4 + (k >> 6)) * 2048 + o_B(n & 31, k & 63)] = f2tf(w);
    }
    for (int i = cta * NT + tid; i < 2048 * 1024; i += NB * NT) {
        int np = i >> 10, k = i & 1023;
        int j = np >> 2, gate = np & 3;
        float w = (k < 512) ? W_ih[(size_t)(gate * Hn + j) * 512 + k]
                            : W_hh[(size_t)(gate * Hn + j) * 512 + (k - 512)];
        g_Wgq[((np >> 6) * 16 + (k >> 6)) * 4096 + o_B(np & 63, k & 63)] = f2tf(w);
    }
    for (int i = cta * NT + tid; i < 4 * Hn; i += NB * NT) {
        int j = i >> 2, gate = i & 3;
        g_bg[i] = b_ih[gate * Hn + j] + b_hh[gate * Hn + j];
    }
    gsync(sense);

    // =================== precompute 1: gamma_h (3200 tiles) + alpha (1600) ===================
    for (int tt = cta; tt < 4800; tt += NB) {
        float acc[4][4];
#pragma unroll
        for (int nf = 0; nf < 4; nf++)
#pragma unroll
            for (int e = 0; e < 4; e++) acc[nf][e] = 0.0f;

        const bool isg = (tt < 3200);
        const int u = isg ? tt : tt - 3200;
        const int ut = isg ? (u >> 3) : (u >> 2);
        const int nt = isg ? (u & 7) : (u & 3);
        const int m0 = ut * 64, n0 = nt * 64;
        const int NI = isg ? 4 : 8;
        const unsigned* Asrc = isg ? (g_dtq + (size_t)ut * 4 * 4096)
                                   : (g_gxmq + (size_t)ut * 8 * 4096);
        const unsigned* Bsrc = isg ? (g_Wtdhq + (size_t)nt * 4 * 4096)
                                   : (g_Wcombq + (size_t)nt * 8 * 4096);

        LOADQ64(Asrc, Bsrc, 0); CMT;
        LOADQ64(Asrc + 4096, Bsrc + 4096, 1); CMT;
        LOADQ64(Asrc + 8192, Bsrc + 8192, 2); CMT;
        for (int i = 0; i < NI; i++) {
            WAIT2;
            __syncthreads();
            if (i + 3 < NI)
                LOADQ64(Asrc + (size_t)(i + 3) * 4096, Bsrc + (size_t)(i + 3) * 4096, (i + 3) & 3);
            CMT;
            int s = i & 3;
            mma64q(SHu + s * STW, SHu + s * STW + 4096, acc, wm, wn, lane);
        }
        __syncthreads();
#pragma unroll
        for (int nf = 0; nf < 4; nf++) {
#pragma unroll
            for (int e = 0; e < 4; e++) {
                int bt = m0 + wm * 16 + gid + ((e >> 1) << 3);
                int n = n0 + wn * 32 + nf * 8 + 2 * tg + (e & 1);
                float v = acc[nf][e];
                if (isg)
                    g_gamma_h[(size_t)bt * Hn + n] = expf(-fmaxf(v + b_td_h[n], 0.f));
                else
                    g_alpha[(size_t)bt * Fn + n] = sigmoidf_(v + b_comb[n]);
            }
        }
    }

    // ===== precompute 2: gate_base = mask @ Wm^T + (b_ih+b_hh), A-resident streaming =====
    // Each bt-tile (64 rows): A (4 mask chunks, 16K words) resident; stream 32x4 B chunks.
    for (int ut = cta; ut < 400; ut += NB) {
        const unsigned* Am = g_gxmq + (size_t)ut * 8 * 4096 + 4 * 4096;  // mask chunks 4..7
        // load resident A (4096 CP16 over 256 threads)
#pragma unroll
        for (int j = 0; j < 16; j++) {
            int c = tid + j * 256;
            CPA((unsigned)(NSTG * STW + 256 + c * 4) * 4u, Am + c * 4);
        }
        CMT;
        LOADB(g_Wgq + (size_t)(0 * 16 + 4 + 0) * 4096, 0); CMT;
        LOADB(g_Wgq + (size_t)(0 * 16 + 4 + 1) * 4096, 1); CMT;
        LOADB(g_Wgq + (size_t)(0 * 16 + 4 + 2) * 4096, 2); CMT;

        float acc[4][4];
#pragma unroll
        for (int nf = 0; nf < 4; nf++)
#pragma unroll
            for (int e = 0; e < 4; e++) acc[nf][e] = 0.0f;

        for (int idx = 0; idx < 128; idx++) {
            WAIT2;
            __syncthreads();
            if (idx + 3 < 128) {
                int nx = (idx + 3) >> 2, kx = (idx + 3) & 3;
                LOADB(g_Wgq + ((size_t)nx * 16 + 4 + kx) * 4096, (idx + 3) & 3);
            }
            CMT;
            int s = idx & 3, kc = idx & 3, nt = idx >> 2;
            mma64q(Ares + kc * 4096, SHu + s * STW, acc, wm, wn, lane);
            if (kc == 3) {
                // emit 64x64 output tile (float2 stores), reset acc
                int n0 = nt * 64;
#pragma unroll
                for (int nf = 0; nf < 4; nf++) {
#pragma unroll
                    for (int ep = 0; ep < 2; ep++) {
                        int bt = ut * 64 + wm * 16 + gid + ep * 8;
                        int n = n0 + wn * 32 + nf * 8 + 2 * tg;
                        float2 v;
                        v.x = acc[nf][ep * 2 + 0] + g_bg[n + 0];
                        v.y = acc[nf][ep * 2 + 1] + g_bg[n + 1];
                        *(float2*)&g_gate_base[(size_t)bt * 2048 + n] = v;
                        acc[nf][ep * 2 + 0] = 0.0f;
                        acc[nf][ep * 2 + 1] = 0.0f;
                    }
                }
            }
        }
    }
    gsync(sense);

    // =================== sequential recurrence (dataflow-synced, 4 groups) ===================
    for (int t = 0; t < Tn; t++) {
        const int par = t & 1, nxt = (t + 1) & 1;

        // ===== P_a: x_h = h_dec @ W_hist^T  (tile 64x32, K=512), CTAs cg<8 =====
        if (cg < 8) {
            const int n0 = cg * 32;
            wait_ge(&g_cnt_h[g], 32u * (unsigned)t);
            const unsigned* Ah = g_hq + (((size_t)par * 4 + g) * 8) * 4096;
            const unsigned* Bw = g_Whistq + (size_t)cg * 8 * 2048;
            float acc[2][4];
#pragma unroll
            for (int nf = 0; nf < 2; nf++)
#pragma unroll
                for (int e = 0; e < 4; e++) acc[nf][e] = 0.0f;
            LOADQ32(Ah, Bw, 0); CMT;
            LOADQ32(Ah + 4096, Bw + 2048, 1); CMT;
            LOADQ32(Ah + 8192, Bw + 4096, 2); CMT;
            for (int i = 0; i < 8; i++) {
                WAIT2;
                __syncthreads();
                if (i + 3 < 8)
                    LOADQ32(Ah + (size_t)(i + 3) * 4096, Bw + (size_t)(i + 3) * 2048, (i + 3) & 3);
                CMT;
                int s = i & 3;
                mma32q(SHu + s * STW, SHu + s * STW + 4096, acc, wm, wn, lane);
            }
            float ls = 0.0f;
#pragma unroll
            for (int nf = 0; nf < 2; nf++) {
#pragma unroll
                for (int e = 0; e < 4; e++) {
                    int r = wm * 16 + gid + ((e >> 1) << 3);
                    int b = b0 + r;
                    int f = n0 + wn * 16 + nf * 8 + 2 * tg + (e & 1);
                    float xh = acc[nf][e] + b_hist[f];
                    g_xh[b * Fn + f] = xh;
                    size_t vi = ((size_t)b * Tn + t) * Fn + f;
                    float x = values[vi], m = masks[vi];
                    ls += fabsf(xh - x) * m;
                    g_xcq[((size_t)g * 4 + (f >> 6)) * 4096 + o_A(r, f & 63)] =
                        f2tf(m * x + (1.0f - m) * xh);
                }
            }
            ls = wredsum(ls);
            if (lane == 0) RED[wid] = ls;
            __syncthreads();
            if (tid == 0) {
                float s = 0.f;
#pragma unroll
                for (int w = 0; w < 8; w++) s += RED[w];
                g_l1[t * 32 + g * 8 + cg] = s;
            }
            arrive(&g_cnt_xh[g]);
        }

        // ===== P_b: z_h = relu(x_c @ Wf^T) (tile 64x32, K=256) + epilogue =====
        if (cg < 8) {
            const int n0 = cg * 32;
            wait_ge(&g_cnt_xh[g], 8u * (unsigned)(t + 1));
            const unsigned* Ax = g_xcq + (size_t)g * 4 * 4096;
            const unsigned* Bf = g_Wfeatq + (size_t)cg * 4 * 2048;
            float acc[2][4];
#pragma unroll
            for (int nf = 0; nf < 2; nf++)
#pragma unroll
                for (int e = 0; e < 4; e++) acc[nf][e] = 0.0f;
            LOADQ32(Ax, Bf, 0); CMT;
            LOADQ32(Ax + 4096, Bf + 2048, 1); CMT;
            LOADQ32(Ax + 8192, Bf + 4096, 2); CMT;
            for (int i = 0; i < 4; i++) {
                WAIT2;
                __syncthreads();
                if (i + 3 < 4)
                    LOADQ32(Ax + (size_t)(i + 3) * 4096, Bf + (size_t)(i + 3) * 2048, (i + 3) & 3);
                CMT;
                int s = i & 3;
                mma32q(SHu + s * STW, SHu + s * STW + 4096, acc, wm, wn, lane);
            }
            float l2s = 0.f, l3s = 0.f, dns = 0.f;
#pragma unroll
            for (int nf = 0; nf < 2; nf++) {
#pragma unroll
                for (int e = 0; e < 4; e++) {
                    int r = wm * 16 + gid + ((e >> 1) << 3);
                    int b = b0 + r;
                    int f = n0 + wn * 16 + nf * 8 + 2 * tg + (e & 1);
                    size_t vi = ((size_t)b * Tn + t) * Fn + f;
                    float z = fmaxf(acc[nf][e] + b_feat[f], 0.0f);
                    float al = g_alpha[vi];
                    float xh = g_xh[b * Fn + f];
                    float x = values[vi], m = masks[vi];
                    float ch = al * z + (1.0f - al) * xh;
                    float cc = m * x + (1.0f - m) * ch;
                    out[vi] = cc;
                    g_ccq[((size_t)g * 4 + (f >> 6)) * 4096 + o_A(r, f & 63)] = f2tf(cc);
                    l2s += fabsf(z - x) * m;
                    l3s += fabsf(ch - x) * m;
                    dns += m;
                }
            }
            l2s = wredsum(l2s); l3s = wredsum(l3s); dns = wredsum(dns);
            if (lane == 0) { RED[wid] = l2s; RED[8 + wid] = l3s; RED[16 + wid] = dns; }
            __syncthreads();
            if (tid == 0) {
                float s2 = 0.f, s3 = 0.f, sd = 0.f;
#pragma unroll
                for (int w = 0; w < 8; w++) { s2 += RED[w]; s3 += RED[8 + w]; sd += RED[16 + w]; }
                int slot = t * 32 + g * 8 + cg;
                g_l2[slot] = s2; g_l3[slot] = s3; g_den[slot] = sd;
            }
            arrive(&g_cnt_cc[g]);
        }

        // ===== P_c: gates (tile 64x64 virt, K=768) + fused LSTM, all 32 CTAs =====
        {
            wait_ge(&g_cnt_cc[g], 8u * (unsigned)(t + 1));
            const size_t wb = (size_t)cg * 16;
#define PCB(kc) (g_Wgq + (wb + (((kc) < 4) ? (unsigned)(kc) : (unsigned)(kc) + 4)) * 4096)
            float acc[4][4];
#pragma unroll
            for (int nf = 0; nf < 4; nf++)
#pragma unroll
                for (int e = 0; e < 4; e++) acc[nf][e] = 0.0f;
            LOADQ64(pcA(g, t, par, 0), PCB(0), 0); CMT;
            LOADQ64(pcA(g, t, par, 1), PCB(1), 1); CMT;
            LOADQ64(pcA(g, t, par, 2), PCB(2), 2); CMT;
            for (int i = 0; i < 12; i++) {
                WAIT2;
                __syncthreads();
                if (i + 3 < 12)
                    LOADQ64(pcA(g, t, par, i + 3), PCB(i + 3), (i + 3) & 3);
                CMT;
                int s = i & 3;
                mma64q(SHu + s * STW, SHu + s * STW + 4096, acc, wm, wn, lane);
            }
            __syncthreads();
            float* EP = (float*)SHu;
#pragma unroll
            for (int nf = 0; nf < 4; nf++)
#pragma unroll
                for (int e = 0; e < 4; e++) {
                    int r = wm * 16 + gid + ((e >> 1) << 3);
                    int cL = wn * 32 + nf * 8 + 2 * tg + (e & 1);
                    EP[r * EPIT + cL] = acc[nf][e];
                }
            __syncthreads();
#pragma unroll
            for (int q = 0; q < 4; q++) {
                int idx = tid + q * 256;
                int r = idx >> 4, jl = idx & 15;
                int b = b0 + r;
                int j = cg * 16 + jl;
                float4 base = *(const float4*)&g_gate_base[((size_t)b * Tn + t) * 2048 + (size_t)j * 4];
                float ia = EP[r * EPIT + jl * 4 + 0] + base.x;
                float fa = EP[r * EPIT + jl * 4 + 1] + base.y;
                float ga = EP[r * EPIT + jl * 4 + 2] + base.z;
                float oa = EP[r * EPIT + jl * 4 + 3] + base.w;
                int ci = b * Hn + j;
                float cn = sigmoidf_(fa) * g_cst[ci] + sigmoidf_(ia) * tanhf(ga);
                float hn = sigmoidf_(oa) * tanhf(cn);
                g_cst[ci] = cn;
                if (t + 1 < Tn) {
                    float hd = hn * g_gamma_h[((size_t)b * Tn + t + 1) * Hn + j];
                    g_hq[(((size_t)nxt * 4 + g) * 8 + (j >> 6)) * 4096 + o_A(r, j & 63)] = f2tf(hd);
                } else {
                    out[BTF + ci] = hn;
                }
            }
            arrive(&g_cnt_h[g]);
        }
    }

    gsync(sense);

    // =================== final deterministic loss reduction + counter reset ===================
    if (cta == 0) {
        float v = 0.0f;
        if (tid < Tn) {
            float den = 1e-9f, n1 = 0.f, n2 = 0.f, n3 = 0.f;
            for (int c2 = 0; c2 < 32; c2++) {
                den += g_den[tid * 32 + c2];
                n1 += g_l1[tid * 32 + c2];
                n2 += g_l2[tid * 32 + c2];
                n3 += g_l3[tid * 32 + c2];
            }
            v = (n1 + n2 + n3) / den;
        }
        __syncthreads();
        RED[tid] = v;
        __syncthreads();
#pragma unroll
        for (int s = 128; s > 0; s >>= 1) {
            if (tid < s) RED[tid] += RED[tid + s];
            __syncthreads();
        }
        if (tid == 0) {
            out[BTF + Bn * Hn] = RED[0] / (3.0f * Tn);
#pragma unroll
            for (int i = 0; i < 4; i++) { g_cnt_h[i] = 0u; g_cnt_xh[i] = 0u; g_cnt_cc[i] = 0u; }
            __threadfence();
        }
    }
}

extern "C" void kernel_launch(void* const* d_in, const int* in_sizes, int n_in,
                              void* d_out, int out_size) {
    (void)in_sizes; (void)n_in; (void)out_size;
    static int configured = 0;
    if (!configured) {
        cudaFuncSetAttribute(rits_kernel, cudaFuncAttributeMaxDynamicSharedMemorySize,
                             SMEM_BYTES);
        configured = 1;
    }
    rits_kernel<<<NB, NT, SMEM_BYTES>>>(
        (const float*)d_in[0],  (const float*)d_in[1],  (const float*)d_in[2],
        (const float*)d_in[3],  (const float*)d_in[4],  (const float*)d_in[5],
        (const float*)d_in[6],  (const float*)d_in[7],  (const float*)d_in[8],
        (const float*)d_in[9],  (const float*)d_in[10], (const float*)d_in[11],
        (const float*)d_in[12], (const float*)d_in[13], (const float*)d_in[14],
        (const float*)d_in[15], (const float*)d_in[16],
        (float*)d_out);
}

// round 11
// speedup vs baseline: 1.3312x; 1.0504x over previous
#include <cuda_runtime.h>
#include <math.h>

#define Bn 256
#define Tn 100
#define Fn 256
#define Hn 512
#define NB 128
#define NT 256
#define BT (Bn * Tn)
#define STW 8192                   // stage words: A 4096 + B 4096
#define NSTG 4
#define EPIT 68
#define SMEM_WORDS (NSTG * STW + 256)
#define SMEM_BYTES (SMEM_WORDS * 4)
#define BTF ((size_t)Bn * Tn * Fn)

// ---------------- global scratch (allocation-free rule) ----------------
__device__ unsigned g_dtq[(size_t)400 * 4 * 4096];   // deltas quads, bt-tiles
__device__ unsigned g_gxmq[(size_t)400 * 8 * 4096];  // [gamma_x | mask] quads
__device__ unsigned g_Wtdhq[8 * 4 * 4096];
__device__ unsigned g_Wcombq[4 * 8 * 4096];
__device__ unsigned g_Whistq[8 * 8 * 2048];
__device__ unsigned g_Wfeatq[8 * 4 * 2048];
__device__ unsigned g_Wgq[32 * 16 * 4096];           // gates W, rows j*4+gate, k [ih|hh]
__device__ float    g_gate_base[(size_t)BT * 2048];  // mask@Wm^T + biases (hoisted)
__device__ unsigned g_hq[2 * 4 * 8 * 4096];          // h_dec quads (double buffer)
__device__ unsigned g_xcq[4 * 4 * 4096];
__device__ unsigned g_ccq[4 * 4 * 4096];
__device__ float g_gamma_h[(size_t)BT * Hn];
__device__ float g_alpha[(size_t)BT * Fn];
__device__ float g_bg[4 * Hn];
__device__ float g_xh[Bn * Fn];
__device__ float g_cst[Bn * Hn];
__device__ float g_l1[Tn * 32], g_l2[Tn * 32], g_l3[Tn * 32], g_den[Tn * 32];
__device__ unsigned g_cnt, g_sense;
__device__ unsigned g_cnt_h[4], g_cnt_xh[4], g_cnt_cc[4];

__device__ __forceinline__ float sigmoidf_(float x) { return 1.0f / (1.0f + expf(-x)); }

__device__ __forceinline__ unsigned f2tf(float f) {
    unsigned u;
    asm("cvt.rna.tf32.f32 %0, %1;" : "=r"(u) : "f"(f));
    return u;
}

// quad layouts (validated rounds 7-10)
__device__ __forceinline__ int o_A(int r, int k) {
    return ((r >> 4) * 8 + (k >> 3)) * 128 + ((r & 7) * 4 + (k & 3)) * 4 +
           ((k & 4) >> 1) + ((r & 8) >> 3);
}
__device__ __forceinline__ int o_B(int n, int k) {
    return ((n >> 4) * 8 + (k >> 3)) * 128 + ((n & 7) * 4 + (k & 3)) * 4 +
           ((n >> 3) & 1) * 2 + ((k >> 2) & 1);
}

#define MMA(d, A0, A1, A2, A3, B0, B1)                                          \
    asm volatile("mma.sync.aligned.m16n8k8.row.col.f32.tf32.tf32.f32 "          \
                 "{%0,%1,%2,%3},{%4,%5,%6,%7},{%8,%9},{%0,%1,%2,%3};"           \
                 : "+f"(d[0]), "+f"(d[1]), "+f"(d[2]), "+f"(d[3])               \
                 : "r"(A0), "r"(A1), "r"(A2), "r"(A3), "r"(B0), "r"(B1))

#define CPA(boff, p)                                                            \
    asm volatile("cp.async.cg.shared.global [%0], [%1], 16;"                    \
                 :: "r"(sbase + (unsigned)(boff)), "l"(p) : "memory")
#define CMT   asm volatile("cp.async.commit_group;" ::: "memory")
#define WAIT2 asm volatile("cp.async.wait_group 2;" ::: "memory")

// 64x64 stage: A 4096 + B 4096 words, linear copy (256 thr -> 8 CP16 each)
#define LOADQ64(pA, pB, s) do {                                                 \
    unsigned _off = (unsigned)((s) * STW * 4);                                  \
    _Pragma("unroll")                                                           \
    for (int _j = 0; _j < 4; _j++) { int _c = tid + _j * 256;                   \
        CPA(_off + (unsigned)_c * 16u, (pA) + _c * 4);                          \
        CPA(_off + 16384u + (unsigned)_c * 16u, (pB) + _c * 4); }               \
} while (0)
// 64x32 stage: A 4096 + B 2048 words
#define LOADQ32(pA, pB, s) do {                                                 \
    unsigned _off = (unsigned)((s) * STW * 4);                                  \
    _Pragma("unroll")                                                           \
    for (int _j = 0; _j < 4; _j++) { int _c = tid + _j * 256;                   \
        CPA(_off + (unsigned)_c * 16u, (pA) + _c * 4); }                        \
    _Pragma("unroll")                                                           \
    for (int _j = 0; _j < 2; _j++) { int _c = tid + _j * 256;                   \
        CPA(_off + 16384u + (unsigned)_c * 16u, (pB) + _c * 4); }               \
} while (0)

// ---------------- sync primitives ----------------
__device__ __forceinline__ void gsync(unsigned& sense) {
    __threadfence();
    __syncthreads();
    unsigned target = sense ^ 1u;
    if (threadIdx.x == 0) {
        unsigned old = atomicAdd(&g_cnt, 1u);
        if (old == NB - 1) {
            g_cnt = 0;
            __threadfence();
            atomicExch(&g_sense, target);
        } else {
            while (atomicAdd(&g_sense, 0u) != target) { __nanosleep(128); }
        }
        __threadfence();
    }
    sense = target;
    __syncthreads();
}
// Consumer wait: NO acquire fence. All cross-CTA loop data (h, x_c, c_c) is
// consumed via cp.async.cg (L2-direct); producer's release fence already
// drained stores to L2 (the coherence point). All in-loop LDG reads are
// CTA-local or frozen before the preceding gsync (which does acquire).
__device__ __forceinline__ void wait_ge(unsigned* cnt, unsigned target) {
    if (threadIdx.x == 0) {
        while (atomicAdd(cnt, 0u) < target) { __nanosleep(64); }
    }
    __syncthreads();
}
__device__ __forceinline__ void arrive(unsigned* cnt) {
    __threadfence();               // release: ALL threads' stores -> L2
    __syncthreads();
    if (threadIdx.x == 0) atomicAdd(cnt, 1u);
}
__device__ __forceinline__ float wredsum(float v) {
#pragma unroll
    for (int o = 16; o; o >>= 1) v += __shfl_xor_sync(0xffffffffu, v, o);
    return v;
}

// ---------------- quad MMA bodies (R7, proven) ----------------
// 64x64 tile: warps 4(M)x2(N), warp tile 16x32
__device__ __forceinline__ void mma64q(const unsigned* As, const unsigned* Bs,
                                       float acc[4][4], int wm, int wn, int lane) {
#pragma unroll
    for (int ks = 0; ks < 8; ks++) {
        uint4 a = *(const uint4*)&As[((wm * 8 + ks) * 32 + lane) * 4];
        uint4 b0 = *(const uint4*)&Bs[(((wn * 2 + 0) * 8 + ks) * 32 + lane) * 4];
        uint4 b1 = *(const uint4*)&Bs[(((wn * 2 + 1) * 8 + ks) * 32 + lane) * 4];
        MMA(acc[0], a.x, a.y, a.z, a.w, b0.x, b0.y);
        MMA(acc[1], a.x, a.y, a.z, a.w, b0.z, b0.w);
        MMA(acc[2], a.x, a.y, a.z, a.w, b1.x, b1.y);
        MMA(acc[3], a.x, a.y, a.z, a.w, b1.z, b1.w);
    }
}
// 64x32 tile: warps 4(M)x2(N), warp tile 16x16
__device__ __forceinline__ void mma32q(const unsigned* As, const unsigned* Bs,
                                       float acc[2][4], int wm, int wn, int lane) {
#pragma unroll
    for (int ks = 0; ks < 8; ks++) {
        uint4 a = *(const uint4*)&As[((wm * 8 + ks) * 32 + lane) * 4];
        uint4 b = *(const uint4*)&Bs[((wn * 8 + ks) * 32 + lane) * 4];
        MMA(acc[0], a.x, a.y, a.z, a.w, b.x, b.y);
        MMA(acc[1], a.x, a.y, a.z, a.w, b.z, b.w);
    }
}

// P_c A chunks: 0-3 = c_c, 4-11 = h_dec (mask block hoisted into g_gate_base)
__device__ __forceinline__ const unsigned* pcA(int g, int par, int kc) {
    if (kc < 4) return g_ccq + ((size_t)g * 4 + kc) * 4096;
    return g_hq + (((size_t)par * 4 + g) * 8 + (kc - 4)) * 4096;
}
// P_c B chunks: 0-3 = W_ih cc cols (k 0..255), 4-11 = W_hh (k 512..1023)
__device__ __forceinline__ const unsigned* pcB(int cg, int kc) {
    int ch = (kc < 4) ? kc : kc + 4;
    return g_Wgq + ((size_t)cg * 16 + ch) * 4096;
}

__global__ void __launch_bounds__(NT, 1) rits_kernel(
    const float* __restrict__ values, const float* __restrict__ masks,
    const float* __restrict__ deltas,
    const float* __restrict__ W_td_h, const float* __restrict__ b_td_h,
    const float* __restrict__ W_td_x, const float* __restrict__ b_td_x,
    const float* __restrict__ W_hist, const float* __restrict__ b_hist,
    const float* __restrict__ W_feat, const float* __restrict__ b_feat,
    const float* __restrict__ W_comb, const float* __restrict__ b_comb,
    const float* __restrict__ W_ih, const float* __restrict__ W_hh,
    const float* __restrict__ b_ih, const float* __restrict__ b_hh,
    float* __restrict__ out)
{
    extern __shared__ unsigned SHu[];
    float* RED = (float*)(SHu + NSTG * STW);
    unsigned sbase = (unsigned)__cvta_generic_to_shared(SHu);

    const int tid = threadIdx.x;
    const int cta = blockIdx.x;
    const int wid = tid >> 5;
    const int lane = tid & 31;
    const int gid = lane >> 2;
    const int tg = lane & 3;
    const int wm = wid & 3, wn = wid >> 2;

    const int g = cta >> 5;
    const int cg = cta & 31;
    const int b0 = g * 64;

    unsigned sense = *((volatile unsigned*)&g_sense);

    // =================== init: state + tf32 quad pre-conversion ===================
    for (int i = cta * NT + tid; i < Bn * Hn; i += NB * NT) g_cst[i] = 0.0f;
    for (int i = cta * NT + tid; i < 2 * 4 * 8 * 4096; i += NB * NT) g_hq[i] = 0u;

    for (int i4 = cta * NT + tid; i4 < BT * Fn / 4; i4 += NB * NT) {
        int bt = i4 >> 6;
        int f0 = (i4 & 63) * 4;
        float4 d = ((const float4*)deltas)[i4];
        float4 mk = ((const float4*)masks)[i4];
        int u = bt >> 6, r = bt & 63;
        float dv[4] = {d.x, d.y, d.z, d.w};
        float mv[4] = {mk.x, mk.y, mk.z, mk.w};
#pragma unroll
        for (int q = 0; q < 4; q++) {
            int f = f0 + q;
            int kc = f >> 6, k = f & 63;
            int oa = o_A(r, k);
            float gx = expf(-fmaxf(fmaf(dv[q], W_td_x[f * Fn + f], b_td_x[f]), 0.f));
            g_dtq[((size_t)u * 4 + kc) * 4096 + oa] = f2tf(dv[q]);
            g_gxmq[((size_t)u * 8 + kc) * 4096 + oa] = f2tf(gx);
            g_gxmq[((size_t)u * 8 + 4 + kc) * 4096 + oa] = f2tf(mv[q]);
        }
    }
    for (int i = cta * NT + tid; i < 512 * 256; i += NB * NT) {
        int n = i >> 8, k = i & 255;
        g_Wtdhq[((n >> 6) * 4 + (k >> 6)) * 4096 + o_B(n & 63, k & 63)] = f2tf(W_td_h[i]);
    }
    for (int i = cta * NT + tid; i < 256 * 512; i += NB * NT) {
        int n = i >> 9, k = i & 511;
        g_Wcombq[((n >> 6) * 8 + (k >> 6)) * 4096 + o_B(n & 63, k & 63)] = f2tf(W_comb[i]);
        g_Whistq[((n >> 5) * 8 + (k >> 6)) * 2048 + o_B(n & 31, k & 63)] = f2tf(W_hist[i]);
    }
    for (int i = cta * NT + tid; i < 256 * 256; i += NB * NT) {
        int n = i >> 8, k = i & 255;
        float w = (n == k) ? 0.0f : W_feat[i];
        g_Wfeatq[((n >> 5) * 4 + (k >> 6)) * 2048 + o_B(n & 31, k & 63)] = f2tf(w);
    }
    for (int i = cta * NT + tid; i < 2048 * 1024; i += NB * NT) {
        int np = i >> 10, k = i & 1023;
        int j = np >> 2, gate = np & 3;
        float w = (k < 512) ? W_ih[(size_t)(gate * Hn + j) * 512 + k]
                            : W_hh[(size_t)(gate * Hn + j) * 512 + (k - 512)];
        g_Wgq[((np >> 6) * 16 + (k >> 6)) * 4096 + o_B(np & 63, k & 63)] = f2tf(w);
    }
    for (int i = cta * NT + tid; i < 4 * Hn; i += NB * NT) {
        int j = i >> 2, gate = i & 3;
        g_bg[i] = b_ih[gate * Hn + j] + b_hh[gate * Hn + j];
    }
    gsync(sense);

    // == precompute: gamma_h (3200) + alpha (1600) + gate_base (12800), one proven loop ==
    for (int tt = cta; tt < 17600; tt += NB) {
        float acc[4][4];
#pragma unroll
        for (int nf = 0; nf < 4; nf++)
#pragma unroll
            for (int e = 0; e < 4; e++) acc[nf][e] = 0.0f;

        int kind, ut, nt, NI;
        const unsigned *Asrc, *Bsrc;
        if (tt < 3200) {
            kind = 0; ut = tt >> 3; nt = tt & 7; NI = 4;
            Asrc = g_dtq + (size_t)ut * 4 * 4096;
            Bsrc = g_Wtdhq + (size_t)nt * 4 * 4096;
        } else if (tt < 4800) {
            int u = tt - 3200;
            kind = 1; ut = u >> 2; nt = u & 3; NI = 8;
            Asrc = g_gxmq + (size_t)ut * 8 * 4096;
            Bsrc = g_Wcombq + (size_t)nt * 8 * 4096;
        } else {
            int u = tt - 4800;
            kind = 2; ut = u >> 5; nt = u & 31; NI = 4;
            Asrc = g_gxmq + (size_t)ut * 8 * 4096 + 4 * 4096;   // mask chunks 4..7
            Bsrc = g_Wgq + ((size_t)nt * 16 + 4) * 4096;        // W_ih mask cols (chunks 4..7)
        }
        const int m0 = ut * 64, n0 = nt * 64;

        LOADQ64(Asrc, Bsrc, 0); CMT;
        LOADQ64(Asrc + 4096, Bsrc + 4096, 1); CMT;
        LOADQ64(Asrc + 8192, Bsrc + 8192, 2); CMT;
        for (int i = 0; i < NI; i++) {
            WAIT2;
            __syncthreads();
            if (i + 3 < NI)
                LOADQ64(Asrc + (size_t)(i + 3) * 4096, Bsrc + (size_t)(i + 3) * 4096, (i + 3) & 3);
            CMT;
            int s = i & 3;
            mma64q(SHu + s * STW, SHu + s * STW + 4096, acc, wm, wn, lane);
        }
        __syncthreads();
#pragma unroll
        for (int nf = 0; nf < 4; nf++) {
#pragma unroll
            for (int e = 0; e < 4; e++) {
                int bt = m0 + wm * 16 + gid + ((e >> 1) << 3);
                int n = n0 + wn * 32 + nf * 8 + 2 * tg + (e & 1);
                float v = acc[nf][e];
                if (kind == 0)
                    g_gamma_h[(size_t)bt * Hn + n] = expf(-fmaxf(v + b_td_h[n], 0.f));
                else if (kind == 1)
                    g_alpha[(size_t)bt * Fn + n] = sigmoidf_(v + b_comb[n]);
                else
                    g_gate_base[(size_t)bt * 2048 + n] = v + g_bg[n];
            }
        }
    }
    gsync(sense);

    // =================== sequential recurrence (dataflow-synced, 4 groups) ===================
    for (int t = 0; t < Tn; t++) {
        const int par = t & 1, nxt = (t + 1) & 1;

        // ===== P_a: x_h = h_dec @ W_hist^T  (tile 64x32, K=512), CTAs cg<8 =====
        if (cg < 8) {
            const int n0 = cg * 32;
            wait_ge(&g_cnt_h[g], 32u * (unsigned)t);
            const unsigned* Ah = g_hq + (((size_t)par * 4 + g) * 8) * 4096;
            const unsigned* Bw = g_Whistq + (size_t)cg * 8 * 2048;
            float acc[2][4];
#pragma unroll
            for (int nf = 0; nf < 2; nf++)
#pragma unroll
                for (int e = 0; e < 4; e++) acc[nf][e] = 0.0f;
            LOADQ32(Ah, Bw, 0); CMT;
            LOADQ32(Ah + 4096, Bw + 2048, 1); CMT;
            LOADQ32(Ah + 8192, Bw + 4096, 2); CMT;
            for (int i = 0; i < 8; i++) {
                WAIT2;
                __syncthreads();
                if (i + 3 < 8)
                    LOADQ32(Ah + (size_t)(i + 3) * 4096, Bw + (size_t)(i + 3) * 2048, (i + 3) & 3);
                CMT;
                int s = i & 3;
                mma32q(SHu + s * STW, SHu + s * STW + 4096, acc, wm, wn, lane);
            }
            float ls = 0.0f;
#pragma unroll
            for (int nf = 0; nf < 2; nf++) {
#pragma unroll
                for (int e = 0; e < 4; e++) {
                    int r = wm * 16 + gid + ((e >> 1) << 3);
                    int b = b0 + r;
                    int f = n0 + wn * 16 + nf * 8 + 2 * tg + (e & 1);
                    float xh = acc[nf][e] + b_hist[f];
                    g_xh[b * Fn + f] = xh;
                    size_t vi = ((size_t)b * Tn + t) * Fn + f;
                    float x = values[vi], m = masks[vi];
                    ls += fabsf(xh - x) * m;
                    g_xcq[((size_t)g * 4 + (f >> 6)) * 4096 + o_A(r, f & 63)] =
                        f2tf(m * x + (1.0f - m) * xh);
                }
            }
            ls = wredsum(ls);
            if (lane == 0) RED[wid] = ls;
            __syncthreads();
            if (tid == 0) {
                float s = 0.f;
#pragma unroll
                for (int w = 0; w < 8; w++) s += RED[w];
                g_l1[t * 32 + g * 8 + cg] = s;
            }
            arrive(&g_cnt_xh[g]);
        }

        // ===== P_b: z_h = relu(x_c @ Wf^T) (tile 64x32, K=256) + epilogue =====
        if (cg < 8) {
            const int n0 = cg * 32;
            wait_ge(&g_cnt_xh[g], 8u * (unsigned)(t + 1));
            const unsigned* Ax = g_xcq + (size_t)g * 4 * 4096;
            const unsigned* Bf = g_Wfeatq + (size_t)cg * 4 * 2048;
            float acc[2][4];
#pragma unroll
            for (int nf = 0; nf < 2; nf++)
#pragma unroll
                for (int e = 0; e < 4; e++) acc[nf][e] = 0.0f;
            LOADQ32(Ax, Bf, 0); CMT;
            LOADQ32(Ax + 4096, Bf + 2048, 1); CMT;
            LOADQ32(Ax + 8192, Bf + 4096, 2); CMT;
            for (int i = 0; i < 4; i++) {
                WAIT2;
                __syncthreads();
                if (i + 3 < 4)
                    LOADQ32(Ax + (size_t)(i + 3) * 4096, Bf + (size_t)(i + 3) * 2048, (i + 3) & 3);
                CMT;
                int s = i & 3;
                mma32q(SHu + s * STW, SHu + s * STW + 4096, acc, wm, wn, lane);
            }
            float l2s = 0.f, l3s = 0.f, dns = 0.f;
#pragma unroll
            for (int nf = 0; nf < 2; nf++) {
#pragma unroll
                for (int e = 0; e < 4; e++) {
                    int r = wm * 16 + gid + ((e >> 1) << 3);
                    int b = b0 + r;
                    int f = n0 + wn * 16 + nf * 8 + 2 * tg + (e & 1);
                    size_t vi = ((size_t)b * Tn + t) * Fn + f;
                    float z = fmaxf(acc[nf][e] + b_feat[f], 0.0f);
                    float al = g_alpha[vi];
                    float xh = g_xh[b * Fn + f];
                    float x = values[vi], m = masks[vi];
                    float ch = al * z + (1.0f - al) * xh;
                    float cc = m * x + (1.0f - m) * ch;
                    out[vi] = cc;
                    g_ccq[((size_t)g * 4 + (f >> 6)) * 4096 + o_A(r, f & 63)] = f2tf(cc);
                    l2s += fabsf(z - x) * m;
                    l3s += fabsf(ch - x) * m;
                    dns += m;
                }
            }
            l2s = wredsum(l2s); l3s = wredsum(l3s); dns = wredsum(dns);
            if (lane == 0) { RED[wid] = l2s; RED[8 + wid] = l3s; RED[16 + wid] = dns; }
            __syncthreads();
            if (tid == 0) {
                float s2 = 0.f, s3 = 0.f, sd = 0.f;
#pragma unroll
                for (int w = 0; w < 8; w++) { s2 += RED[w]; s3 += RED[8 + w]; sd += RED[16 + w]; }
                int slot = t * 32 + g * 8 + cg;
                g_l2[slot] = s2; g_l3[slot] = s3; g_den[slot] = sd;
            }
            arrive(&g_cnt_cc[g]);
        }

        // ===== P_c: gates (tile 64x64 virt, K=768) + fused LSTM, all 32 CTAs =====
        {
            wait_ge(&g_cnt_cc[g], 8u * (unsigned)(t + 1));
            float acc[4][4];
#pragma unroll
            for (int nf = 0; nf < 4; nf++)
#pragma unroll
                for (int e = 0; e < 4; e++) acc[nf][e] = 0.0f;
            LOADQ64(pcA(g, par, 0), pcB(cg, 0), 0); CMT;
            LOADQ64(pcA(g, par, 1), pcB(cg, 1), 1); CMT;
            LOADQ64(pcA(g, par, 2), pcB(cg, 2), 2); CMT;
            for (int i = 0; i < 12; i++) {
                WAIT2;
                __syncthreads();
                if (i + 3 < 12)
                    LOADQ64(pcA(g, par, i + 3), pcB(cg, i + 3), (i + 3) & 3);
                CMT;
                int s = i & 3;
                mma64q(SHu + s * STW, SHu + s * STW + 4096, acc, wm, wn, lane);
            }
            __syncthreads();
            float* EP = (float*)SHu;
#pragma unroll
            for (int nf = 0; nf < 4; nf++)
#pragma unroll
                for (int e = 0; e < 4; e++) {
                    int r = wm * 16 + gid + ((e >> 1) << 3);
                    int cL = wn * 32 + nf * 8 + 2 * tg + (e & 1);
                    EP[r * EPIT + cL] = acc[nf][e];
                }
            __syncthreads();
#pragma unroll
            for (int q = 0; q < 4; q++) {
                int idx = tid + q * 256;
                int r = idx >> 4, jl = idx & 15;
                int b = b0 + r;
                int j = cg * 16 + jl;
                float4 base = *(const float4*)&g_gate_base[((size_t)b * Tn + t) * 2048 + (size_t)j * 4];
                float ia = EP[r * EPIT + jl * 4 + 0] + base.x;
                float fa = EP[r * EPIT + jl * 4 + 1] + base.y;
                float ga = EP[r * EPIT + jl * 4 + 2] + base.z;
                float oa = EP[r * EPIT + jl * 4 + 3] + base.w;
                int ci = b * Hn + j;
                float cn = sigmoidf_(fa) * g_cst[ci] + sigmoidf_(ia) * tanhf(ga);
                float hn = sigmoidf_(oa) * tanhf(cn);
                g_cst[ci] = cn;
                if (t + 1 < Tn) {
                    float hd = hn * g_gamma_h[((size_t)b * Tn + t + 1) * Hn + j];
                    g_hq[(((size_t)nxt * 4 + g) * 8 + (j >> 6)) * 4096 + o_A(r, j & 63)] = f2tf(hd);
                } else {
                    out[BTF + ci] = hn;
                }
            }
            arrive(&g_cnt_h[g]);
        }
    }

    gsync(sense);

    // =================== final deterministic loss reduction + counter reset ===================
    if (cta == 0) {
        float v = 0.0f;
        if (tid < Tn) {
            float den = 1e-9f, n1 = 0.f, n2 = 0.f, n3 = 0.f;
            for (int c2 = 0; c2 < 32; c2++) {
                den += g_den[tid * 32 + c2];
                n1 += g_l1[tid * 32 + c2];
                n2 += g_l2[tid * 32 + c2];
                n3 += g_l3[tid * 32 + c2];
            }
            v = (n1 + n2 + n3) / den;
        }
        __syncthreads();
        RED[tid] = v;
        __syncthreads();
#pragma unroll
        for (int s = 128; s > 0; s >>= 1) {
            if (tid < s) RED[tid] += RED[tid + s];
            __syncthreads();
        }
        if (tid == 0) {
            out[BTF + Bn * Hn] = RED[0] / (3.0f * Tn);
#pragma unroll
            for (int i = 0; i < 4; i++) { g_cnt_h[i] = 0u; g_cnt_xh[i] = 0u; g_cnt_cc[i] = 0u; }
            __threadfence();
        }
    }
}

extern "C" void kernel_launch(void* const* d_in, const int* in_sizes, int n_in,
                              void* d_out, int out_size) {
    (void)in_sizes; (void)n_in; (void)out_size;
    static int configured = 0;
    if (!configured) {
        cudaFuncSetAttribute(rits_kernel, cudaFuncAttributeMaxDynamicSharedMemorySize,
                             SMEM_BYTES);
        configured = 1;
    }
    rits_kernel<<<NB, NT, SMEM_BYTES>>>(
        (const float*)d_in[0],  (const float*)d_in[1],  (const float*)d_in[2],
        (const float*)d_in[3],  (const float*)d_in[4],  (const float*)d_in[5],
        (const float*)d_in[6],  (const float*)d_in[7],  (const float*)d_in[8],
        (const float*)d_in[9],  (const float*)d_in[10], (const float*)d_in[11],
        (const float*)d_in[12], (const float*)d_in[13], (const float*)d_in[14],
        (const float*)d_in[15], (const float*)d_in[16],
        (float*)d_out);
}

// round 12
// speedup vs baseline: 1.7325x; 1.3015x over previous
#include <cuda_runtime.h>
#include <math.h>

#define Bn 256
#define Tn 100
#define Fn 256
#define Hn 512
#define NB 128
#define NT 256
#define BT (Bn * Tn)
#define STW 8192                   // stage words: A 4096 + B 4096
#define NSTG 4
#define EPIT 68
#define SMEM_WORDS (NSTG * STW + 256)
#define SMEM_BYTES (SMEM_WORDS * 4)
#define BTF ((size_t)Bn * Tn * Fn)

// ---------------- global scratch (allocation-free rule) ----------------
__device__ unsigned g_dtq[(size_t)400 * 4 * 4096];   // deltas quads, bt-tiles
__device__ unsigned g_gxmq[(size_t)400 * 8 * 4096];  // [gamma_x | mask] quads
__device__ unsigned g_mq[(size_t)4 * Tn * 4 * 4096]; // masks quads, (group,t)-tiles
__device__ unsigned g_Wtdhq[8 * 4 * 4096];
__device__ unsigned g_Wcombq[4 * 8 * 4096];
__device__ unsigned g_Whistq[8 * 8 * 2048];
__device__ unsigned g_Wfeatq[8 * 4 * 2048];
__device__ unsigned g_Wgq[32 * 16 * 4096];           // gates W, rows j*4+gate
__device__ unsigned g_hq[2 * 4 * 8 * 4096];          // h_dec quads (double buffer)
__device__ unsigned g_xcq[4 * 4 * 4096];
__device__ unsigned g_ccq[4 * 4 * 4096];
__device__ float g_gamma_h[(size_t)BT * Hn];
__device__ float g_alpha[(size_t)BT * Fn];
__device__ float g_bg[4 * Hn];
__device__ float g_cst[Bn * Hn];
__device__ float g_l1[Tn * 32], g_l2[Tn * 32], g_l3[Tn * 32], g_den[Tn * 32];
__device__ unsigned g_cnt, g_sense;
__device__ unsigned g_cnt_h[4], g_cnt_xh[4], g_cnt_cc[4];

__device__ __forceinline__ float sigmoidf_(float x) { return 1.0f / (1.0f + expf(-x)); }

__device__ __forceinline__ unsigned f2tf(float f) {
    unsigned u;
    asm("cvt.rna.tf32.f32 %0, %1;" : "=r"(u) : "f"(f));
    return u;
}

// quad layouts (validated rounds 7-11)
__device__ __forceinline__ int o_A(int r, int k) {
    return ((r >> 4) * 8 + (k >> 3)) * 128 + ((r & 7) * 4 + (k & 3)) * 4 +
           ((k & 4) >> 1) + ((r & 8) >> 3);
}
__device__ __forceinline__ int o_B(int n, int k) {
    return ((n >> 4) * 8 + (k >> 3)) * 128 + ((n & 7) * 4 + (k & 3)) * 4 +
           ((n >> 3) & 1) * 2 + ((k >> 2) & 1);
}

#define MMA(d, A0, A1, A2, A3, B0, B1)                                          \
    asm volatile("mma.sync.aligned.m16n8k8.row.col.f32.tf32.tf32.f32 "          \
                 "{%0,%1,%2,%3},{%4,%5,%6,%7},{%8,%9},{%0,%1,%2,%3};"           \
                 : "+f"(d[0]), "+f"(d[1]), "+f"(d[2]), "+f"(d[3])               \
                 : "r"(A0), "r"(A1), "r"(A2), "r"(A3), "r"(B0), "r"(B1))

#define CPA(boff, p)                                                            \
    asm volatile("cp.async.cg.shared.global [%0], [%1], 16;"                    \
                 :: "r"(sbase + (unsigned)(boff)), "l"(p) : "memory")
#define CMT   asm volatile("cp.async.commit_group;" ::: "memory")
#define WAIT2 asm volatile("cp.async.wait_group 2;" ::: "memory")

// full 64x64 stage (A 4096 + B 4096 words)
#define LOADQ64(pA, pB, s) do {                                                 \
    unsigned _off = (unsigned)((s) * STW * 4);                                  \
    _Pragma("unroll")                                                           \
    for (int _j = 0; _j < 4; _j++) { int _c = tid + _j * 256;                   \
        CPA(_off + (unsigned)_c * 16u, (pA) + _c * 4);                          \
        CPA(_off + 16384u + (unsigned)_c * 16u, (pB) + _c * 4); }               \
} while (0)
// full 64x32 stage (A 4096 + B 2048 words)
#define LOADQ32(pA, pB, s) do {                                                 \
    unsigned _off = (unsigned)((s) * STW * 4);                                  \
    _Pragma("unroll")                                                           \
    for (int _j = 0; _j < 4; _j++) { int _c = tid + _j * 256;                   \
        CPA(_off + (unsigned)_c * 16u, (pA) + _c * 4); }                        \
    _Pragma("unroll")                                                           \
    for (int _j = 0; _j < 2; _j++) { int _c = tid + _j * 256;                   \
        CPA(_off + 16384u + (unsigned)_c * 16u, (pB) + _c * 4); }               \
} while (0)
// split halves: B issued pre-wait, A post-wait
#define LOADB64(pB, s) do {                                                     \
    unsigned _off = (unsigned)((s) * STW * 4) + 16384u;                         \
    _Pragma("unroll")                                                           \
    for (int _j = 0; _j < 4; _j++) { int _c = tid + _j * 256;                   \
        CPA(_off + (unsigned)_c * 16u, (pB) + _c * 4); }                        \
} while (0)
#define LOADA64(pA, s) do {                                                     \
    unsigned _off = (unsigned)((s) * STW * 4);                                  \
    _Pragma("unroll")                                                           \
    for (int _j = 0; _j < 4; _j++) { int _c = tid + _j * 256;                   \
        CPA(_off + (unsigned)_c * 16u, (pA) + _c * 4); }                        \
} while (0)
#define LOADB32(pB, s) do {                                                     \
    unsigned _off = (unsigned)((s) * STW * 4) + 16384u;                         \
    _Pragma("unroll")                                                           \
    for (int _j = 0; _j < 2; _j++) { int _c = tid + _j * 256;                   \
        CPA(_off + (unsigned)_c * 16u, (pB) + _c * 4); }                        \
} while (0)
#define LOADA32(pA, s) do {                                                     \
    unsigned _off = (unsigned)((s) * STW * 4);                                  \
    _Pragma("unroll")                                                           \
    for (int _j = 0; _j < 4; _j++) { int _c = tid + _j * 256;                   \
        CPA(_off + (unsigned)_c * 16u, (pA) + _c * 4); }                        \
} while (0)

// ---------------- sync primitives ----------------
__device__ __forceinline__ void gsync(unsigned& sense) {
    __threadfence();
    __syncthreads();
    unsigned target = sense ^ 1u;
    if (threadIdx.x == 0) {
        unsigned old = atomicAdd(&g_cnt, 1u);
        if (old == NB - 1) {
            g_cnt = 0;
            __threadfence();
            atomicExch(&g_sense, target);
        } else {
            while (atomicAdd(&g_sense, 0u) != target) { __nanosleep(128); }
        }
        __threadfence();
    }
    sense = target;
    __syncthreads();
}
// Consumer wait, NO acquire fence (validated R11): all cross-CTA loop data is
// consumed via cp.async.cg (reads at L2 = the release fence's drain point);
// in-loop LDG reads are CTA-local, same-thread, or frozen before gsync.
__device__ __forceinline__ void wait_ge(unsigned* cnt, unsigned target) {
    if (threadIdx.x == 0) {
        while (atomicAdd(cnt, 0u) < target) { __nanosleep(64); }
    }
    __syncthreads();
}
__device__ __forceinline__ void arrive(unsigned* cnt) {
    __threadfence();               // release: ALL threads' stores -> L2
    __syncthreads();
    if (threadIdx.x == 0) atomicAdd(cnt, 1u);
}
__device__ __forceinline__ float wredsum(float v) {
#pragma unroll
    for (int o = 16; o; o >>= 1) v += __shfl_xor_sync(0xffffffffu, v, o);
    return v;
}

// ---------------- quad MMA bodies (R7, proven) ----------------
__device__ __forceinline__ void mma64q(const unsigned* As, const unsigned* Bs,
                                       float acc[4][4], int wm, int wn, int lane) {
#pragma unroll
    for (int ks = 0; ks < 8; ks++) {
        uint4 a = *(const uint4*)&As[((wm * 8 + ks) * 32 + lane) * 4];
        uint4 b0 = *(const uint4*)&Bs[(((wn * 2 + 0) * 8 + ks) * 32 + lane) * 4];
        uint4 b1 = *(const uint4*)&Bs[(((wn * 2 + 1) * 8 + ks) * 32 + lane) * 4];
        MMA(acc[0], a.x, a.y, a.z, a.w, b0.x, b0.y);
        MMA(acc[1], a.x, a.y, a.z, a.w, b0.z, b0.w);
        MMA(acc[2], a.x, a.y, a.z, a.w, b1.x, b1.y);
        MMA(acc[3], a.x, a.y, a.z, a.w, b1.z, b1.w);
    }
}
__device__ __forceinline__ void mma32q(const unsigned* As, const unsigned* Bs,
                                       float acc[2][4], int wm, int wn, int lane) {
#pragma unroll
    for (int ks = 0; ks < 8; ks++) {
        uint4 a = *(const uint4*)&As[((wm * 8 + ks) * 32 + lane) * 4];
        uint4 b = *(const uint4*)&Bs[((wn * 8 + ks) * 32 + lane) * 4];
        MMA(acc[0], a.x, a.y, a.z, a.w, b.x, b.y);
        MMA(acc[1], a.x, a.y, a.z, a.w, b.z, b.w);
    }
}

__device__ __forceinline__ const unsigned* pcA(int g, int t, int par, int kc) {
    if (kc < 4)  return g_ccq + ((size_t)g * 4 + kc) * 4096;
    if (kc < 8)  return g_mq + (((size_t)g * Tn + t) * 4 + (kc - 4)) * 4096;
    return g_hq + (((size_t)par * 4 + g) * 8 + (kc - 8)) * 4096;
}

__global__ void __launch_bounds__(NT, 1) rits_kernel(
    const float* __restrict__ values, const float* __restrict__ masks,
    const float* __restrict__ deltas,
    const float* __restrict__ W_td_h, const float* __restrict__ b_td_h,
    const float* __restrict__ W_td_x, const float* __restrict__ b_td_x,
    const float* __restrict__ W_hist, const float* __restrict__ b_hist,
    const float* __restrict__ W_feat, const float* __restrict__ b_feat,
    const float* __restrict__ W_comb, const float* __restrict__ b_comb,
    const float* __restrict__ W_ih, const float* __restrict__ W_hh,
    const float* __restrict__ b_ih, const float* __restrict__ b_hh,
    float* __restrict__ out)
{
    extern __shared__ unsigned SHu[];
    float* RED = (float*)(SHu + NSTG * STW);
    unsigned sbase = (unsigned)__cvta_generic_to_shared(SHu);

    const int tid = threadIdx.x;
    const int cta = blockIdx.x;
    const int wid = tid >> 5;
    const int lane = tid & 31;
    const int gid = lane >> 2;
    const int tg = lane & 3;
    const int wm = wid & 3, wn = wid >> 2;

    const int g = cta >> 5;
    const int cg = cta & 31;
    const int b0 = g * 64;

    unsigned sense = *((volatile unsigned*)&g_sense);

    // =================== init: state + tf32 quad pre-conversion ===================
    for (int i = cta * NT + tid; i < Bn * Hn; i += NB * NT) g_cst[i] = 0.0f;
    for (int i = cta * NT + tid; i < 2 * 4 * 8 * 4096; i += NB * NT) g_hq[i] = 0u;

    for (int i4 = cta * NT + tid; i4 < BT * Fn / 4; i4 += NB * NT) {
        int bt = i4 >> 6;
        int f0 = (i4 & 63) * 4;
        float4 d = ((const float4*)deltas)[i4];
        float4 mk = ((const float4*)masks)[i4];
        int u = bt >> 6, r = bt & 63;
        int b = bt / Tn;
        int tt2 = bt - b * Tn;
        int g2 = b >> 6, r2 = b & 63;
        float dv[4] = {d.x, d.y, d.z, d.w};
        float mv[4] = {mk.x, mk.y, mk.z, mk.w};
#pragma unroll
        for (int q = 0; q < 4; q++) {
            int f = f0 + q;
            int kc = f >> 6, k = f & 63;
            int oa = o_A(r, k);
            float gx = expf(-fmaxf(fmaf(dv[q], W_td_x[f * Fn + f], b_td_x[f]), 0.f));
            unsigned mu = f2tf(mv[q]);
            g_dtq[((size_t)u * 4 + kc) * 4096 + oa] = f2tf(dv[q]);
            g_gxmq[((size_t)u * 8 + kc) * 4096 + oa] = f2tf(gx);
            g_gxmq[((size_t)u * 8 + 4 + kc) * 4096 + oa] = mu;
            g_mq[(((size_t)g2 * Tn + tt2) * 4 + kc) * 4096 + o_A(r2, k)] = mu;
        }
    }
    for (int i = cta * NT + tid; i < 512 * 256; i += NB * NT) {
        int n = i >> 8, k = i & 255;
        g_Wtdhq[((n >> 6) * 4 + (k >> 6)) * 4096 + o_B(n & 63, k & 63)] = f2tf(W_td_h[i]);
    }
    for (int i = cta * NT + tid; i < 256 * 512; i += NB * NT) {
        int n = i >> 9, k = i & 511;
        g_Wcombq[((n >> 6) * 8 + (k >> 6)) * 4096 + o_B(n & 63, k & 63)] = f2tf(W_comb[i]);
        g_Whistq[((n >> 5) * 8 + (k >> 6)) * 2048 + o_B(n & 31, k & 63)] = f2tf(W_hist[i]);
    }
    for (int i = cta * NT + tid; i < 256 * 256; i += NB * NT) {
        int n = i >> 8, k = i & 255;
        float w = (n == k) ? 0.0f : W_feat[i];
        g_Wfeatq[((n >> 5) * 4 + (k >> 6)) * 2048 + o_B(n & 31, k & 63)] = f2tf(w);
    }
    for (int i = cta * NT + tid; i < 2048 * 1024; i += NB * NT) {
        int np = i >> 10, k = i & 1023;
        int j = np >> 2, gate = np & 3;
        float w = (k < 512) ? W_ih[(size_t)(gate * Hn + j) * 512 + k]
                            : W_hh[(size_t)(gate * Hn + j) * 512 + (k - 512)];
        g_Wgq[((np >> 6) * 16 + (k >> 6)) * 4096 + o_B(np & 63, k & 63)] = f2tf(w);
    }
    for (int i = cta * NT + tid; i < 4 * Hn; i += NB * NT) {
        int j = i >> 2, gate = i & 3;
        g_bg[i] = b_ih[gate * Hn + j] + b_hh[gate * Hn + j];
    }
    gsync(sense);

    // =================== precompute gamma_h (3200 tiles) + alpha (1600) ===================
    for (int tt = cta; tt < 4800; tt += NB) {
        float acc[4][4];
#pragma unroll
        for (int nf = 0; nf < 4; nf++)
#pragma unroll
            for (int e = 0; e < 4; e++) acc[nf][e] = 0.0f;

        const bool isg = (tt < 3200);
        const int u = isg ? tt : tt - 3200;
        const int ut = isg ? (u >> 3) : (u >> 2);
        const int nt = isg ? (u & 7) : (u & 3);
        const int m0 = ut * 64, n0 = nt * 64;
        const int NI = isg ? 4 : 8;
        const unsigned* Asrc = isg ? (g_dtq + (size_t)ut * 4 * 4096)
                                   : (g_gxmq + (size_t)ut * 8 * 4096);
        const unsigned* Bsrc = isg ? (g_Wtdhq + (size_t)nt * 4 * 4096)
                                   : (g_Wcombq + (size_t)nt * 8 * 4096);

        LOADQ64(Asrc, Bsrc, 0); CMT;
        LOADQ64(Asrc + 4096, Bsrc + 4096, 1); CMT;
        LOADQ64(Asrc + 8192, Bsrc + 8192, 2); CMT;
        for (int i = 0; i < NI; i++) {
            WAIT2;
            __syncthreads();
            if (i + 3 < NI)
                LOADQ64(Asrc + (size_t)(i + 3) * 4096, Bsrc + (size_t)(i + 3) * 4096, (i + 3) & 3);
            CMT;
            int s = i & 3;
            mma64q(SHu + s * STW, SHu + s * STW + 4096, acc, wm, wn, lane);
        }
        __syncthreads();
#pragma unroll
        for (int nf = 0; nf < 4; nf++) {
#pragma unroll
            for (int e = 0; e < 4; e++) {
                int bt = m0 + wm * 16 + gid + ((e >> 1) << 3);
                int n = n0 + wn * 32 + nf * 8 + 2 * tg + (e & 1);
                float v = acc[nf][e];
                if (isg)
                    g_gamma_h[(size_t)bt * Hn + n] = expf(-fmaxf(v + b_td_h[n], 0.f));
                else
                    g_alpha[(size_t)bt * Fn + n] = sigmoidf_(v + b_comb[n]);
            }
        }
    }
    gsync(sense);

    // =================== sequential recurrence (dataflow-synced, 4 groups) ===================
    for (int t = 0; t < Tn; t++) {
        const int par = t & 1, nxt = (t + 1) & 1;
        float xh_r[2][4], x_r[2][4], m_r[2][4];

        // ===== P_a: x_h = h_dec @ W_hist^T  (tile 64x32, K=512), CTAs cg<8 =====
        if (cg < 8) {
            const int n0 = cg * 32;
            const unsigned* Ah = g_hq + (((size_t)par * 4 + g) * 8) * 4096;
            const unsigned* Bw = g_Whistq + (size_t)cg * 8 * 2048;
            // pre-wait: weights start fetching; pure-input epilogue operands prefetch
            LOADB32(Bw, 0); LOADB32(Bw + 2048, 1); LOADB32(Bw + 4096, 2); CMT;
#pragma unroll
            for (int nf = 0; nf < 2; nf++) {
#pragma unroll
                for (int hh = 0; hh < 2; hh++) {
                    int b = b0 + wm * 16 + gid + hh * 8;
                    int f0 = n0 + wn * 16 + nf * 8 + 2 * tg;
                    size_t vi = ((size_t)b * Tn + t) * Fn + f0;
                    float2 xv = *(const float2*)&values[vi];
                    float2 mv = *(const float2*)&masks[vi];
                    x_r[nf][hh * 2 + 0] = xv.x; x_r[nf][hh * 2 + 1] = xv.y;
                    m_r[nf][hh * 2 + 0] = mv.x; m_r[nf][hh * 2 + 1] = mv.y;
                }
            }
            wait_ge(&g_cnt_h[g], 32u * (unsigned)t);
            LOADA32(Ah, 0); CMT;
            LOADA32(Ah + 4096, 1); CMT;
            LOADA32(Ah + 8192, 2); CMT;
            float acc[2][4];
#pragma unroll
            for (int nf = 0; nf < 2; nf++)
#pragma unroll
                for (int e = 0; e < 4; e++) acc[nf][e] = 0.0f;
            for (int i = 0; i < 8; i++) {
                WAIT2;
                __syncthreads();
                if (i + 3 < 8)
                    LOADQ32(Ah + (size_t)(i + 3) * 4096, Bw + (size_t)(i + 3) * 2048, (i + 3) & 3);
                CMT;
                int s = i & 3;
                mma32q(SHu + s * STW, SHu + s * STW + 4096, acc, wm, wn, lane);
            }
            float ls = 0.0f;
#pragma unroll
            for (int nf = 0; nf < 2; nf++) {
#pragma unroll
                for (int e = 0; e < 4; e++) {
                    int r = wm * 16 + gid + ((e >> 1) << 3);
                    int f = n0 + wn * 16 + nf * 8 + 2 * tg + (e & 1);
                    float xh = acc[nf][e] + b_hist[f];
                    float x = x_r[nf][e], m = m_r[nf][e];
                    xh_r[nf][e] = xh;
                    ls += fabsf(xh - x) * m;
                    g_xcq[((size_t)g * 4 + (f >> 6)) * 4096 + o_A(r, f & 63)] =
                        f2tf(m * x + (1.0f - m) * xh);
                }
            }
            ls = wredsum(ls);
            if (lane == 0) RED[wid] = ls;
            __syncthreads();
            if (tid == 0) {
                float s = 0.f;
#pragma unroll
                for (int w = 0; w < 8; w++) s += RED[w];
                g_l1[t * 32 + g * 8 + cg] = s;
            }
            arrive(&g_cnt_xh[g]);
        }

        // ===== P_b: z_h = relu(x_c @ Wf^T) (tile 64x32, K=256) + epilogue =====
        if (cg < 8) {
            const int n0 = cg * 32;
            const unsigned* Ax = g_xcq + (size_t)g * 4 * 4096;
            const unsigned* Bf = g_Wfeatq + (size_t)cg * 4 * 2048;
            LOADB32(Bf, 0); LOADB32(Bf + 2048, 1); LOADB32(Bf + 4096, 2); CMT;
            float al_r[2][4];
#pragma unroll
            for (int nf = 0; nf < 2; nf++) {
#pragma unroll
                for (int hh = 0; hh < 2; hh++) {
                    int b = b0 + wm * 16 + gid + hh * 8;
                    int f0 = n0 + wn * 16 + nf * 8 + 2 * tg;
                    size_t vi = ((size_t)b * Tn + t) * Fn + f0;
                    float2 av = *(const float2*)&g_alpha[vi];
                    al_r[nf][hh * 2 + 0] = av.x; al_r[nf][hh * 2 + 1] = av.y;
                }
            }
            wait_ge(&g_cnt_xh[g], 8u * (unsigned)(t + 1));
            LOADA32(Ax, 0); CMT;
            LOADA32(Ax + 4096, 1); CMT;
            LOADA32(Ax + 8192, 2); CMT;
            float acc[2][4];
#pragma unroll
            for (int nf = 0; nf < 2; nf++)
#pragma unroll
                for (int e = 0; e < 4; e++) acc[nf][e] = 0.0f;
            for (int i = 0; i < 4; i++) {
                WAIT2;
                __syncthreads();
                if (i + 3 < 4)
                    LOADQ32(Ax + (size_t)(i + 3) * 4096, Bf + (size_t)(i + 3) * 2048, (i + 3) & 3);
                CMT;
                int s = i & 3;
                mma32q(SHu + s * STW, SHu + s * STW + 4096, acc, wm, wn, lane);
            }
            float l2s = 0.f, l3s = 0.f, dns = 0.f;
#pragma unroll
            for (int nf = 0; nf < 2; nf++) {
#pragma unroll
                for (int e = 0; e < 4; e++) {
                    int r = wm * 16 + gid + ((e >> 1) << 3);
                    int b = b0 + r;
                    int f = n0 + wn * 16 + nf * 8 + 2 * tg + (e & 1);
                    size_t vi = ((size_t)b * Tn + t) * Fn + f;
                    float z = fmaxf(acc[nf][e] + b_feat[f], 0.0f);
                    float al = al_r[nf][e];
                    float x = x_r[nf][e], m = m_r[nf][e];
                    float ch = al * z + (1.0f - al) * xh_r[nf][e];
                    float cc = m * x + (1.0f - m) * ch;
                    out[vi] = cc;
                    g_ccq[((size_t)g * 4 + (f >> 6)) * 4096 + o_A(r, f & 63)] = f2tf(cc);
                    l2s += fabsf(z - x) * m;
                    l3s += fabsf(ch - x) * m;
                    dns += m;
                }
            }
            l2s = wredsum(l2s); l3s = wredsum(l3s); dns = wredsum(dns);
            if (lane == 0) { RED[wid] = l2s; RED[8 + wid] = l3s; RED[16 + wid] = dns; }
            __syncthreads();
            if (tid == 0) {
                float s2 = 0.f, s3 = 0.f, sd = 0.f;
#pragma unroll
                for (int w = 0; w < 8; w++) { s2 += RED[w]; s3 += RED[8 + w]; sd += RED[16 + w]; }
                int slot = t * 32 + g * 8 + cg;
                g_l2[slot] = s2; g_l3[slot] = s3; g_den[slot] = sd;
            }
            arrive(&g_cnt_cc[g]);
        }

        // ===== P_c: gates (tile 64x64 virt, K=1024) + fused LSTM, all 32 CTAs =====
        {
            const unsigned* Bb = g_Wgq + (size_t)cg * 16 * 4096;
            LOADB64(Bb, 0); LOADB64(Bb + 4096, 1); LOADB64(Bb + 8192, 2); CMT;
            float cst_r[4], gam_r[4];
#pragma unroll
            for (int q = 0; q < 4; q++) {
                int idx = tid + q * 256;
                int r = idx >> 4, jl = idx & 15;
                int b = b0 + r;
                int j = cg * 16 + jl;
                cst_r[q] = g_cst[b * Hn + j];        // same-thread write last step
                gam_r[q] = (t + 1 < Tn)
                         ? g_gamma_h[((size_t)b * Tn + t + 1) * Hn + j] : 0.0f;
            }
            wait_ge(&g_cnt_cc[g], 8u * (unsigned)(t + 1));
            LOADA64(pcA(g, t, par, 0), 0); CMT;
            LOADA64(pcA(g, t, par, 1), 1); CMT;
            LOADA64(pcA(g, t, par, 2), 2); CMT;
            float acc[4][4];
#pragma unroll
            for (int nf = 0; nf < 4; nf++)
#pragma unroll
                for (int e = 0; e < 4; e++) acc[nf][e] = 0.0f;
            for (int i = 0; i < 16; i++) {
                WAIT2;
                __syncthreads();
                if (i + 3 < 16)
                    LOADQ64(pcA(g, t, par, i + 3), Bb + (size_t)(i + 3) * 4096, (i + 3) & 3);
                CMT;
                int s = i & 3;
                mma64q(SHu + s * STW, SHu + s * STW + 4096, acc, wm, wn, lane);
            }
            __syncthreads();
            float* EP = (float*)SHu;
#pragma unroll
            for (int nf = 0; nf < 4; nf++)
#pragma unroll
                for (int e = 0; e < 4; e++) {
                    int r = wm * 16 + gid + ((e >> 1) << 3);
                    int cL = wn * 32 + nf * 8 + 2 * tg + (e & 1);
                    EP[r * EPIT + cL] = acc[nf][e];
                }
            __syncthreads();
#pragma unroll
            for (int q = 0; q < 4; q++) {
                int idx = tid + q * 256;
                int r = idx >> 4, jl = idx & 15;
                int b = b0 + r;
                int j = cg * 16 + jl;
                float ia = EP[r * EPIT + jl * 4 + 0] + g_bg[j * 4 + 0];
                float fa = EP[r * EPIT + jl * 4 + 1] + g_bg[j * 4 + 1];
                float ga = EP[r * EPIT + jl * 4 + 2] + g_bg[j * 4 + 2];
                float oa = EP[r * EPIT + jl * 4 + 3] + g_bg[j * 4 + 3];
                int ci = b * Hn + j;
                float cn = sigmoidf_(fa) * cst_r[q] + sigmoidf_(ia) * tanhf(ga);
                float hn = sigmoidf_(oa) * tanhf(cn);
                g_cst[ci] = cn;
                if (t + 1 < Tn) {
                    g_hq[(((size_t)nxt * 4 + g) * 8 + (j >> 6)) * 4096 + o_A(r, j & 63)] =
                        f2tf(hn * gam_r[q]);
                } else {
                    out[BTF + ci] = hn;
                }
            }
            arrive(&g_cnt_h[g]);
        }
    }

    gsync(sense);

    // =================== final deterministic loss reduction + counter reset ===================
    if (cta == 0) {
        float v = 0.0f;
        if (tid < Tn) {
            float den = 1e-9f, n1 = 0.f, n2 = 0.f, n3 = 0.f;
            for (int c2 = 0; c2 < 32; c2++) {
                den += g_den[tid * 32 + c2];
                n1 += g_l1[tid * 32 + c2];
                n2 += g_l2[tid * 32 + c2];
                n3 += g_l3[tid * 32 + c2];
            }
            v = (n1 + n2 + n3) / den;
        }
        __syncthreads();
        RED[tid] = v;
        __syncthreads();
#pragma unroll
        for (int s = 128; s > 0; s >>= 1) {
            if (tid < s) RED[tid] += RED[tid + s];
            __syncthreads();
        }
        if (tid == 0) {
            out[BTF + Bn * Hn] = RED[0] / (3.0f * Tn);
#pragma unroll
            for (int i = 0; i < 4; i++) { g_cnt_h[i] = 0u; g_cnt_xh[i] = 0u; g_cnt_cc[i] = 0u; }
            __threadfence();
        }
    }
}

extern "C" void kernel_launch(void* const* d_in, const int* in_sizes, int n_in,
                              void* d_out, int out_size) {
    (void)in_sizes; (void)n_in; (void)out_size;
    static int configured = 0;
    if (!configured) {
        cudaFuncSetAttribute(rits_kernel, cudaFuncAttributeMaxDynamicSharedMemorySize,
                             SMEM_BYTES);
        configured = 1;
    }
    rits_kernel<<<NB, NT, SMEM_BYTES>>>(
        (const float*)d_in[0],  (const float*)d_in[1],  (const float*)d_in[2],
        (const float*)d_in[3],  (const float*)d_in[4],  (const float*)d_in[5],
        (const float*)d_in[6],  (const float*)d_in[7],  (const float*)d_in[8],
        (const float*)d_in[9],  (const float*)d_in[10], (const float*)d_in[11],
        (const float*)d_in[12], (const float*)d_in[13], (const float*)d_in[14],
        (const float*)d_in[15], (const float*)d_in[16],
        (float*)d_out);
}

// round 13
// speedup vs baseline: 1.7776x; 1.0260x over previous
#include <cuda_runtime.h>
#include <math.h>

#define Bn 256
#define Tn 100
#define Fn 256
#define Hn 512
#define NB 128
#define NT 256
#define BT (Bn * Tn)
#define STW 8192                   // stage words: A 4096 + B 4096
#define NSTG 4
#define EPIT 68
#define SMEM_WORDS (NSTG * STW + 256)
#define SMEM_BYTES (SMEM_WORDS * 4)
#define BTF ((size_t)Bn * Tn * Fn)
#define NTH (NB * NT)

// ---------------- global scratch (allocation-free rule) ----------------
__device__ unsigned g_dtq[(size_t)400 * 4 * 4096];   // deltas quads, bt-tiles
__device__ unsigned g_gxmq[(size_t)400 * 8 * 4096];  // [gamma_x | mask] quads
__device__ unsigned g_mq[(size_t)4 * Tn * 4 * 4096]; // masks quads, (group,t)-tiles
__device__ unsigned g_Wtdhq[8 * 4 * 4096];
__device__ unsigned g_Wcombq[4 * 8 * 4096];
__device__ unsigned g_Whistq[8 * 8 * 2048];
__device__ unsigned g_Wfeatq[8 * 4 * 2048];
__device__ unsigned g_Wgq[32 * 16 * 4096];           // gates W, rows j*4+gate
__device__ unsigned g_hq[2 * 4 * 8 * 4096];          // h_dec quads (double buffer)
__device__ unsigned g_xcq[4 * 4 * 4096];
__device__ unsigned g_ccq[4 * 4 * 4096];
__device__ float g_gamma_h[(size_t)BT * Hn];
__device__ float g_alpha[(size_t)BT * Fn];
__device__ float g_bg[4 * Hn];
__device__ float g_cst[Bn * Hn];
__device__ float g_l1[Tn * 32], g_l2[Tn * 32], g_l3[Tn * 32], g_den[Tn * 32];
__device__ unsigned g_cnt, g_sense;
__device__ unsigned g_cnt_h[4], g_cnt_xh[4], g_cnt_cc[4];

__device__ __forceinline__ float sigmoidf_(float x) { return 1.0f / (1.0f + expf(-x)); }

__device__ __forceinline__ unsigned f2tf(float f) {
    unsigned u;
    asm("cvt.rna.tf32.f32 %0, %1;" : "=r"(u) : "f"(f));
    return u;
}

// quad layouts (validated rounds 7-12)
__device__ __forceinline__ int o_A(int r, int k) {
    return ((r >> 4) * 8 + (k >> 3)) * 128 + ((r & 7) * 4 + (k & 3)) * 4 +
           ((k & 4) >> 1) + ((r & 8) >> 3);
}
__device__ __forceinline__ int o_B(int n, int k) {
    return ((n >> 4) * 8 + (k >> 3)) * 128 + ((n & 7) * 4 + (k & 3)) * 4 +
           ((n >> 3) & 1) * 2 + ((k >> 2) & 1);
}

// vectorized init helpers: one task = 2 rows x 8 cols = 16 elems = 4 contiguous uint4
__device__ __forceinline__ void load8(const float* p, float* v) {
    float4 a = *(const float4*)p, b = *(const float4*)(p + 4);
    v[0] = a.x; v[1] = a.y; v[2] = a.z; v[3] = a.w;
    v[4] = b.x; v[5] = b.y; v[6] = b.z; v[7] = b.w;
}
// A-quad: {(r,k),(r+8,k),(r,k+4),(r+8,k+4)}
__device__ __forceinline__ void storeA16(unsigned* tile, int rblk, int r0, int ko,
                                         const float* lo, const float* hi) {
    unsigned* dst = tile + (size_t)(rblk * 8 + ko) * 128 + r0 * 16;
#pragma unroll
    for (int tg = 0; tg < 4; tg++) {
        uint4 q = {f2tf(lo[tg]), f2tf(hi[tg]), f2tf(lo[tg + 4]), f2tf(hi[tg + 4])};
        *(uint4*)&dst[tg * 4] = q;
    }
}
// B-quad: {(n,k),(n,k+4),(n+8,k),(n+8,k+4)}
__device__ __forceinline__ void storeB16(unsigned* tile, int nblk, int n0, int ko,
                                         const float* lo, const float* hi) {
    unsigned* dst = tile + (size_t)(nblk * 8 + ko) * 128 + n0 * 16;
#pragma unroll
    for (int tg = 0; tg < 4; tg++) {
        uint4 q = {f2tf(lo[tg]), f2tf(lo[tg + 4]), f2tf(hi[tg]), f2tf(hi[tg + 4])};
        *(uint4*)&dst[tg * 4] = q;
    }
}

#define MMA(d, A0, A1, A2, A3, B0, B1)                                          \
    asm volatile("mma.sync.aligned.m16n8k8.row.col.f32.tf32.tf32.f32 "          \
                 "{%0,%1,%2,%3},{%4,%5,%6,%7},{%8,%9},{%0,%1,%2,%3};"           \
                 : "+f"(d[0]), "+f"(d[1]), "+f"(d[2]), "+f"(d[3])               \
                 : "r"(A0), "r"(A1), "r"(A2), "r"(A3), "r"(B0), "r"(B1))

#define CPA(boff, p)                                                            \
    asm volatile("cp.async.cg.shared.global [%0], [%1], 16;"                    \
                 :: "r"(sbase + (unsigned)(boff)), "l"(p) : "memory")
#define CMT   asm volatile("cp.async.commit_group;" ::: "memory")
#define WAIT2 asm volatile("cp.async.wait_group 2;" ::: "memory")

#define LOADQ64(pA, pB, s) do {                                                 \
    unsigned _off = (unsigned)((s) * STW * 4);                                  \
    _Pragma("unroll")                                                           \
    for (int _j = 0; _j < 4; _j++) { int _c = tid + _j * 256;                   \
        CPA(_off + (unsigned)_c * 16u, (pA) + _c * 4);                          \
        CPA(_off + 16384u + (unsigned)_c * 16u, (pB) + _c * 4); }               \
} while (0)
#define LOADQ32(pA, pB, s) do {                                                 \
    unsigned _off = (unsigned)((s) * STW * 4);                                  \
    _Pragma("unroll")                                                           \
    for (int _j = 0; _j < 4; _j++) { int _c = tid + _j * 256;                   \
        CPA(_off + (unsigned)_c * 16u, (pA) + _c * 4); }                        \
    _Pragma("unroll")                                                           \
    for (int _j = 0; _j < 2; _j++) { int _c = tid + _j * 256;                   \
        CPA(_off + 16384u + (unsigned)_c * 16u, (pB) + _c * 4); }               \
} while (0)
#define LOADB64(pB, s) do {                                                     \
    unsigned _off = (unsigned)((s) * STW * 4) + 16384u;                         \
    _Pragma("unroll")                                                           \
    for (int _j = 0; _j < 4; _j++) { int _c = tid + _j * 256;                   \
        CPA(_off + (unsigned)_c * 16u, (pB) + _c * 4); }                        \
} while (0)
#define LOADA64(pA, s) do {                                                     \
    unsigned _off = (unsigned)((s) * STW * 4);                                  \
    _Pragma("unroll")                                                           \
    for (int _j = 0; _j < 4; _j++) { int _c = tid + _j * 256;                   \
        CPA(_off + (unsigned)_c * 16u, (pA) + _c * 4); }                        \
} while (0)
#define LOADB32(pB, s) do {                                                     \
    unsigned _off = (unsigned)((s) * STW * 4) + 16384u;                         \
    _Pragma("unroll")                                                           \
    for (int _j = 0; _j < 2; _j++) { int _c = tid + _j * 256;                   \
        CPA(_off + (unsigned)_c * 16u, (pB) + _c * 4); }                        \
} while (0)
#define LOADA32(pA, s) LOADA64(pA, s)

// ---------------- sync primitives (proven R12) ----------------
__device__ __forceinline__ void gsync(unsigned& sense) {
    __threadfence();
    __syncthreads();
    unsigned target = sense ^ 1u;
    if (threadIdx.x == 0) {
        unsigned old = atomicAdd(&g_cnt, 1u);
        if (old == NB - 1) {
            g_cnt = 0;
            __threadfence();
            atomicExch(&g_sense, target);
        } else {
            while (atomicAdd(&g_sense, 0u) != target) { __nanosleep(128); }
        }
        __threadfence();
    }
    sense = target;
    __syncthreads();
}
__device__ __forceinline__ void wait_ge(unsigned* cnt, unsigned target) {
    if (threadIdx.x == 0) {
        while (atomicAdd(cnt, 0u) < target) { __nanosleep(64); }
    }
    __syncthreads();
}
__device__ __forceinline__ void arrive(unsigned* cnt) {
    __threadfence();               // release: ALL threads' stores -> L2
    __syncthreads();
    if (threadIdx.x == 0) atomicAdd(cnt, 1u);
}
__device__ __forceinline__ float wredsum(float v) {
#pragma unroll
    for (int o = 16; o; o >>= 1) v += __shfl_xor_sync(0xffffffffu, v, o);
    return v;
}

// ---------------- quad MMA bodies (proven) ----------------
__device__ __forceinline__ void mma64q(const unsigned* As, const unsigned* Bs,
                                       float acc[4][4], int wm, int wn, int lane) {
#pragma unroll
    for (int ks = 0; ks < 8; ks++) {
        uint4 a = *(const uint4*)&As[((wm * 8 + ks) * 32 + lane) * 4];
        uint4 b0 = *(const uint4*)&Bs[(((wn * 2 + 0) * 8 + ks) * 32 + lane) * 4];
        uint4 b1 = *(const uint4*)&Bs[(((wn * 2 + 1) * 8 + ks) * 32 + lane) * 4];
        MMA(acc[0], a.x, a.y, a.z, a.w, b0.x, b0.y);
        MMA(acc[1], a.x, a.y, a.z, a.w, b0.z, b0.w);
        MMA(acc[2], a.x, a.y, a.z, a.w, b1.x, b1.y);
        MMA(acc[3], a.x, a.y, a.z, a.w, b1.z, b1.w);
    }
}
__device__ __forceinline__ void mma32q(const unsigned* As, const unsigned* Bs,
                                       float acc[2][4], int wm, int wn, int lane) {
#pragma unroll
    for (int ks = 0; ks < 8; ks++) {
        uint4 a = *(const uint4*)&As[((wm * 8 + ks) * 32 + lane) * 4];
        uint4 b = *(const uint4*)&Bs[((wn * 8 + ks) * 32 + lane) * 4];
        MMA(acc[0], a.x, a.y, a.z, a.w, b.x, b.y);
        MMA(acc[1], a.x, a.y, a.z, a.w, b.z, b.w);
    }
}

__device__ __forceinline__ const unsigned* pcA(int g, int t, int par, int kc) {
    if (kc < 4)  return g_ccq + ((size_t)g * 4 + kc) * 4096;
    if (kc < 8)  return g_mq + (((size_t)g * Tn + t) * 4 + (kc - 4)) * 4096;
    return g_hq + (((size_t)par * 4 + g) * 8 + (kc - 8)) * 4096;
}

__global__ void __launch_bounds__(NT, 1) rits_kernel(
    const float* __restrict__ values, const float* __restrict__ masks,
    const float* __restrict__ deltas,
    const float* __restrict__ W_td_h, const float* __restrict__ b_td_h,
    const float* __restrict__ W_td_x, const float* __restrict__ b_td_x,
    const float* __restrict__ W_hist, const float* __restrict__ b_hist,
    const float* __restrict__ W_feat, const float* __restrict__ b_feat,
    const float* __restrict__ W_comb, const float* __restrict__ b_comb,
    const float* __restrict__ W_ih, const float* __restrict__ W_hh,
    const float* __restrict__ b_ih, const float* __restrict__ b_hh,
    float* __restrict__ out)
{
    extern __shared__ unsigned SHu[];
    float* RED = (float*)(SHu + NSTG * STW);
    unsigned sbase = (unsigned)__cvta_generic_to_shared(SHu);

    const int tid = threadIdx.x;
    const int cta = blockIdx.x;
    const int wid = tid >> 5;
    const int lane = tid & 31;
    const int gid = lane >> 2;
    const int tg = lane & 3;
    const int wm = wid & 3, wn = wid >> 2;

    const int g = cta >> 5;
    const int cg = cta & 31;
    const int b0 = g * 64;
    const int gtid = cta * NT + tid;

    unsigned sense = *((volatile unsigned*)&g_sense);

    // =================== init: state + vectorized tf32 quad conversion ===================
    for (int i = gtid; i < Bn * Hn; i += NTH) g_cst[i] = 0.0f;
    for (int i = gtid; i < 2 * 4 * 8 * 4096; i += NTH) g_hq[i] = 0u;

    // cache diag(W_td_x) + b_td_x in smem (stage area unused yet)
    {
        float* DIAG = (float*)SHu;
        float* BTDX = (float*)SHu + 256;
        if (tid < 256) {
            DIAG[tid] = W_td_x[tid * Fn + tid];
            BTDX[tid] = b_td_x[tid];
        }
        __syncthreads();

        // pass 1: deltas -> g_dtq; gamma_x|mask -> g_gxmq (bt tiles)
        for (int task = gtid; task < 409600; task += NTH) {
            int u = task >> 10;
            int rem = task & 1023;
            int kc = rem >> 8;
            int w = rem & 255;
            int ko = w & 7, rp = w >> 3;
            int rblk = rp >> 3, r0 = rp & 7;
            int bt_lo = u * 64 + rblk * 16 + r0;
            int f0 = kc * 64 + ko * 8;
            float dlo[8], dhi[8], mlo[8], mhi[8], glo[8], ghi[8];
            load8(&deltas[(size_t)bt_lo * Fn + f0], dlo);
            load8(&deltas[(size_t)(bt_lo + 8) * Fn + f0], dhi);
            load8(&masks[(size_t)bt_lo * Fn + f0], mlo);
            load8(&masks[(size_t)(bt_lo + 8) * Fn + f0], mhi);
#pragma unroll
            for (int q = 0; q < 8; q++) {
                float dg = DIAG[f0 + q], bb = BTDX[f0 + q];
                glo[q] = expf(-fmaxf(fmaf(dlo[q], dg, bb), 0.f));
                ghi[q] = expf(-fmaxf(fmaf(dhi[q], dg, bb), 0.f));
            }
            storeA16(g_dtq + ((size_t)u * 4 + kc) * 4096, rblk, r0, ko, dlo, dhi);
            storeA16(g_gxmq + ((size_t)u * 8 + kc) * 4096, rblk, r0, ko, glo, ghi);
            storeA16(g_gxmq + ((size_t)u * 8 + 4 + kc) * 4096, rblk, r0, ko, mlo, mhi);
        }
        // pass 2: masks -> g_mq ((group, t) tiles; rows = batch within group)
        for (int task = gtid; task < 409600; task += NTH) {
            int gt = task >> 10;
            int rem = task & 1023;
            int kc = rem >> 8;
            int w = rem & 255;
            int ko = w & 7, rp = w >> 3;
            int rblk = rp >> 3, r0 = rp & 7;
            int g2 = gt / Tn, t = gt - g2 * Tn;
            int blo = g2 * 64 + rblk * 16 + r0;
            int f0 = kc * 64 + ko * 8;
            float mlo[8], mhi[8];
            load8(&masks[((size_t)blo * Tn + t) * Fn + f0], mlo);
            load8(&masks[((size_t)(blo + 8) * Tn + t) * Fn + f0], mhi);
            storeA16(g_mq + (((size_t)g2 * Tn + t) * 4 + kc) * 4096, rblk, r0, ko, mlo, mhi);
        }
        __syncthreads();
    }

    // weights (B layout, vectorized)
    for (int task = gtid; task < 8192; task += NTH) {       // W_td_h 512x256
        int tile = task >> 8;
        int nt = tile >> 2, kt = tile & 3;
        int w = task & 255, ko = w & 7, np = w >> 3;
        int nblk = np >> 3, n0 = np & 7;
        int n_lo = nt * 64 + nblk * 16 + n0;
        int kg = kt * 64 + ko * 8;
        float lo[8], hi[8];
        load8(&W_td_h[(size_t)n_lo * 256 + kg], lo);
        load8(&W_td_h[(size_t)(n_lo + 8) * 256 + kg], hi);
        storeB16(g_Wtdhq + (size_t)tile * 4096, nblk, n0, ko, lo, hi);
    }
    for (int task = gtid; task < 8192; task += NTH) {       // W_comb 256x512
        int tile = task >> 8;
        int nt = tile >> 3, kt = tile & 7;
        int w = task & 255, ko = w & 7, np = w >> 3;
        int nblk = np >> 3, n0 = np & 7;
        int n_lo = nt * 64 + nblk * 16 + n0;
        int kg = kt * 64 + ko * 8;
        float lo[8], hi[8];
        load8(&W_comb[(size_t)n_lo * 512 + kg], lo);
        load8(&W_comb[(size_t)(n_lo + 8) * 512 + kg], hi);
        storeB16(g_Wcombq + (size_t)tile * 4096, nblk, n0, ko, lo, hi);
    }
    for (int task = gtid; task < 8192; task += NTH) {       // W_hist 256x512, 32-row tiles
        int tile = task >> 7;                               // 64 tiles (8 nt x 8 kt)
        int nt = tile >> 3, kt = tile & 7;
        int w = task & 127, ko = w & 7, np = w >> 3;        // np 0..15
        int nblk = np >> 3, n0 = np & 7;
        int n_lo = nt * 32 + nblk * 16 + n0;
        int kg = kt * 64 + ko * 8;
        float lo[8], hi[8];
        load8(&W_hist[(size_t)n_lo * 512 + kg], lo);
        load8(&W_hist[(size_t)(n_lo + 8) * 512 + kg], hi);
        storeB16(g_Whistq + (size_t)tile * 2048, nblk, n0, ko, lo, hi);
    }
    for (int task = gtid; task < 4096; task += NTH) {       // W_feat 256x256 (diag->0), 32-row tiles
        int tile = task >> 7;                               // 32 tiles (8 nt x 4 kt)
        int nt = tile >> 2, kt = tile & 3;
        int w = task & 127, ko = w & 7, np = w >> 3;
        int nblk = np >> 3, n0 = np & 7;
        int n_lo = nt * 32 + nblk * 16 + n0;
        int kg = kt * 64 + ko * 8;
        float lo[8], hi[8];
        load8(&W_feat[(size_t)n_lo * 256 + kg], lo);
        load8(&W_feat[(size_t)(n_lo + 8) * 256 + kg], hi);
#pragma unroll
        for (int q = 0; q < 8; q++) {
            if (n_lo == kg + q) lo[q] = 0.0f;
            if (n_lo + 8 == kg + q) hi[q] = 0.0f;
        }
        storeB16(g_Wfeatq + (size_t)tile * 2048, nblk, n0, ko, lo, hi);
    }
    for (int task = gtid; task < 131072; task += NTH) {     // gates W 2048x1024
        int tile = task >> 8;                               // 512 tiles (32 nt x 16 kt)
        int nt = tile >> 4, kt = tile & 15;
        int w = task & 255, ko = w & 7, np = w >> 3;
        int nblk = np >> 3, n0 = np & 7;
        int n_lo = nt * 64 + nblk * 16 + n0;                // row = j*4+gate
        int kg = kt * 64 + ko * 8;
        int j = n_lo >> 2, gate = n_lo & 3;
        const float* src_lo;
        const float* src_hi;
        if (kg < 512) {
            src_lo = &W_ih[(size_t)(gate * Hn + j) * 512 + kg];
            src_hi = &W_ih[(size_t)(gate * Hn + j + 2) * 512 + kg];
        } else {
            src_lo = &W_hh[(size_t)(gate * Hn + j) * 512 + (kg - 512)];
            src_hi = &W_hh[(size_t)(gate * Hn + j + 2) * 512 + (kg - 512)];
        }
        float lo[8], hi[8];
        load8(src_lo, lo);
        load8(src_hi, hi);
        storeB16(g_Wgq + (size_t)tile * 4096, nblk, n0, ko, lo, hi);
    }
    for (int i = gtid; i < 4 * Hn; i += NTH) {
        int j = i >> 2, gate = i & 3;
        g_bg[i] = b_ih[gate * Hn + j] + b_hh[gate * Hn + j];
    }
    gsync(sense);

    // =================== precompute gamma_h (3200 tiles) + alpha (1600) ===================
    for (int tt = cta; tt < 4800; tt += NB) {
        float acc[4][4];
#pragma unroll
        for (int nf = 0; nf < 4; nf++)
#pragma unroll
            for (int e = 0; e < 4; e++) acc[nf][e] = 0.0f;

        const bool isg = (tt < 3200);
        const int u = isg ? tt : tt - 3200;
        const int ut = isg ? (u >> 3) : (u >> 2);
        const int nt = isg ? (u & 7) : (u & 3);
        const int m0 = ut * 64, n0 = nt * 64;
        const int NI = isg ? 4 : 8;
        const unsigned* Asrc = isg ? (g_dtq + (size_t)ut * 4 * 4096)
                                   : (g_gxmq + (size_t)ut * 8 * 4096);
        const unsigned* Bsrc = isg ? (g_Wtdhq + (size_t)nt * 4 * 4096)
                                   : (g_Wcombq + (size_t)nt * 8 * 4096);

        LOADQ64(Asrc, Bsrc, 0); CMT;
        LOADQ64(Asrc + 4096, Bsrc + 4096, 1); CMT;
        LOADQ64(Asrc + 8192, Bsrc + 8192, 2); CMT;
        for (int i = 0; i < NI; i++) {
            WAIT2;
            __syncthreads();
            if (i + 3 < NI)
                LOADQ64(Asrc + (size_t)(i + 3) * 4096, Bsrc + (size_t)(i + 3) * 4096, (i + 3) & 3);
            CMT;
            int s = i & 3;
            mma64q(SHu + s * STW, SHu + s * STW + 4096, acc, wm, wn, lane);
        }
        __syncthreads();
#pragma unroll
        for (int nf = 0; nf < 4; nf++) {
#pragma unroll
            for (int ep = 0; ep < 2; ep++) {
                int bt = m0 + wm * 16 + gid + ep * 8;
                int n = n0 + wn * 32 + nf * 8 + 2 * tg;
                float v0 = acc[nf][2 * ep + 0], v1 = acc[nf][2 * ep + 1];
                float2 r;
                if (isg) {
                    r.x = expf(-fmaxf(v0 + b_td_h[n], 0.f));
                    r.y = expf(-fmaxf(v1 + b_td_h[n + 1], 0.f));
                    *(float2*)&g_gamma_h[(size_t)bt * Hn + n] = r;
                } else {
                    r.x = sigmoidf_(v0 + b_comb[n]);
                    r.y = sigmoidf_(v1 + b_comb[n + 1]);
                    *(float2*)&g_alpha[(size_t)bt * Fn + n] = r;
                }
            }
        }
    }
    gsync(sense);

    // =================== sequential recurrence (R12, byte-identical) ===================
    for (int t = 0; t < Tn; t++) {
        const int par = t & 1, nxt = (t + 1) & 1;
        float xh_r[2][4], x_r[2][4], m_r[2][4];

        // ===== P_a =====
        if (cg < 8) {
            const int n0 = cg * 32;
            const unsigned* Ah = g_hq + (((size_t)par * 4 + g) * 8) * 4096;
            const unsigned* Bw = g_Whistq + (size_t)cg * 8 * 2048;
            LOADB32(Bw, 0); LOADB32(Bw + 2048, 1); LOADB32(Bw + 4096, 2); CMT;
#pragma unroll
            for (int nf = 0; nf < 2; nf++) {
#pragma unroll
                for (int hh = 0; hh < 2; hh++) {
                    int b = b0 + wm * 16 + gid + hh * 8;
                    int f0 = n0 + wn * 16 + nf * 8 + 2 * tg;
                    size_t vi = ((size_t)b * Tn + t) * Fn + f0;
                    float2 xv = *(const float2*)&values[vi];
                    float2 mv = *(const float2*)&masks[vi];
                    x_r[nf][hh * 2 + 0] = xv.x; x_r[nf][hh * 2 + 1] = xv.y;
                    m_r[nf][hh * 2 + 0] = mv.x; m_r[nf][hh * 2 + 1] = mv.y;
                }
            }
            wait_ge(&g_cnt_h[g], 32u * (unsigned)t);
            LOADA32(Ah, 0); CMT;
            LOADA32(Ah + 4096, 1); CMT;
            LOADA32(Ah + 8192, 2); CMT;
            float acc[2][4];
#pragma unroll
            for (int nf = 0; nf < 2; nf++)
#pragma unroll
                for (int e = 0; e < 4; e++) acc[nf][e] = 0.0f;
            for (int i = 0; i < 8; i++) {
                WAIT2;
                __syncthreads();
                if (i + 3 < 8)
                    LOADQ32(Ah + (size_t)(i + 3) * 4096, Bw + (size_t)(i + 3) * 2048, (i + 3) & 3);
                CMT;
                int s = i & 3;
                mma32q(SHu + s * STW, SHu + s * STW + 4096, acc, wm, wn, lane);
            }
            float ls = 0.0f;
#pragma unroll
            for (int nf = 0; nf < 2; nf++) {
#pragma unroll
                for (int e = 0; e < 4; e++) {
                    int r = wm * 16 + gid + ((e >> 1) << 3);
                    int f = n0 + wn * 16 + nf * 8 + 2 * tg + (e & 1);
                    float xh = acc[nf][e] + b_hist[f];
                    float x = x_r[nf][e], m = m_r[nf][e];
                    xh_r[nf][e] = xh;
                    ls += fabsf(xh - x) * m;
                    g_xcq[((size_t)g * 4 + (f >> 6)) * 4096 + o_A(r, f & 63)] =
                        f2tf(m * x + (1.0f - m) * xh);
                }
            }
            ls = wredsum(ls);
            if (lane == 0) RED[wid] = ls;
            __syncthreads();
            if (tid == 0) {
                float s = 0.f;
#pragma unroll
                for (int w = 0; w < 8; w++) s += RED[w];
                g_l1[t * 32 + g * 8 + cg] = s;
            }
            arrive(&g_cnt_xh[g]);
        }

        // ===== P_b =====
        if (cg < 8) {
            const int n0 = cg * 32;
            const unsigned* Ax = g_xcq + (size_t)g * 4 * 4096;
            const unsigned* Bf = g_Wfeatq + (size_t)cg * 4 * 2048;
            LOADB32(Bf, 0); LOADB32(Bf + 2048, 1); LOADB32(Bf + 4096, 2); CMT;
            float al_r[2][4];
#pragma unroll
            for (int nf = 0; nf < 2; nf++) {
#pragma unroll
                for (int hh = 0; hh < 2; hh++) {
                    int b = b0 + wm * 16 + gid + hh * 8;
                    int f0 = n0 + wn * 16 + nf * 8 + 2 * tg;
                    size_t vi = ((size_t)b * Tn + t) * Fn + f0;
                    float2 av = *(const float2*)&g_alpha[vi];
                    al_r[nf][hh * 2 + 0] = av.x; al_r[nf][hh * 2 + 1] = av.y;
                }
            }
            wait_ge(&g_cnt_xh[g], 8u * (unsigned)(t + 1));
            LOADA32(Ax, 0); CMT;
            LOADA32(Ax + 4096, 1); CMT;
            LOADA32(Ax + 8192, 2); CMT;
            float acc[2][4];
#pragma unroll
            for (int nf = 0; nf < 2; nf++)
#pragma unroll
                for (int e = 0; e < 4; e++) acc[nf][e] = 0.0f;
            for (int i = 0; i < 4; i++) {
                WAIT2;
                __syncthreads();
                if (i + 3 < 4)
                    LOADQ32(Ax + (size_t)(i + 3) * 4096, Bf + (size_t)(i + 3) * 2048, (i + 3) & 3);
                CMT;
                int s = i & 3;
                mma32q(SHu + s * STW, SHu + s * STW + 4096, acc, wm, wn, lane);
            }
            float l2s = 0.f, l3s = 0.f, dns = 0.f;
#pragma unroll
            for (int nf = 0; nf < 2; nf++) {
#pragma unroll
                for (int e = 0; e < 4; e++) {
                    int r = wm * 16 + gid + ((e >> 1) << 3);
                    int b = b0 + r;
                    int f = n0 + wn * 16 + nf * 8 + 2 * tg + (e & 1);
                    size_t vi = ((size_t)b * Tn + t) * Fn + f;
                    float z = fmaxf(acc[nf][e] + b_feat[f], 0.0f);
                    float al = al_r[nf][e];
                    float x = x_r[nf][e], m = m_r[nf][e];
                    float ch = al * z + (1.0f - al) * xh_r[nf][e];
                    float cc = m * x + (1.0f - m) * ch;
                    out[vi] = cc;
                    g_ccq[((size_t)g * 4 + (f >> 6)) * 4096 + o_A(r, f & 63)] = f2tf(cc);
                    l2s += fabsf(z - x) * m;
                    l3s += fabsf(ch - x) * m;
                    dns += m;
                }
            }
            l2s = wredsum(l2s); l3s = wredsum(l3s); dns = wredsum(dns);
            if (lane == 0) { RED[wid] = l2s; RED[8 + wid] = l3s; RED[16 + wid] = dns; }
            __syncthreads();
            if (tid == 0) {
                float s2 = 0.f, s3 = 0.f, sd = 0.f;
#pragma unroll
                for (int w = 0; w < 8; w++) { s2 += RED[w]; s3 += RED[8 + w]; sd += RED[16 + w]; }
                int slot = t * 32 + g * 8 + cg;
                g_l2[slot] = s2; g_l3[slot] = s3; g_den[slot] = sd;
            }
            arrive(&g_cnt_cc[g]);
        }

        // ===== P_c =====
        {
            const unsigned* Bb = g_Wgq + (size_t)cg * 16 * 4096;
            LOADB64(Bb, 0); LOADB64(Bb + 4096, 1); LOADB64(Bb + 8192, 2); CMT;
            float cst_r[4], gam_r[4];
#pragma unroll
            for (int q = 0; q < 4; q++) {
                int idx = tid + q * 256;
                int r = idx >> 4, jl = idx & 15;
                int b = b0 + r;
                int j = cg * 16 + jl;
                cst_r[q] = g_cst[b * Hn + j];
                gam_r[q] = (t + 1 < Tn)
                         ? g_gamma_h[((size_t)b * Tn + t + 1) * Hn + j] : 0.0f;
            }
            wait_ge(&g_cnt_cc[g], 8u * (unsigned)(t + 1));
            LOADA64(pcA(g, t, par, 0), 0); CMT;
            LOADA64(pcA(g, t, par, 1), 1); CMT;
            LOADA64(pcA(g, t, par, 2), 2); CMT;
            float acc[4][4];
#pragma unroll
            for (int nf = 0; nf < 4; nf++)
#pragma unroll
                for (int e = 0; e < 4; e++) acc[nf][e] = 0.0f;
            for (int i = 0; i < 16; i++) {
                WAIT2;
                __syncthreads();
                if (i + 3 < 16)
                    LOADQ64(pcA(g, t, par, i + 3), Bb + (size_t)(i + 3) * 4096, (i + 3) & 3);
                CMT;
                int s = i & 3;
                mma64q(SHu + s * STW, SHu + s * STW + 4096, acc, wm, wn, lane);
            }
            __syncthreads();
            float* EP = (float*)SHu;
#pragma unroll
            for (int nf = 0; nf < 4; nf++)
#pragma unroll
                for (int e = 0; e < 4; e++) {
                    int r = wm * 16 + gid + ((e >> 1) << 3);
                    int cL = wn * 32 + nf * 8 + 2 * tg + (e & 1);
                    EP[r * EPIT + cL] = acc[nf][e];
                }
            __syncthreads();
#pragma unroll
            for (int q = 0; q < 4; q++) {
                int idx = tid + q * 256;
                int r = idx >> 4, jl = idx & 15;
                int b = b0 + r;
                int j = cg * 16 + jl;
                float ia = EP[r * EPIT + jl * 4 + 0] + g_bg[j * 4 + 0];
                float fa = EP[r * EPIT + jl * 4 + 1] + g_bg[j * 4 + 1];
                float ga = EP[r * EPIT + jl * 4 + 2] + g_bg[j * 4 + 2];
                float oa = EP[r * EPIT + jl * 4 + 3] + g_bg[j * 4 + 3];
                int ci = b * Hn + j;
                float cn = sigmoidf_(fa) * cst_r[q] + sigmoidf_(ia) * tanhf(ga);
                float hn = sigmoidf_(oa) * tanhf(cn);
                g_cst[ci] = cn;
                if (t + 1 < Tn) {
                    g_hq[(((size_t)nxt * 4 + g) * 8 + (j >> 6)) * 4096 + o_A(r, j & 63)] =
                        f2tf(hn * gam_r[q]);
                } else {
                    out[BTF + ci] = hn;
                }
            }
            arrive(&g_cnt_h[g]);
        }
    }

    gsync(sense);

    // =================== final deterministic loss reduction + counter reset ===================
    if (cta == 0) {
        float v = 0.0f;
        if (tid < Tn) {
            float den = 1e-9f, n1 = 0.f, n2 = 0.f, n3 = 0.f;
            for (int c2 = 0; c2 < 32; c2++) {
                den += g_den[tid * 32 + c2];
                n1 += g_l1[tid * 32 + c2];
                n2 += g_l2[tid * 32 + c2];
                n3 += g_l3[tid * 32 + c2];
            }
            v = (n1 + n2 + n3) / den;
        }
        __syncthreads();
        RED[tid] = v;
        __syncthreads();
#pragma unroll
        for (int s = 128; s > 0; s >>= 1) {
            if (tid < s) RED[tid] += RED[tid + s];
            __syncthreads();
        }
        if (tid == 0) {
            out[BTF + Bn * Hn] = RED[0] / (3.0f * Tn);
#pragma unroll
            for (int i = 0; i < 4; i++) { g_cnt_h[i] = 0u; g_cnt_xh[i] = 0u; g_cnt_cc[i] = 0u; }
            __threadfence();
        }
    }
}

extern "C" void kernel_launch(void* const* d_in, const int* in_sizes, int n_in,
                              void* d_out, int out_size) {
    (void)in_sizes; (void)n_in; (void)out_size;
    static int configured = 0;
    if (!configured) {
        cudaFuncSetAttribute(rits_kernel, cudaFuncAttributeMaxDynamicSharedMemorySize,
                             SMEM_BYTES);
        configured = 1;
    }
    rits_kernel<<<NB, NT, SMEM_BYTES>>>(
        (const float*)d_in[0],  (const float*)d_in[1],  (const float*)d_in[2],
        (const float*)d_in[3],  (const float*)d_in[4],  (const float*)d_in[5],
        (const float*)d_in[6],  (const float*)d_in[7],  (const float*)d_in[8],
        (const float*)d_in[9],  (const float*)d_in[10], (const float*)d_in[11],
        (const float*)d_in[12], (const float*)d_in[13], (const float*)d_in[14],
        (const float*)d_in[15], (const float*)d_in[16],
        (float*)d_out);
}

// round 14
// speedup vs baseline: 1.7849x; 1.0041x over previous
#include <cuda_runtime.h>
#include <math.h>

#define Bn 256
#define Tn 100
#define Fn 256
#define Hn 512
#define NB 128
#define NT 256
#define BT (Bn * Tn)
#define STW 12288                  // stage words: A 4096 + B up to 8192
#define NSTG 3
#define EPIT 132
#define SMEM_WORDS (NSTG * STW + 256)
#define SMEM_BYTES (SMEM_WORDS * 4)
#define BTF ((size_t)Bn * Tn * Fn)
#define NTH (NB * NT)

// ---------------- global scratch (allocation-free rule) ----------------
__device__ unsigned g_dtq[(size_t)400 * 4 * 4096];
__device__ unsigned g_gxmq[(size_t)400 * 8 * 4096];
__device__ unsigned g_mq[(size_t)4 * Tn * 4 * 4096];
__device__ unsigned g_Wtdhq[8 * 4 * 4096];
__device__ unsigned g_Wcombq[4 * 8 * 4096];
__device__ unsigned g_Whistq[16 * 8 * 1024];         // 16-row B tiles
__device__ unsigned g_Wfeatq[16 * 4 * 1024];         // 16-row B tiles
__device__ unsigned g_Wgq[32 * 16 * 4096];
__device__ unsigned g_hq[2 * 4 * 8 * 4096];
__device__ unsigned g_xcq[4 * 4 * 4096];
__device__ unsigned g_ccq[4 * 4 * 4096];
__device__ float g_gamma_h[(size_t)BT * Hn];
__device__ float g_alpha[(size_t)BT * Fn];
__device__ float g_bg[4 * Hn];
__device__ float g_cst[Bn * Hn];
__device__ float g_l1[Tn * 64], g_l2[Tn * 64], g_l3[Tn * 64], g_den[Tn * 64];
__device__ unsigned g_cnt, g_sense;
__device__ unsigned g_cnt_h[4], g_cnt_xh[4], g_cnt_cc[4];

__device__ __forceinline__ float sigmoidf_(float x) { return 1.0f / (1.0f + expf(-x)); }

__device__ __forceinline__ unsigned f2tf(float f) {
    unsigned u;
    asm("cvt.rna.tf32.f32 %0, %1;" : "=r"(u) : "f"(f));
    return u;
}

__device__ __forceinline__ int o_A(int r, int k) {
    return ((r >> 4) * 8 + (k >> 3)) * 128 + ((r & 7) * 4 + (k & 3)) * 4 +
           ((k & 4) >> 1) + ((r & 8) >> 3);
}

// vectorized init helpers (R13, proven)
__device__ __forceinline__ void load8(const float* p, float* v) {
    float4 a = *(const float4*)p, b = *(const float4*)(p + 4);
    v[0] = a.x; v[1] = a.y; v[2] = a.z; v[3] = a.w;
    v[4] = b.x; v[5] = b.y; v[6] = b.z; v[7] = b.w;
}
__device__ __forceinline__ void storeA16(unsigned* tile, int rblk, int r0, int ko,
                                         const float* lo, const float* hi) {
    unsigned* dst = tile + (size_t)(rblk * 8 + ko) * 128 + r0 * 16;
#pragma unroll
    for (int tg = 0; tg < 4; tg++) {
        uint4 q = {f2tf(lo[tg]), f2tf(hi[tg]), f2tf(lo[tg + 4]), f2tf(hi[tg + 4])};
        *(uint4*)&dst[tg * 4] = q;
    }
}
__device__ __forceinline__ void storeB16(unsigned* tile, int nblk, int n0, int ko,
                                         const float* lo, const float* hi) {
    unsigned* dst = tile + (size_t)(nblk * 8 + ko) * 128 + n0 * 16;
#pragma unroll
    for (int tg = 0; tg < 4; tg++) {
        uint4 q = {f2tf(lo[tg]), f2tf(lo[tg + 4]), f2tf(hi[tg]), f2tf(hi[tg + 4])};
        *(uint4*)&dst[tg * 4] = q;
    }
}

#define MMA(d, A0, A1, A2, A3, B0, B1)                                          \
    asm volatile("mma.sync.aligned.m16n8k8.row.col.f32.tf32.tf32.f32 "          \
                 "{%0,%1,%2,%3},{%4,%5,%6,%7},{%8,%9},{%0,%1,%2,%3};"           \
                 : "+f"(d[0]), "+f"(d[1]), "+f"(d[2]), "+f"(d[3])               \
                 : "r"(A0), "r"(A1), "r"(A2), "r"(A3), "r"(B0), "r"(B1))

#define CPA(boff, p)                                                            \
    asm volatile("cp.async.cg.shared.global [%0], [%1], 16;"                    \
                 :: "r"(sbase + (unsigned)(boff)), "l"(p) : "memory")
#define CMT   asm volatile("cp.async.commit_group;" ::: "memory")
#define WAIT1 asm volatile("cp.async.wait_group 1;" ::: "memory")

#define LOADA(pA, s) do {                                                       \
    unsigned _off = (unsigned)((s) * STW * 4);                                  \
    _Pragma("unroll")                                                           \
    for (int _j = 0; _j < 4; _j++) { int _c = tid + _j * 256;                   \
        CPA(_off + (unsigned)_c * 16u, (pA) + _c * 4); }                        \
} while (0)
#define LOADB4K(pB, s) do {                                                     \
    unsigned _off = (unsigned)((s) * STW * 4) + 16384u;                         \
    _Pragma("unroll")                                                           \
    for (int _j = 0; _j < 4; _j++) { int _c = tid + _j * 256;                   \
        CPA(_off + (unsigned)_c * 16u, (pB) + _c * 4); }                        \
} while (0)
#define LOADB1K(pB, s) do {                                                     \
    unsigned _off = (unsigned)((s) * STW * 4) + 16384u;                         \
    { int _c = tid; CPA(_off + (unsigned)_c * 16u, (pB) + _c * 4); }            \
} while (0)
#define LOADBPC(pB0, pB1, s) do {                                               \
    unsigned _off = (unsigned)((s) * STW * 4) + 16384u;                         \
    _Pragma("unroll")                                                           \
    for (int _j = 0; _j < 4; _j++) { int _c = tid + _j * 256;                   \
        CPA(_off + (unsigned)_c * 16u, (pB0) + _c * 4);                         \
        CPA(_off + 16384u + (unsigned)_c * 16u, (pB1) + _c * 4); }              \
} while (0)

// ---------------- sync primitives (proven R12/R13) ----------------
__device__ __forceinline__ void gsync(unsigned& sense) {
    __threadfence();
    __syncthreads();
    unsigned target = sense ^ 1u;
    if (threadIdx.x == 0) {
        unsigned old = atomicAdd(&g_cnt, 1u);
        if (old == NB - 1) {
            g_cnt = 0;
            __threadfence();
            atomicExch(&g_sense, target);
        } else {
            while (atomicAdd(&g_sense, 0u) != target) { __nanosleep(128); }
        }
        __threadfence();
    }
    sense = target;
    __syncthreads();
}
__device__ __forceinline__ void wait_ge(unsigned* cnt, unsigned target) {
    if (threadIdx.x == 0) {
        while (atomicAdd(cnt, 0u) < target) { __nanosleep(64); }
    }
    __syncthreads();
}
__device__ __forceinline__ void arrive(unsigned* cnt) {
    __threadfence();
    __syncthreads();
    if (threadIdx.x == 0) atomicAdd(cnt, 1u);
}
__device__ __forceinline__ float wredsum(float v) {
#pragma unroll
    for (int o = 16; o; o >>= 1) v += __shfl_xor_sync(0xffffffffu, v, o);
    return v;
}

// ---------------- MMA bodies ----------------
// precompute 64x64: warps 4(M)x2(N), warp tile 16x32
__device__ __forceinline__ void mma64q(const unsigned* As, const unsigned* Bs,
                                       float acc[4][4], int wm, int wn, int lane) {
#pragma unroll
    for (int ks = 0; ks < 8; ks++) {
        uint4 a = *(const uint4*)&As[((wm * 8 + ks) * 32 + lane) * 4];
        uint4 b0 = *(const uint4*)&Bs[(((wn * 2 + 0) * 8 + ks) * 32 + lane) * 4];
        uint4 b1 = *(const uint4*)&Bs[(((wn * 2 + 1) * 8 + ks) * 32 + lane) * 4];
        MMA(acc[0], a.x, a.y, a.z, a.w, b0.x, b0.y);
        MMA(acc[1], a.x, a.y, a.z, a.w, b0.z, b0.w);
        MMA(acc[2], a.x, a.y, a.z, a.w, b1.x, b1.y);
        MMA(acc[3], a.x, a.y, a.z, a.w, b1.z, b1.w);
    }
}
// P_a/P_b 64x16: warps 4(M)x2(N), warp tile 16x8
__device__ __forceinline__ void mma16q(const unsigned* As, const unsigned* Bs,
                                       float acc[4], int wm, int wn, int lane) {
#pragma unroll
    for (int ks = 0; ks < 8; ks++) {
        uint4 a = *(const uint4*)&As[((wm * 8 + ks) * 32 + lane) * 4];
        uint4 b = *(const uint4*)&Bs[(ks * 32 + lane) * 4];
        unsigned b0 = wn ? b.z : b.x;
        unsigned b1 = wn ? b.w : b.y;
        MMA(acc, a.x, a.y, a.z, a.w, b0, b1);
    }
}
// P_c 64x128: warps 4(M)x2(N64), warp tile 16x64
__device__ __forceinline__ void mma128q(const unsigned* As, const unsigned* Bs,
                                        float acc[8][4], int wm, int wn, int lane) {
    const unsigned* Bw = Bs + wn * 4096;
#pragma unroll
    for (int ks = 0; ks < 8; ks++) {
        uint4 a = *(const uint4*)&As[((wm * 8 + ks) * 32 + lane) * 4];
#pragma unroll
        for (int nb = 0; nb < 4; nb++) {
            uint4 b = *(const uint4*)&Bw[((nb * 8 + ks) * 32 + lane) * 4];
            MMA(acc[nb * 2 + 0], a.x, a.y, a.z, a.w, b.x, b.y);
            MMA(acc[nb * 2 + 1], a.x, a.y, a.z, a.w, b.z, b.w);
        }
    }
}

__device__ __forceinline__ const unsigned* pcA(int g, int t, int par, int kc) {
    if (kc < 4)  return g_ccq + ((size_t)g * 4 + kc) * 4096;
    if (kc < 8)  return g_mq + (((size_t)g * Tn + t) * 4 + (kc - 4)) * 4096;
    return g_hq + (((size_t)par * 4 + g) * 8 + (kc - 8)) * 4096;
}
// P_c K order: h chunks first (ready), then masks (input), cc last
__device__ __forceinline__ int pc_ord(int i) {
    return (i < 8) ? (8 + i) : ((i < 12) ? (i - 4) : (i - 12));
}

__global__ void __launch_bounds__(NT, 1) rits_kernel(
    const float* __restrict__ values, const float* __restrict__ masks,
    const float* __restrict__ deltas,
    const float* __restrict__ W_td_h, const float* __restrict__ b_td_h,
    const float* __restrict__ W_td_x, const float* __restrict__ b_td_x,
    const float* __restrict__ W_hist, const float* __restrict__ b_hist,
    const float* __restrict__ W_feat, const float* __restrict__ b_feat,
    const float* __restrict__ W_comb, const float* __restrict__ b_comb,
    const float* __restrict__ W_ih, const float* __restrict__ W_hh,
    const float* __restrict__ b_ih, const float* __restrict__ b_hh,
    float* __restrict__ out)
{
    extern __shared__ unsigned SHu[];
    float* RED = (float*)(SHu + NSTG * STW);
    unsigned sbase = (unsigned)__cvta_generic_to_shared(SHu);

    const int tid = threadIdx.x;
    const int cta = blockIdx.x;
    const int wid = tid >> 5;
    const int lane = tid & 31;
    const int gid = lane >> 2;
    const int tg = lane & 3;
    const int wm = wid & 3, wn = wid >> 2;

    const int g = cta >> 5;
    const int cg = cta & 31;
    const int b0 = g * 64;
    const int gtid = cta * NT + tid;

    unsigned sense = *((volatile unsigned*)&g_sense);

    // =================== init (R13 vectorized) ===================
    for (int i = gtid; i < Bn * Hn; i += NTH) g_cst[i] = 0.0f;
    for (int i = gtid; i < 2 * 4 * 8 * 4096; i += NTH) g_hq[i] = 0u;

    {
        float* DIAG = (float*)SHu;
        float* BTDX = (float*)SHu + 256;
        if (tid < 256) {
            DIAG[tid] = W_td_x[tid * Fn + tid];
            BTDX[tid] = b_td_x[tid];
        }
        __syncthreads();
        for (int task = gtid; task < 409600; task += NTH) {
            int u = task >> 10;
            int rem = task & 1023;
            int kc = rem >> 8;
            int w = rem & 255;
            int ko = w & 7, rp = w >> 3;
            int rblk = rp >> 3, r0 = rp & 7;
            int bt_lo = u * 64 + rblk * 16 + r0;
            int f0 = kc * 64 + ko * 8;
            float dlo[8], dhi[8], mlo[8], mhi[8], glo[8], ghi[8];
            load8(&deltas[(size_t)bt_lo * Fn + f0], dlo);
            load8(&deltas[(size_t)(bt_lo + 8) * Fn + f0], dhi);
            load8(&masks[(size_t)bt_lo * Fn + f0], mlo);
            load8(&masks[(size_t)(bt_lo + 8) * Fn + f0], mhi);
#pragma unroll
            for (int q = 0; q < 8; q++) {
                float dg = DIAG[f0 + q], bb = BTDX[f0 + q];
                glo[q] = expf(-fmaxf(fmaf(dlo[q], dg, bb), 0.f));
                ghi[q] = expf(-fmaxf(fmaf(dhi[q], dg, bb), 0.f));
            }
            storeA16(g_dtq + ((size_t)u * 4 + kc) * 4096, rblk, r0, ko, dlo, dhi);
            storeA16(g_gxmq + ((size_t)u * 8 + kc) * 4096, rblk, r0, ko, glo, ghi);
            storeA16(g_gxmq + ((size_t)u * 8 + 4 + kc) * 4096, rblk, r0, ko, mlo, mhi);
        }
        for (int task = gtid; task < 409600; task += NTH) {
            int gt = task >> 10;
            int rem = task & 1023;
            int kc = rem >> 8;
            int w = rem & 255;
            int ko = w & 7, rp = w >> 3;
            int rblk = rp >> 3, r0 = rp & 7;
            int g2 = gt / Tn, t = gt - g2 * Tn;
            int blo = g2 * 64 + rblk * 16 + r0;
            int f0 = kc * 64 + ko * 8;
            float mlo[8], mhi[8];
            load8(&masks[((size_t)blo * Tn + t) * Fn + f0], mlo);
            load8(&masks[((size_t)(blo + 8) * Tn + t) * Fn + f0], mhi);
            storeA16(g_mq + (((size_t)g2 * Tn + t) * 4 + kc) * 4096, rblk, r0, ko, mlo, mhi);
        }
        __syncthreads();
    }

    for (int task = gtid; task < 8192; task += NTH) {       // W_td_h 512x256 (64-row tiles)
        int tile = task >> 8;
        int w = task & 255, ko = w & 7, np = w >> 3;
        int nblk = np >> 3, n0 = np & 7;
        int nt = tile >> 2, kt = tile & 3;
        int n_lo = nt * 64 + nblk * 16 + n0;
        int kg = kt * 64 + ko * 8;
        float lo[8], hi[8];
        load8(&W_td_h[(size_t)n_lo * 256 + kg], lo);
        load8(&W_td_h[(size_t)(n_lo + 8) * 256 + kg], hi);
        storeB16(g_Wtdhq + (size_t)tile * 4096, nblk, n0, ko, lo, hi);
    }
    for (int task = gtid; task < 8192; task += NTH) {       // W_comb 256x512 (64-row tiles)
        int tile = task >> 8;
        int w = task & 255, ko = w & 7, np = w >> 3;
        int nblk = np >> 3, n0 = np & 7;
        int nt = tile >> 3, kt = tile & 7;
        int n_lo = nt * 64 + nblk * 16 + n0;
        int kg = kt * 64 + ko * 8;
        float lo[8], hi[8];
        load8(&W_comb[(size_t)n_lo * 512 + kg], lo);
        load8(&W_comb[(size_t)(n_lo + 8) * 512 + kg], hi);
        storeB16(g_Wcombq + (size_t)tile * 4096, nblk, n0, ko, lo, hi);
    }
    for (int task = gtid; task < 8192; task += NTH) {       // W_hist 256x512 -> 16-row tiles
        int tile = task >> 6;                               // 128 tiles (16 nt x 8 kt)
        int w = task & 63, ko = w & 7, np = w >> 3;         // np 0..7
        int nt = tile >> 3, kt = tile & 7;
        int n_lo = nt * 16 + np;
        int kg = kt * 64 + ko * 8;
        float lo[8], hi[8];
        load8(&W_hist[(size_t)n_lo * 512 + kg], lo);
        load8(&W_hist[(size_t)(n_lo + 8) * 512 + kg], hi);
        storeB16(g_Whistq + (size_t)tile * 1024, 0, np, ko, lo, hi);
    }
    for (int task = gtid; task < 4096; task += NTH) {       // W_feat 256x256 -> 16-row tiles
        int tile = task >> 6;                               // 64 tiles (16 nt x 4 kt)
        int w = task & 63, ko = w & 7, np = w >> 3;
        int nt = tile >> 2, kt = tile & 3;
        int n_lo = nt * 16 + np;
        int kg = kt * 64 + ko * 8;
        float lo[8], hi[8];
        load8(&W_feat[(size_t)n_lo * 256 + kg], lo);
        load8(&W_feat[(size_t)(n_lo + 8) * 256 + kg], hi);
#pragma unroll
        for (int q = 0; q < 8; q++) {
            if (n_lo == kg + q) lo[q] = 0.0f;
            if (n_lo + 8 == kg + q) hi[q] = 0.0f;
        }
        storeB16(g_Wfeatq + (size_t)tile * 1024, 0, np, ko, lo, hi);
    }
    for (int task = gtid; task < 131072; task += NTH) {     // gates W 2048x1024 (64-row tiles)
        int tile = task >> 8;
        int w = task & 255, ko = w & 7, np = w >> 3;
        int nblk = np >> 3, n0 = np & 7;
        int nt = tile >> 4, kt = tile & 15;
        int n_lo = nt * 64 + nblk * 16 + n0;
        int kg = kt * 64 + ko * 8;
        int j = n_lo >> 2, gate = n_lo & 3;
        const float* src_lo;
        const float* src_hi;
        if (kg < 512) {
            src_lo = &W_ih[(size_t)(gate * Hn + j) * 512 + kg];
            src_hi = &W_ih[(size_t)(gate * Hn + j + 2) * 512 + kg];
        } else {
            src_lo = &W_hh[(size_t)(gate * Hn + j) * 512 + (kg - 512)];
            src_hi = &W_hh[(size_t)(gate * Hn + j + 2) * 512 + (kg - 512)];
        }
        float lo[8], hi[8];
        load8(src_lo, lo);
        load8(src_hi, hi);
        storeB16(g_Wgq + (size_t)tile * 4096, nblk, n0, ko, lo, hi);
    }
    for (int i = gtid; i < 4 * Hn; i += NTH) {
        int j = i >> 2, gate = i & 3;
        g_bg[i] = b_ih[gate * Hn + j] + b_hh[gate * Hn + j];
    }
    gsync(sense);

    // =================== precompute gamma_h + alpha (3-stage pipeline) ===================
    for (int tt = cta; tt < 4800; tt += NB) {
        float acc[4][4];
#pragma unroll
        for (int nf = 0; nf < 4; nf++)
#pragma unroll
            for (int e = 0; e < 4; e++) acc[nf][e] = 0.0f;

        const bool isg = (tt < 3200);
        const int u = isg ? tt : tt - 3200;
        const int ut = isg ? (u >> 3) : (u >> 2);
        const int nt = isg ? (u & 7) : (u & 3);
        const int m0 = ut * 64, n0 = nt * 64;
        const int NI = isg ? 4 : 8;
        const unsigned* Asrc = isg ? (g_dtq + (size_t)ut * 4 * 4096)
                                   : (g_gxmq + (size_t)ut * 8 * 4096);
        const unsigned* Bsrc = isg ? (g_Wtdhq + (size_t)nt * 4 * 4096)
                                   : (g_Wcombq + (size_t)nt * 8 * 4096);

        LOADA(Asrc, 0); LOADB4K(Bsrc, 0); CMT;
        LOADA(Asrc + 4096, 1); LOADB4K(Bsrc + 4096, 1); CMT;
        for (int i = 0; i < NI; i++) {
            WAIT1;
            __syncthreads();
            if (i + 2 < NI) {
                LOADA(Asrc + (size_t)(i + 2) * 4096, (i + 2) % 3);
                LOADB4K(Bsrc + (size_t)(i + 2) * 4096, (i + 2) % 3);
            }
            CMT;
            int s = i % 3;
            mma64q(SHu + s * STW, SHu + s * STW + 4096, acc, wm, wn, lane);
        }
        __syncthreads();
#pragma unroll
        for (int nf = 0; nf < 4; nf++) {
#pragma unroll
            for (int ep = 0; ep < 2; ep++) {
                int bt = m0 + wm * 16 + gid + ep * 8;
                int n = n0 + wn * 32 + nf * 8 + 2 * tg;
                float v0 = acc[nf][2 * ep + 0], v1 = acc[nf][2 * ep + 1];
                float2 r;
                if (isg) {
                    r.x = expf(-fmaxf(v0 + b_td_h[n], 0.f));
                    r.y = expf(-fmaxf(v1 + b_td_h[n + 1], 0.f));
                    *(float2*)&g_gamma_h[(size_t)bt * Hn + n] = r;
                } else {
                    r.x = sigmoidf_(v0 + b_comb[n]);
                    r.y = sigmoidf_(v1 + b_comb[n + 1]);
                    *(float2*)&g_alpha[(size_t)bt * Fn + n] = r;
                }
            }
        }
    }
    gsync(sense);

    // =================== recurrence: team-split dataflow ===================
    for (int t = 0; t < Tn; t++) {
        const int par = t & 1, nxt = (t + 1) & 1;

        if (cg < 16) {
            // ===== team A: P_a then P_b (tile 64x16 each) =====
            const int n0 = cg * 16;
            float xh_r[4], x_r[4], m_r[4];
            {   // P_a: K=512, 8 iters
                const unsigned* Ah = g_hq + (((size_t)par * 4 + g) * 8) * 4096;
                const unsigned* Bw = g_Whistq + (size_t)cg * 8 * 1024;
                LOADB1K(Bw, 0); LOADB1K(Bw + 1024, 1); CMT;
#pragma unroll
                for (int hh = 0; hh < 2; hh++) {
                    int b = b0 + wm * 16 + gid + hh * 8;
                    int f0 = n0 + wn * 8 + 2 * tg;
                    size_t vi = ((size_t)b * Tn + t) * Fn + f0;
                    float2 xv = *(const float2*)&values[vi];
                    float2 mv = *(const float2*)&masks[vi];
                    x_r[hh * 2 + 0] = xv.x; x_r[hh * 2 + 1] = xv.y;
                    m_r[hh * 2 + 0] = mv.x; m_r[hh * 2 + 1] = mv.y;
                }
                wait_ge(&g_cnt_h[g], 16u * (unsigned)t);
                LOADA(Ah, 0); CMT;
                LOADA(Ah + 4096, 1); CMT;
                float acc[4] = {0.f, 0.f, 0.f, 0.f};
                for (int i = 0; i < 8; i++) {
                    WAIT1;
                    __syncthreads();
                    if (i + 2 < 8) {
                        LOADA(Ah + (size_t)(i + 2) * 4096, (i + 2) % 3);
                        LOADB1K(Bw + (size_t)(i + 2) * 1024, (i + 2) % 3);
                    }
                    CMT;
                    int s = i % 3;
                    mma16q(SHu + s * STW, SHu + s * STW + 4096, acc, wm, wn, lane);
                }
                float ls = 0.0f;
#pragma unroll
                for (int e = 0; e < 4; e++) {
                    int r = wm * 16 + gid + ((e >> 1) << 3);
                    int f = n0 + wn * 8 + 2 * tg + (e & 1);
                    float xh = acc[e] + b_hist[f];
                    float x = x_r[e], m = m_r[e];
                    xh_r[e] = xh;
                    ls += fabsf(xh - x) * m;
                    g_xcq[((size_t)g * 4 + (f >> 6)) * 4096 + o_A(r, f & 63)] =
                        f2tf(m * x + (1.0f - m) * xh);
                }
                ls = wredsum(ls);
                if (lane == 0) RED[wid] = ls;
                __syncthreads();
                if (tid == 0) {
                    float s = 0.f;
#pragma unroll
                    for (int w = 0; w < 8; w++) s += RED[w];
                    g_l1[t * 64 + g * 16 + cg] = s;
                }
                arrive(&g_cnt_xh[g]);
            }
            {   // P_b: K=256, 4 iters
                const unsigned* Ax = g_xcq + (size_t)g * 4 * 4096;
                const unsigned* Bf = g_Wfeatq + (size_t)cg * 4 * 1024;
                LOADB1K(Bf, 0); LOADB1K(Bf + 1024, 1); CMT;
                float al_r[4];
#pragma unroll
                for (int hh = 0; hh < 2; hh++) {
                    int b = b0 + wm * 16 + gid + hh * 8;
                    int f0 = n0 + wn * 8 + 2 * tg;
                    size_t vi = ((size_t)b * Tn + t) * Fn + f0;
                    float2 av = *(const float2*)&g_alpha[vi];
                    al_r[hh * 2 + 0] = av.x; al_r[hh * 2 + 1] = av.y;
                }
                wait_ge(&g_cnt_xh[g], 16u * (unsigned)(t + 1));
                LOADA(Ax, 0); CMT;
                LOADA(Ax + 4096, 1); CMT;
                float acc[4] = {0.f, 0.f, 0.f, 0.f};
                for (int i = 0; i < 4; i++) {
                    WAIT1;
                    __syncthreads();
                    if (i + 2 < 4) {
                        LOADA(Ax + (size_t)(i + 2) * 4096, (i + 2) % 3);
                        LOADB1K(Bf + (size_t)(i + 2) * 1024, (i + 2) % 3);
                    }
                    CMT;
                    int s = i % 3;
                    mma16q(SHu + s * STW, SHu + s * STW + 4096, acc, wm, wn, lane);
                }
                float l2s = 0.f, l3s = 0.f, dns = 0.f;
#pragma unroll
                for (int e = 0; e < 4; e++) {
                    int r = wm * 16 + gid + ((e >> 1) << 3);
                    int b = b0 + r;
                    int f = n0 + wn * 8 + 2 * tg + (e & 1);
                    size_t vi = ((size_t)b * Tn + t) * Fn + f;
                    float z = fmaxf(acc[e] + b_feat[f], 0.0f);
                    float al = al_r[e];
                    float x = x_r[e], m = m_r[e];
                    float ch = al * z + (1.0f - al) * xh_r[e];
                    float cc = m * x + (1.0f - m) * ch;
                    out[vi] = cc;
                    g_ccq[((size_t)g * 4 + (f >> 6)) * 4096 + o_A(r, f & 63)] = f2tf(cc);
                    l2s += fabsf(z - x) * m;
                    l3s += fabsf(ch - x) * m;
                    dns += m;
                }
                l2s = wredsum(l2s); l3s = wredsum(l3s); dns = wredsum(dns);
                if (lane == 0) { RED[wid] = l2s; RED[8 + wid] = l3s; RED[16 + wid] = dns; }
                __syncthreads();
                if (tid == 0) {
                    float s2 = 0.f, s3 = 0.f, sd = 0.f;
#pragma unroll
                    for (int w = 0; w < 8; w++) { s2 += RED[w]; s3 += RED[8 + w]; sd += RED[16 + w]; }
                    int slot = t * 64 + g * 16 + cg;
                    g_l2[slot] = s2; g_l3[slot] = s3; g_den[slot] = sd;
                }
                arrive(&g_cnt_cc[g]);
            }
        } else {
            // ===== team B: P_c (tile 64x128, K=1024, h-first order) + LSTM =====
            const int cg16 = cg - 16;
            const int j0 = cg16 * 32;
            const unsigned* Bt0 = g_Wgq + ((size_t)(cg16 * 2 + 0) * 16) * 4096;
            const unsigned* Bt1 = g_Wgq + ((size_t)(cg16 * 2 + 1) * 16) * 4096;
            LOADBPC(Bt0 + (size_t)pc_ord(0) * 4096, Bt1 + (size_t)pc_ord(0) * 4096, 0);
            LOADBPC(Bt0 + (size_t)pc_ord(1) * 4096, Bt1 + (size_t)pc_ord(1) * 4096, 1);
            CMT;
            float cst_r[8], gam_r[8];
#pragma unroll
            for (int q = 0; q < 8; q++) {
                int idx = tid + q * 256;
                int r = idx >> 5, jl = idx & 31;
                int b = b0 + r;
                int j = j0 + jl;
                cst_r[q] = g_cst[b * Hn + j];
                gam_r[q] = (t + 1 < Tn)
                         ? g_gamma_h[((size_t)b * Tn + t + 1) * Hn + j] : 0.0f;
            }
            wait_ge(&g_cnt_h[g], 16u * (unsigned)t);
            LOADA(pcA(g, t, par, pc_ord(0)), 0); CMT;
            LOADA(pcA(g, t, par, pc_ord(1)), 1); CMT;
            float acc[8][4];
#pragma unroll
            for (int nf = 0; nf < 8; nf++)
#pragma unroll
                for (int e = 0; e < 4; e++) acc[nf][e] = 0.0f;
            for (int i = 0; i < 16; i++) {
                WAIT1;
                __syncthreads();
                if (i == 10) wait_ge(&g_cnt_cc[g], 16u * (unsigned)(t + 1));
                if (i + 2 < 16) {
                    int kc = pc_ord(i + 2);
                    LOADA(pcA(g, t, par, kc), (i + 2) % 3);
                    LOADBPC(Bt0 + (size_t)kc * 4096, Bt1 + (size_t)kc * 4096, (i + 2) % 3);
                }
                CMT;
                int s = i % 3;
                mma128q(SHu + s * STW, SHu + s * STW + 4096, acc, wm, wn, lane);
            }
            __syncthreads();
            float* EP = (float*)SHu;
#pragma unroll
            for (int nf = 0; nf < 8; nf++)
#pragma unroll
                for (int e = 0; e < 4; e++) {
                    int r = wm * 16 + gid + ((e >> 1) << 3);
                    int v = wn * 64 + nf * 8 + 2 * tg + (e & 1);
                    EP[r * EPIT + v] = acc[nf][e];
                }
            __syncthreads();
#pragma unroll
            for (int q = 0; q < 8; q++) {
                int idx = tid + q * 256;
                int r = idx >> 5, jl = idx & 31;
                int b = b0 + r;
                int j = j0 + jl;
                float ia = EP[r * EPIT + jl * 4 + 0] + g_bg[j * 4 + 0];
                float fa = EP[r * EPIT + jl * 4 + 1] + g_bg[j * 4 + 1];
                float ga = EP[r * EPIT + jl * 4 + 2] + g_bg[j * 4 + 2];
                float oa = EP[r * EPIT + jl * 4 + 3] + g_bg[j * 4 + 3];
                int ci = b * Hn + j;
                float cn = sigmoidf_(fa) * cst_r[q] + sigmoidf_(ia) * tanhf(ga);
                float hn = sigmoidf_(oa) * tanhf(cn);
                g_cst[ci] = cn;
                if (t + 1 < Tn) {
                    g_hq[(((size_t)nxt * 4 + g) * 8 + (j >> 6)) * 4096 + o_A(r, j & 63)] =
                        f2tf(hn * gam_r[q]);
                } else {
                    out[BTF + ci] = hn;
                }
            }
            arrive(&g_cnt_h[g]);
        }
    }

    gsync(sense);

    // =================== final loss reduction + counter reset ===================
    if (cta == 0) {
        float v = 0.0f;
        if (tid < Tn) {
            float den = 1e-9f, n1 = 0.f, n2 = 0.f, n3 = 0.f;
            for (int c2 = 0; c2 < 64; c2++) {
                den += g_den[tid * 64 + c2];
                n1 += g_l1[tid * 64 + c2];
                n2 += g_l2[tid * 64 + c2];
                n3 += g_l3[tid * 64 + c2];
            }
            v = (n1 + n2 + n3) / den;
        }
        __syncthreads();
        RED[tid] = v;
        __syncthreads();
#pragma unroll
        for (int s = 128; s > 0; s >>= 1) {
            if (tid < s) RED[tid] += RED[tid + s];
            __syncthreads();
        }
        if (tid == 0) {
            out[BTF + Bn * Hn] = RED[0] / (3.0f * Tn);
#pragma unroll
            for (int i = 0; i < 4; i++) { g_cnt_h[i] = 0u; g_cnt_xh[i] = 0u; g_cnt_cc[i] = 0u; }
            __threadfence();
        }
    }
}

extern "C" void kernel_launch(void* const* d_in, const int* in_sizes, int n_in,
                              void* d_out, int out_size) {
    (void)in_sizes; (void)n_in; (void)out_size;
    static int configured = 0;
    if (!configured) {
        cudaFuncSetAttribute(rits_kernel, cudaFuncAttributeMaxDynamicSharedMemorySize,
                             SMEM_BYTES);
        configured = 1;
    }
    rits_kernel<<<NB, NT, SMEM_BYTES>>>(
        (const float*)d_in[0],  (const float*)d_in[1],  (const float*)d_in[2],
        (const float*)d_in[3],  (const float*)d_in[4],  (const float*)d_in[5],
        (const float*)d_in[6],  (const float*)d_in[7],  (const float*)d_in[8],
        (const float*)d_in[9],  (const float*)d_in[10], (const float*)d_in[11],
        (const float*)d_in[12], (const float*)d_in[13], (const float*)d_in[14],
        (const float*)d_in[15], (const float*)d_in[16],
        (float*)d_out);
}

// round 15
// speedup vs baseline: 1.7883x; 1.0019x over previous
#include <cuda_runtime.h>
#include <math.h>

#define Bn 256
#define Tn 100
#define Fn 256
#define Hn 512
#define NB 128
#define NT 256
#define BT (Bn * Tn)
#define STW 12288                  // team-B stage words: A 4096 + B 8192
#define NSTG 3
#define SWA 5120                   // team-A stage words: A 4096 + B 1024
#define EPIT 132
#define SMEM_WORDS (NSTG * STW + 256)
#define SMEM_BYTES (SMEM_WORDS * 4)
#define BTF ((size_t)Bn * Tn * Fn)
#define NTH (NB * NT)

// ---------------- global scratch (allocation-free rule) ----------------
__device__ unsigned g_dtq[(size_t)400 * 4 * 4096];
__device__ unsigned g_gxmq[(size_t)400 * 8 * 4096];
__device__ unsigned g_mq[(size_t)4 * Tn * 4 * 4096];
__device__ unsigned g_Wtdhq[8 * 4 * 4096];
__device__ unsigned g_Wcombq[4 * 8 * 4096];
__device__ unsigned g_Whistq[16 * 8 * 1024];
__device__ unsigned g_Wfeatq[16 * 4 * 1024];
__device__ unsigned g_Wgq[32 * 16 * 4096];
__device__ unsigned g_hq[2 * 4 * 8 * 4096];
__device__ unsigned g_xcq[4 * 4 * 4096];
__device__ unsigned g_ccq[4 * 4 * 4096];
__device__ float g_gamma_h[(size_t)BT * Hn];
__device__ float g_alpha[(size_t)BT * Fn];
__device__ float g_bg[4 * Hn];
__device__ float g_cst[Bn * Hn];
__device__ float g_l1[Tn * 64], g_l2[Tn * 64], g_l3[Tn * 64], g_den[Tn * 64];
__device__ unsigned g_cnt, g_sense;
__device__ unsigned g_cnt_h[4], g_cnt_xh[4], g_cnt_cc[4];

__device__ __forceinline__ float sigmoidf_(float x) { return 1.0f / (1.0f + expf(-x)); }

__device__ __forceinline__ unsigned f2tf(float f) {
    unsigned u;
    asm("cvt.rna.tf32.f32 %0, %1;" : "=r"(u) : "f"(f));
    return u;
}

__device__ __forceinline__ int o_A(int r, int k) {
    return ((r >> 4) * 8 + (k >> 3)) * 128 + ((r & 7) * 4 + (k & 3)) * 4 +
           ((k & 4) >> 1) + ((r & 8) >> 3);
}

// vectorized init helpers (R13, proven)
__device__ __forceinline__ void load8(const float* p, float* v) {
    float4 a = *(const float4*)p, b = *(const float4*)(p + 4);
    v[0] = a.x; v[1] = a.y; v[2] = a.z; v[3] = a.w;
    v[4] = b.x; v[5] = b.y; v[6] = b.z; v[7] = b.w;
}
__device__ __forceinline__ void storeA16(unsigned* tile, int rblk, int r0, int ko,
                                         const float* lo, const float* hi) {
    unsigned* dst = tile + (size_t)(rblk * 8 + ko) * 128 + r0 * 16;
#pragma unroll
    for (int tg = 0; tg < 4; tg++) {
        uint4 q = {f2tf(lo[tg]), f2tf(hi[tg]), f2tf(lo[tg + 4]), f2tf(hi[tg + 4])};
        *(uint4*)&dst[tg * 4] = q;
    }
}
__device__ __forceinline__ void storeB16(unsigned* tile, int nblk, int n0, int ko,
                                         const float* lo, const float* hi) {
    unsigned* dst = tile + (size_t)(nblk * 8 + ko) * 128 + n0 * 16;
#pragma unroll
    for (int tg = 0; tg < 4; tg++) {
        uint4 q = {f2tf(lo[tg]), f2tf(lo[tg + 4]), f2tf(hi[tg]), f2tf(hi[tg + 4])};
        *(uint4*)&dst[tg * 4] = q;
    }
}

#define MMA(d, A0, A1, A2, A3, B0, B1)                                          \
    asm volatile("mma.sync.aligned.m16n8k8.row.col.f32.tf32.tf32.f32 "          \
                 "{%0,%1,%2,%3},{%4,%5,%6,%7},{%8,%9},{%0,%1,%2,%3};"           \
                 : "+f"(d[0]), "+f"(d[1]), "+f"(d[2]), "+f"(d[3])               \
                 : "r"(A0), "r"(A1), "r"(A2), "r"(A3), "r"(B0), "r"(B1))

#define CPA(boff, p)                                                            \
    asm volatile("cp.async.cg.shared.global [%0], [%1], 16;"                    \
                 :: "r"(sbase + (unsigned)(boff)), "l"(p) : "memory")
#define CMT   asm volatile("cp.async.commit_group;" ::: "memory")
#define WAIT1 asm volatile("cp.async.wait_group 1;" ::: "memory")
#define WAIT2 asm volatile("cp.async.wait_group 2;" ::: "memory")

// team-B / precompute stage macros (stride STW)
#define LOADA(pA, s) do {                                                       \
    unsigned _off = (unsigned)((s) * STW * 4);                                  \
    _Pragma("unroll")                                                           \
    for (int _j = 0; _j < 4; _j++) { int _c = tid + _j * 256;                   \
        CPA(_off + (unsigned)_c * 16u, (pA) + _c * 4); }                        \
} while (0)
#define LOADB4K(pB, s) do {                                                     \
    unsigned _off = (unsigned)((s) * STW * 4) + 16384u;                         \
    _Pragma("unroll")                                                           \
    for (int _j = 0; _j < 4; _j++) { int _c = tid + _j * 256;                   \
        CPA(_off + (unsigned)_c * 16u, (pB) + _c * 4); }                        \
} while (0)
#define LOADBPC(pB0, pB1, s) do {                                               \
    unsigned _off = (unsigned)((s) * STW * 4) + 16384u;                         \
    _Pragma("unroll")                                                           \
    for (int _j = 0; _j < 4; _j++) { int _c = tid + _j * 256;                   \
        CPA(_off + (unsigned)_c * 16u, (pB0) + _c * 4);                         \
        CPA(_off + 16384u + (unsigned)_c * 16u, (pB1) + _c * 4); }              \
} while (0)
// team-A stage macros (stride SWA = 5120 words; 4 stages = 20480 words < 3*STW)
#define LOADAA(pA, s) do {                                                      \
    unsigned _off = (unsigned)((s) * SWA * 4);                                  \
    _Pragma("unroll")                                                           \
    for (int _j = 0; _j < 4; _j++) { int _c = tid + _j * 256;                   \
        CPA(_off + (unsigned)_c * 16u, (pA) + _c * 4); }                        \
} while (0)
#define LOADBA(pB, s) do {                                                      \
    unsigned _off = (unsigned)((s) * SWA * 4) + 16384u;                         \
    { int _c = tid; CPA(_off + (unsigned)_c * 16u, (pB) + _c * 4); }            \
} while (0)

// ---------------- sync primitives (proven) ----------------
__device__ __forceinline__ void gsync(unsigned& sense) {
    __threadfence();
    __syncthreads();
    unsigned target = sense ^ 1u;
    if (threadIdx.x == 0) {
        unsigned old = atomicAdd(&g_cnt, 1u);
        if (old == NB - 1) {
            g_cnt = 0;
            __threadfence();
            atomicExch(&g_sense, target);
        } else {
            while (atomicAdd(&g_sense, 0u) != target) { __nanosleep(128); }
        }
        __threadfence();
    }
    sense = target;
    __syncthreads();
}
__device__ __forceinline__ void wait_ge(unsigned* cnt, unsigned target) {
    if (threadIdx.x == 0) {
        while (atomicAdd(cnt, 0u) < target) { __nanosleep(64); }
    }
    __syncthreads();
}
__device__ __forceinline__ void arrive(unsigned* cnt) {
    __threadfence();
    __syncthreads();
    if (threadIdx.x == 0) atomicAdd(cnt, 1u);
}
__device__ __forceinline__ float wredsum(float v) {
#pragma unroll
    for (int o = 16; o; o >>= 1) v += __shfl_xor_sync(0xffffffffu, v, o);
    return v;
}

// ---------------- MMA bodies (R14) ----------------
__device__ __forceinline__ void mma64q(const unsigned* As, const unsigned* Bs,
                                       float acc[4][4], int wm, int wn, int lane) {
#pragma unroll
    for (int ks = 0; ks < 8; ks++) {
        uint4 a = *(const uint4*)&As[((wm * 8 + ks) * 32 + lane) * 4];
        uint4 b0 = *(const uint4*)&Bs[(((wn * 2 + 0) * 8 + ks) * 32 + lane) * 4];
        uint4 b1 = *(const uint4*)&Bs[(((wn * 2 + 1) * 8 + ks) * 32 + lane) * 4];
        MMA(acc[0], a.x, a.y, a.z, a.w, b0.x, b0.y);
        MMA(acc[1], a.x, a.y, a.z, a.w, b0.z, b0.w);
        MMA(acc[2], a.x, a.y, a.z, a.w, b1.x, b1.y);
        MMA(acc[3], a.x, a.y, a.z, a.w, b1.z, b1.w);
    }
}
__device__ __forceinline__ void mma16q(const unsigned* As, const unsigned* Bs,
                                       float acc[4], int wm, int wn, int lane) {
#pragma unroll
    for (int ks = 0; ks < 8; ks++) {
        uint4 a = *(const uint4*)&As[((wm * 8 + ks) * 32 + lane) * 4];
        uint4 b = *(const uint4*)&Bs[(ks * 32 + lane) * 4];
        unsigned b0 = wn ? b.z : b.x;
        unsigned b1 = wn ? b.w : b.y;
        MMA(acc, a.x, a.y, a.z, a.w, b0, b1);
    }
}
__device__ __forceinline__ void mma128q(const unsigned* As, const unsigned* Bs,
                                        float acc[8][4], int wm, int wn, int lane) {
    const unsigned* Bw = Bs + wn * 4096;
#pragma unroll
    for (int ks = 0; ks < 8; ks++) {
        uint4 a = *(const uint4*)&As[((wm * 8 + ks) * 32 + lane) * 4];
#pragma unroll
        for (int nb = 0; nb < 4; nb++) {
            uint4 b = *(const uint4*)&Bw[((nb * 8 + ks) * 32 + lane) * 4];
            MMA(acc[nb * 2 + 0], a.x, a.y, a.z, a.w, b.x, b.y);
            MMA(acc[nb * 2 + 1], a.x, a.y, a.z, a.w, b.z, b.w);
        }
    }
}

__device__ __forceinline__ const unsigned* pcA(int g, int t, int par, int kc) {
    if (kc < 4)  return g_ccq + ((size_t)g * 4 + kc) * 4096;
    if (kc < 8)  return g_mq + (((size_t)g * Tn + t) * 4 + (kc - 4)) * 4096;
    return g_hq + (((size_t)par * 4 + g) * 8 + (kc - 8)) * 4096;
}
__device__ __forceinline__ int pc_ord(int i) {
    return (i < 8) ? (8 + i) : ((i < 12) ? (i - 4) : (i - 12));
}

__global__ void __launch_bounds__(NT, 1) rits_kernel(
    const float* __restrict__ values, const float* __restrict__ masks,
    const float* __restrict__ deltas,
    const float* __restrict__ W_td_h, const float* __restrict__ b_td_h,
    const float* __restrict__ W_td_x, const float* __restrict__ b_td_x,
    const float* __restrict__ W_hist, const float* __restrict__ b_hist,
    const float* __restrict__ W_feat, const float* __restrict__ b_feat,
    const float* __restrict__ W_comb, const float* __restrict__ b_comb,
    const float* __restrict__ W_ih, const float* __restrict__ W_hh,
    const float* __restrict__ b_ih, const float* __restrict__ b_hh,
    float* __restrict__ out)
{
    extern __shared__ unsigned SHu[];
    float* RED = (float*)(SHu + NSTG * STW);
    unsigned sbase = (unsigned)__cvta_generic_to_shared(SHu);

    const int tid = threadIdx.x;
    const int cta = blockIdx.x;
    const int wid = tid >> 5;
    const int lane = tid & 31;
    const int gid = lane >> 2;
    const int tg = lane & 3;
    const int wm = wid & 3, wn = wid >> 2;

    const int g = cta >> 5;
    const int cg = cta & 31;
    const int b0 = g * 64;
    const int gtid = cta * NT + tid;

    unsigned sense = *((volatile unsigned*)&g_sense);

    // =================== init (R13/R14 vectorized) ===================
    for (int i = gtid; i < Bn * Hn; i += NTH) g_cst[i] = 0.0f;
    for (int i = gtid; i < 2 * 4 * 8 * 4096; i += NTH) g_hq[i] = 0u;

    {
        float* DIAG = (float*)SHu;
        float* BTDX = (float*)SHu + 256;
        if (tid < 256) {
            DIAG[tid] = W_td_x[tid * Fn + tid];
            BTDX[tid] = b_td_x[tid];
        }
        __syncthreads();
        for (int task = gtid; task < 409600; task += NTH) {
            int u = task >> 10;
            int rem = task & 1023;
            int kc = rem >> 8;
            int w = rem & 255;
            int ko = w & 7, rp = w >> 3;
            int rblk = rp >> 3, r0 = rp & 7;
            int bt_lo = u * 64 + rblk * 16 + r0;
            int f0 = kc * 64 + ko * 8;
            float dlo[8], dhi[8], mlo[8], mhi[8], glo[8], ghi[8];
            load8(&deltas[(size_t)bt_lo * Fn + f0], dlo);
            load8(&deltas[(size_t)(bt_lo + 8) * Fn + f0], dhi);
            load8(&masks[(size_t)bt_lo * Fn + f0], mlo);
            load8(&masks[(size_t)(bt_lo + 8) * Fn + f0], mhi);
#pragma unroll
            for (int q = 0; q < 8; q++) {
                float dg = DIAG[f0 + q], bb = BTDX[f0 + q];
                glo[q] = expf(-fmaxf(fmaf(dlo[q], dg, bb), 0.f));
                ghi[q] = expf(-fmaxf(fmaf(dhi[q], dg, bb), 0.f));
            }
            storeA16(g_dtq + ((size_t)u * 4 + kc) * 4096, rblk, r0, ko, dlo, dhi);
            storeA16(g_gxmq + ((size_t)u * 8 + kc) * 4096, rblk, r0, ko, glo, ghi);
            storeA16(g_gxmq + ((size_t)u * 8 + 4 + kc) * 4096, rblk, r0, ko, mlo, mhi);
        }
        for (int task = gtid; task < 409600; task += NTH) {
            int gt = task >> 10;
            int rem = task & 1023;
            int kc = rem >> 8;
            int w = rem & 255;
            int ko = w & 7, rp = w >> 3;
            int rblk = rp >> 3, r0 = rp & 7;
            int g2 = gt / Tn, t = gt - g2 * Tn;
            int blo = g2 * 64 + rblk * 16 + r0;
            int f0 = kc * 64 + ko * 8;
            float mlo[8], mhi[8];
            load8(&masks[((size_t)blo * Tn + t) * Fn + f0], mlo);
            load8(&masks[((size_t)(blo + 8) * Tn + t) * Fn + f0], mhi);
            storeA16(g_mq + (((size_t)g2 * Tn + t) * 4 + kc) * 4096, rblk, r0, ko, mlo, mhi);
        }
        __syncthreads();
    }

    for (int task = gtid; task < 8192; task += NTH) {
        int tile = task >> 8;
        int w = task & 255, ko = w & 7, np = w >> 3;
        int nblk = np >> 3, n0 = np & 7;
        int nt = tile >> 2, kt = tile & 3;
        int n_lo = nt * 64 + nblk * 16 + n0;
        int kg = kt * 64 + ko * 8;
        float lo[8], hi[8];
        load8(&W_td_h[(size_t)n_lo * 256 + kg], lo);
        load8(&W_td_h[(size_t)(n_lo + 8) * 256 + kg], hi);
        storeB16(g_Wtdhq + (size_t)tile * 4096, nblk, n0, ko, lo, hi);
    }
    for (int task = gtid; task < 8192; task += NTH) {
        int tile = task >> 8;
        int w = task & 255, ko = w & 7, np = w >> 3;
        int nblk = np >> 3, n0 = np & 7;
        int nt = tile >> 3, kt = tile & 7;
        int n_lo = nt * 64 + nblk * 16 + n0;
        int kg = kt * 64 + ko * 8;
        float lo[8], hi[8];
        load8(&W_comb[(size_t)n_lo * 512 + kg], lo);
        load8(&W_comb[(size_t)(n_lo + 8) * 512 + kg], hi);
        storeB16(g_Wcombq + (size_t)tile * 4096, nblk, n0, ko, lo, hi);
    }
    for (int task = gtid; task < 8192; task += NTH) {
        int tile = task >> 6;
        int w = task & 63, ko = w & 7, np = w >> 3;
        int nt = tile >> 3, kt = tile & 7;
        int n_lo = nt * 16 + np;
        int kg = kt * 64 + ko * 8;
        float lo[8], hi[8];
        load8(&W_hist[(size_t)n_lo * 512 + kg], lo);
        load8(&W_hist[(size_t)(n_lo + 8) * 512 + kg], hi);
        storeB16(g_Whistq + (size_t)tile * 1024, 0, np, ko, lo, hi);
    }
    for (int task = gtid; task < 4096; task += NTH) {
        int tile = task >> 6;
        int w = task & 63, ko = w & 7, np = w >> 3;
        int nt = tile >> 2, kt = tile & 3;
        int n_lo = nt * 16 + np;
        int kg = kt * 64 + ko * 8;
        float lo[8], hi[8];
        load8(&W_feat[(size_t)n_lo * 256 + kg], lo);
        load8(&W_feat[(size_t)(n_lo + 8) * 256 + kg], hi);
#pragma unroll
        for (int q = 0; q < 8; q++) {
            if (n_lo == kg + q) lo[q] = 0.0f;
            if (n_lo + 8 == kg + q) hi[q] = 0.0f;
        }
        storeB16(g_Wfeatq + (size_t)tile * 1024, 0, np, ko, lo, hi);
    }
    for (int task = gtid; task < 131072; task += NTH) {
        int tile = task >> 8;
        int w = task & 255, ko = w & 7, np = w >> 3;
        int nblk = np >> 3, n0 = np & 7;
        int nt = tile >> 4, kt = tile & 15;
        int n_lo = nt * 64 + nblk * 16 + n0;
        int kg = kt * 64 + ko * 8;
        int j = n_lo >> 2, gate = n_lo & 3;
        const float* src_lo;
        const float* src_hi;
        if (kg < 512) {
            src_lo = &W_ih[(size_t)(gate * Hn + j) * 512 + kg];
            src_hi = &W_ih[(size_t)(gate * Hn + j + 2) * 512 + kg];
        } else {
            src_lo = &W_hh[(size_t)(gate * Hn + j) * 512 + (kg - 512)];
            src_hi = &W_hh[(size_t)(gate * Hn + j + 2) * 512 + (kg - 512)];
        }
        float lo[8], hi[8];
        load8(src_lo, lo);
        load8(src_hi, hi);
        storeB16(g_Wgq + (size_t)tile * 4096, nblk, n0, ko, lo, hi);
    }
    for (int i = gtid; i < 4 * Hn; i += NTH) {
        int j = i >> 2, gate = i & 3;
        g_bg[i] = b_ih[gate * Hn + j] + b_hh[gate * Hn + j];
    }
    gsync(sense);

    // =================== precompute gamma_h + alpha ===================
    for (int tt = cta; tt < 4800; tt += NB) {
        float acc[4][4];
#pragma unroll
        for (int nf = 0; nf < 4; nf++)
#pragma unroll
            for (int e = 0; e < 4; e++) acc[nf][e] = 0.0f;

        const bool isg = (tt < 3200);
        const int u = isg ? tt : tt - 3200;
        const int ut = isg ? (u >> 3) : (u >> 2);
        const int nt = isg ? (u & 7) : (u & 3);
        const int m0 = ut * 64, n0 = nt * 64;
        const int NI = isg ? 4 : 8;
        const unsigned* Asrc = isg ? (g_dtq + (size_t)ut * 4 * 4096)
                                   : (g_gxmq + (size_t)ut * 8 * 4096);
        const unsigned* Bsrc = isg ? (g_Wtdhq + (size_t)nt * 4 * 4096)
                                   : (g_Wcombq + (size_t)nt * 8 * 4096);

        LOADA(Asrc, 0); LOADB4K(Bsrc, 0); CMT;
        LOADA(Asrc + 4096, Bsrc == 0 ? 1 : 1); LOADB4K(Bsrc + 4096, 1); CMT;
        for (int i = 0; i < NI; i++) {
            WAIT1;
            __syncthreads();
            if (i + 2 < NI) {
                LOADA(Asrc + (size_t)(i + 2) * 4096, (i + 2) % 3);
                LOADB4K(Bsrc + (size_t)(i + 2) * 4096, (i + 2) % 3);
            }
            CMT;
            int s = i % 3;
            mma64q(SHu + s * STW, SHu + s * STW + 4096, acc, wm, wn, lane);
        }
        __syncthreads();
#pragma unroll
        for (int nf = 0; nf < 4; nf++) {
#pragma unroll
            for (int ep = 0; ep < 2; ep++) {
                int bt = m0 + wm * 16 + gid + ep * 8;
                int n = n0 + wn * 32 + nf * 8 + 2 * tg;
                float v0 = acc[nf][2 * ep + 0], v1 = acc[nf][2 * ep + 1];
                float2 r;
                if (isg) {
                    r.x = expf(-fmaxf(v0 + b_td_h[n], 0.f));
                    r.y = expf(-fmaxf(v1 + b_td_h[n + 1], 0.f));
                    *(float2*)&g_gamma_h[(size_t)bt * Hn + n] = r;
                } else {
                    r.x = sigmoidf_(v0 + b_comb[n]);
                    r.y = sigmoidf_(v1 + b_comb[n + 1]);
                    *(float2*)&g_alpha[(size_t)bt * Fn + n] = r;
                }
            }
        }
    }
    gsync(sense);

    // =================== recurrence: team-split dataflow ===================
    for (int t = 0; t < Tn; t++) {
        const int par = t & 1, nxt = (t + 1) & 1;

        if (cg < 16) {
            // ===== team A: P_a then P_b (tile 64x16, 4-stage deep pipeline) =====
            const int n0 = cg * 16;
            float xh_r[4], x_r[4], m_r[4];
            {   // P_a: K=512, 8 iters
                const unsigned* Ah = g_hq + (((size_t)par * 4 + g) * 8) * 4096;
                const unsigned* Bw = g_Whistq + (size_t)cg * 8 * 1024;
                LOADBA(Bw, 0); LOADBA(Bw + 1024, 1); LOADBA(Bw + 2048, 2); CMT;
#pragma unroll
                for (int hh = 0; hh < 2; hh++) {
                    int b = b0 + wm * 16 + gid + hh * 8;
                    int f0 = n0 + wn * 8 + 2 * tg;
                    size_t vi = ((size_t)b * Tn + t) * Fn + f0;
                    float2 xv = *(const float2*)&values[vi];
                    float2 mv = *(const float2*)&masks[vi];
                    x_r[hh * 2 + 0] = xv.x; x_r[hh * 2 + 1] = xv.y;
                    m_r[hh * 2 + 0] = mv.x; m_r[hh * 2 + 1] = mv.y;
                }
                wait_ge(&g_cnt_h[g], 16u * (unsigned)t);
                LOADAA(Ah, 0); CMT;
                LOADAA(Ah + 4096, 1); CMT;
                LOADAA(Ah + 8192, 2); CMT;
                float acc[4] = {0.f, 0.f, 0.f, 0.f};
                for (int i = 0; i < 8; i++) {
                    WAIT2;
                    __syncthreads();
                    if (i + 3 < 8) {
                        LOADAA(Ah + (size_t)(i + 3) * 4096, (i + 3) & 3);
                        LOADBA(Bw + (size_t)(i + 3) * 1024, (i + 3) & 3);
                    }
                    CMT;
                    int s = i & 3;
                    mma16q(SHu + s * SWA, SHu + s * SWA + 4096, acc, wm, wn, lane);
                }
                float ls = 0.0f;
#pragma unroll
                for (int e = 0; e < 4; e++) {
                    int r = wm * 16 + gid + ((e >> 1) << 3);
                    int f = n0 + wn * 8 + 2 * tg + (e & 1);
                    float xh = acc[e] + b_hist[f];
                    float x = x_r[e], m = m_r[e];
                    xh_r[e] = xh;
                    ls += fabsf(xh - x) * m;
                    g_xcq[((size_t)g * 4 + (f >> 6)) * 4096 + o_A(r, f & 63)] =
                        f2tf(m * x + (1.0f - m) * xh);
                }
                arrive(&g_cnt_xh[g]);          // publish x_c ASAP; loss follows
                ls = wredsum(ls);
                if (lane == 0) RED[wid] = ls;
                __syncthreads();
                if (tid == 0) {
                    float s = 0.f;
#pragma unroll
                    for (int w = 0; w < 8; w++) s += RED[w];
                    g_l1[t * 64 + g * 16 + cg] = s;
                }
            }
            {   // P_b: K=256, 4 iters
                const unsigned* Ax = g_xcq + (size_t)g * 4 * 4096;
                const unsigned* Bf = g_Wfeatq + (size_t)cg * 4 * 1024;
                __syncthreads();               // all threads past P_a smem reads
                LOADBA(Bf, 0); LOADBA(Bf + 1024, 1); LOADBA(Bf + 2048, 2); CMT;
                float al_r[4];
#pragma unroll
                for (int hh = 0; hh < 2; hh++) {
                    int b = b0 + wm * 16 + gid + hh * 8;
                    int f0 = n0 + wn * 8 + 2 * tg;
                    size_t vi = ((size_t)b * Tn + t) * Fn + f0;
                    float2 av = *(const float2*)&g_alpha[vi];
                    al_r[hh * 2 + 0] = av.x; al_r[hh * 2 + 1] = av.y;
                }
                wait_ge(&g_cnt_xh[g], 16u * (unsigned)(t + 1));
                LOADAA(Ax, 0); CMT;
                LOADAA(Ax + 4096, 1); CMT;
                LOADAA(Ax + 8192, 2); CMT;
                float acc[4] = {0.f, 0.f, 0.f, 0.f};
                for (int i = 0; i < 4; i++) {
                    WAIT2;
                    __syncthreads();
                    if (i + 3 < 4) {
                        LOADAA(Ax + (size_t)(i + 3) * 4096, (i + 3) & 3);
                        LOADBA(Bf + (size_t)(i + 3) * 1024, (i + 3) & 3);
                    }
                    CMT;
                    int s = i & 3;
                    mma16q(SHu + s * SWA, SHu + s * SWA + 4096, acc, wm, wn, lane);
                }
                float l2s = 0.f, l3s = 0.f, dns = 0.f;
#pragma unroll
                for (int e = 0; e < 4; e++) {
                    int r = wm * 16 + gid + ((e >> 1) << 3);
                    int b = b0 + r;
                    int f = n0 + wn * 8 + 2 * tg + (e & 1);
                    size_t vi = ((size_t)b * Tn + t) * Fn + f;
                    float z = fmaxf(acc[e] + b_feat[f], 0.0f);
                    float al = al_r[e];
                    float x = x_r[e], m = m_r[e];
                    float ch = al * z + (1.0f - al) * xh_r[e];
                    float cc = m * x + (1.0f - m) * ch;
                    out[vi] = cc;
                    g_ccq[((size_t)g * 4 + (f >> 6)) * 4096 + o_A(r, f & 63)] = f2tf(cc);
                    l2s += fabsf(z - x) * m;
                    l3s += fabsf(ch - x) * m;
                    dns += m;
                }
                arrive(&g_cnt_cc[g]);          // publish c_c ASAP; losses follow
                l2s = wredsum(l2s); l3s = wredsum(l3s); dns = wredsum(dns);
                if (lane == 0) { RED[wid] = l2s; RED[8 + wid] = l3s; RED[16 + wid] = dns; }
                __syncthreads();
                if (tid == 0) {
                    float s2 = 0.f, s3 = 0.f, sd = 0.f;
#pragma unroll
                    for (int w = 0; w < 8; w++) { s2 += RED[w]; s3 += RED[8 + w]; sd += RED[16 + w]; }
                    int slot = t * 64 + g * 16 + cg;
                    g_l2[slot] = s2; g_l3[slot] = s3; g_den[slot] = sd;
                }
            }
        } else {
            // ===== team B: P_c (tile 64x128, K=1024, h-first) + LSTM =====
            const int cg16 = cg - 16;
            const int j0 = cg16 * 32;
            const unsigned* Bt0 = g_Wgq + ((size_t)(cg16 * 2 + 0) * 16) * 4096;
            const unsigned* Bt1 = g_Wgq + ((size_t)(cg16 * 2 + 1) * 16) * 4096;
            LOADBPC(Bt0 + (size_t)pc_ord(0) * 4096, Bt1 + (size_t)pc_ord(0) * 4096, 0);
            LOADBPC(Bt0 + (size_t)pc_ord(1) * 4096, Bt1 + (size_t)pc_ord(1) * 4096, 1);
            CMT;
            float cst_r[8], gam_r[8];
#pragma unroll
            for (int q = 0; q < 8; q++) {
                int idx = tid + q * 256;
                int r = idx >> 5, jl = idx & 31;
                int b = b0 + r;
                int j = j0 + jl;
                cst_r[q] = g_cst[b * Hn + j];
                gam_r[q] = (t + 1 < Tn)
                         ? g_gamma_h[((size_t)b * Tn + t + 1) * Hn + j] : 0.0f;
            }
            wait_ge(&g_cnt_h[g], 16u * (unsigned)t);
            LOADA(pcA(g, t, par, pc_ord(0)), 0); CMT;
            LOADA(pcA(g, t, par, pc_ord(1)), 1); CMT;
            float acc[8][4];
#pragma unroll
            for (int nf = 0; nf < 8; nf++)
#pragma unroll
                for (int e = 0; e < 4; e++) acc[nf][e] = 0.0f;
            for (int i = 0; i < 16; i++) {
                WAIT1;
                __syncthreads();
                if (i == 10) wait_ge(&g_cnt_cc[g], 16u * (unsigned)(t + 1));
                if (i + 2 < 16) {
                    int kc = pc_ord(i + 2);
                    LOADA(pcA(g, t, par, kc), (i + 2) % 3);
                    LOADBPC(Bt0 + (size_t)kc * 4096, Bt1 + (size_t)kc * 4096, (i + 2) % 3);
                }
                CMT;
                int s = i % 3;
                mma128q(SHu + s * STW, SHu + s * STW + 4096, acc, wm, wn, lane);
            }
            __syncthreads();
            float* EP = (float*)SHu;
#pragma unroll
            for (int nf = 0; nf < 8; nf++)
#pragma unroll
                for (int e = 0; e < 4; e++) {
                    int r = wm * 16 + gid + ((e >> 1) << 3);
                    int v = wn * 64 + nf * 8 + 2 * tg + (e & 1);
                    EP[r * EPIT + v] = acc[nf][e];
                }
            __syncthreads();
#pragma unroll
            for (int q = 0; q < 8; q++) {
                int idx = tid + q * 256;
                int r = idx >> 5, jl = idx & 31;
                int b = b0 + r;
                int j = j0 + jl;
                float ia = EP[r * EPIT + jl * 4 + 0] + g_bg[j * 4 + 0];
                float fa = EP[r * EPIT + jl * 4 + 1] + g_bg[j * 4 + 1];
                float ga = EP[r * EPIT + jl * 4 + 2] + g_bg[j * 4 + 2];
                float oa = EP[r * EPIT + jl * 4 + 3] + g_bg[j * 4 + 3];
                int ci = b * Hn + j;
                float cn = sigmoidf_(fa) * cst_r[q] + sigmoidf_(ia) * tanhf(ga);
                float hn = sigmoidf_(oa) * tanhf(cn);
                g_cst[ci] = cn;
                if (t + 1 < Tn) {
                    g_hq[(((size_t)nxt * 4 + g) * 8 + (j >> 6)) * 4096 + o_A(r, j & 63)] =
                        f2tf(hn * gam_r[q]);
                } else {
                    out[BTF + ci] = hn;
                }
            }
            arrive(&g_cnt_h[g]);
        }
    }

    gsync(sense);

    // =================== final loss reduction + counter reset ===================
    if (cta == 0) {
        float v = 0.0f;
        if (tid < Tn) {
            float den = 1e-9f, n1 = 0.f, n2 = 0.f, n3 = 0.f;
            for (int c2 = 0; c2 < 64; c2++) {
                den += g_den[tid * 64 + c2];
                n1 += g_l1[tid * 64 + c2];
                n2 += g_l2[tid * 64 + c2];
                n3 += g_l3[tid * 64 + c2];
            }
            v = (n1 + n2 + n3) / den;
        }
        __syncthreads();
        RED[tid] = v;
        __syncthreads();
#pragma unroll
        for (int s = 128; s > 0; s >>= 1) {
            if (tid < s) RED[tid] += RED[tid + s];
            __syncthreads();
        }
        if (tid == 0) {
            out[BTF + Bn * Hn] = RED[0] / (3.0f * Tn);
#pragma unroll
            for (int i = 0; i < 4; i++) { g_cnt_h[i] = 0u; g_cnt_xh[i] = 0u; g_cnt_cc[i] = 0u; }
            __threadfence();
        }
    }
}

extern "C" void kernel_launch(void* const* d_in, const int* in_sizes, int n_in,
                              void* d_out, int out_size) {
    (void)in_sizes; (void)n_in; (void)out_size;
    static int configured = 0;
    if (!configured) {
        cudaFuncSetAttribute(rits_kernel, cudaFuncAttributeMaxDynamicSharedMemorySize,
                             SMEM_BYTES);
        configured = 1;
    }
    rits_kernel<<<NB, NT, SMEM_BYTES>>>(
        (const float*)d_in[0],  (const float*)d_in[1],  (const float*)d_in[2],
        (const float*)d_in[3],  (const float*)d_in[4],  (const float*)d_in[5],
        (const float*)d_in[6],  (const float*)d_in[7],  (const float*)d_in[8],
        (const float*)d_in[9],  (const float*)d_in[10], (const float*)d_in[11],
        (const float*)d_in[12], (const float*)d_in[13], (const float*)d_in[14],
        (const float*)d_in[15], (const float*)d_in[16],
        (float*)d_out);
}

// round 16
// speedup vs baseline: 1.9179x; 1.0725x over previous
#include <cuda_runtime.h>
#include <math.h>

#define Bn 256
#define Tn 100
#define Fn 256
#define Hn 512
#define NB 128
#define NT 256
#define BT (Bn * Tn)
#define STW 12288                  // team-B stage words: A 4096 + B 8192
#define NSTG 3
#define EPIT 132
#define RESOFF 16384               // team-A resident weights offset (words)
#define SMEM_WORDS (NSTG * STW + 256)
#define SMEM_BYTES (SMEM_WORDS * 4)
#define BTF ((size_t)Bn * Tn * Fn)
#define NTH (NB * NT)

// ---------------- global scratch (allocation-free rule) ----------------
__device__ unsigned g_dtq[(size_t)400 * 4 * 4096];
__device__ unsigned g_gxmq[(size_t)400 * 8 * 4096];
__device__ unsigned g_mq[(size_t)4 * Tn * 4 * 4096];
__device__ unsigned g_Wtdhq[8 * 4 * 4096];
__device__ unsigned g_Wcombq[4 * 8 * 4096];
__device__ unsigned g_Whistq[16 * 8 * 1024];
__device__ unsigned g_Wfeatq[16 * 4 * 1024];
__device__ unsigned g_Wgq[32 * 16 * 4096];
__device__ unsigned g_hq[2 * 4 * 8 * 4096];
__device__ unsigned g_xcq[4 * 4 * 4096];
__device__ unsigned g_ccq[4 * 4 * 4096];
__device__ float g_gamma_h[(size_t)BT * Hn];
__device__ float g_alpha[(size_t)BT * Fn];
__device__ float g_bg[4 * Hn];
__device__ float g_cst[Bn * Hn];
__device__ float g_l1[Tn * 64], g_l2[Tn * 64], g_l3[Tn * 64], g_den[Tn * 64];
__device__ unsigned g_cnt, g_sense;
__device__ unsigned g_cnt_h[4], g_cnt_xh[4], g_cnt_cc[4];

__device__ __forceinline__ float sigmoidf_(float x) { return 1.0f / (1.0f + expf(-x)); }

__device__ __forceinline__ unsigned f2tf(float f) {
    unsigned u;
    asm("cvt.rna.tf32.f32 %0, %1;" : "=r"(u) : "f"(f));
    return u;
}

__device__ __forceinline__ int o_A(int r, int k) {
    return ((r >> 4) * 8 + (k >> 3)) * 128 + ((r & 7) * 4 + (k & 3)) * 4 +
           ((k & 4) >> 1) + ((r & 8) >> 3);
}

// vectorized init helpers (proven)
__device__ __forceinline__ void load8(const float* p, float* v) {
    float4 a = *(const float4*)p, b = *(const float4*)(p + 4);
    v[0] = a.x; v[1] = a.y; v[2] = a.z; v[3] = a.w;
    v[4] = b.x; v[5] = b.y; v[6] = b.z; v[7] = b.w;
}
__device__ __forceinline__ void storeA16(unsigned* tile, int rblk, int r0, int ko,
                                         const float* lo, const float* hi) {
    unsigned* dst = tile + (size_t)(rblk * 8 + ko) * 128 + r0 * 16;
#pragma unroll
    for (int tg = 0; tg < 4; tg++) {
        uint4 q = {f2tf(lo[tg]), f2tf(hi[tg]), f2tf(lo[tg + 4]), f2tf(hi[tg + 4])};
        *(uint4*)&dst[tg * 4] = q;
    }
}
__device__ __forceinline__ void storeB16(unsigned* tile, int nblk, int n0, int ko,
                                         const float* lo, const float* hi) {
    unsigned* dst = tile + (size_t)(nblk * 8 + ko) * 128 + n0 * 16;
#pragma unroll
    for (int tg = 0; tg < 4; tg++) {
        uint4 q = {f2tf(lo[tg]), f2tf(lo[tg + 4]), f2tf(hi[tg]), f2tf(hi[tg + 4])};
        *(uint4*)&dst[tg * 4] = q;
    }
}

#define MMA(d, A0, A1, A2, A3, B0, B1)                                          \
    asm volatile("mma.sync.aligned.m16n8k8.row.col.f32.tf32.tf32.f32 "          \
                 "{%0,%1,%2,%3},{%4,%5,%6,%7},{%8,%9},{%0,%1,%2,%3};"           \
                 : "+f"(d[0]), "+f"(d[1]), "+f"(d[2]), "+f"(d[3])               \
                 : "r"(A0), "r"(A1), "r"(A2), "r"(A3), "r"(B0), "r"(B1))

#define CPA(boff, p)                                                            \
    asm volatile("cp.async.cg.shared.global [%0], [%1], 16;"                    \
                 :: "r"(sbase + (unsigned)(boff)), "l"(p) : "memory")
#define CMT   asm volatile("cp.async.commit_group;" ::: "memory")
#define WAIT0 asm volatile("cp.async.wait_group 0;" ::: "memory")
#define WAIT1 asm volatile("cp.async.wait_group 1;" ::: "memory")
#define WAIT2 asm volatile("cp.async.wait_group 2;" ::: "memory")

// team-B / precompute stage macros (stride STW)
#define LOADA(pA, s) do {                                                       \
    unsigned _off = (unsigned)((s) * STW * 4);                                  \
    _Pragma("unroll")                                                           \
    for (int _j = 0; _j < 4; _j++) { int _c = tid + _j * 256;                   \
        CPA(_off + (unsigned)_c * 16u, (pA) + _c * 4); }                        \
} while (0)
#define LOADB4K(pB, s) do {                                                     \
    unsigned _off = (unsigned)((s) * STW * 4) + 16384u;                         \
    _Pragma("unroll")                                                           \
    for (int _j = 0; _j < 4; _j++) { int _c = tid + _j * 256;                   \
        CPA(_off + (unsigned)_c * 16u, (pB) + _c * 4); }                        \
} while (0)
#define LOADBPC(pB0, pB1, s) do {                                               \
    unsigned _off = (unsigned)((s) * STW * 4) + 16384u;                         \
    _Pragma("unroll")                                                           \
    for (int _j = 0; _j < 4; _j++) { int _c = tid + _j * 256;                   \
        CPA(_off + (unsigned)_c * 16u, (pB0) + _c * 4);                         \
        CPA(_off + 16384u + (unsigned)_c * 16u, (pB1) + _c * 4); }              \
} while (0)
// team-A A-only stage macro (stride 4096 words, 4 stages in [0, RESOFF))
#define LOADA2(pA, s) do {                                                      \
    unsigned _off = (unsigned)((s) * 16384);                                    \
    _Pragma("unroll")                                                           \
    for (int _j = 0; _j < 4; _j++) { int _c = tid + _j * 256;                   \
        CPA(_off + (unsigned)_c * 16u, (pA) + _c * 4); }                        \
} while (0)

// ---------------- sync primitives (proven) ----------------
__device__ __forceinline__ void gsync(unsigned& sense) {
    __threadfence();
    __syncthreads();
    unsigned target = sense ^ 1u;
    if (threadIdx.x == 0) {
        unsigned old = atomicAdd(&g_cnt, 1u);
        if (old == NB - 1) {
            g_cnt = 0;
            __threadfence();
            atomicExch(&g_sense, target);
        } else {
            while (atomicAdd(&g_sense, 0u) != target) { __nanosleep(128); }
        }
        __threadfence();
    }
    sense = target;
    __syncthreads();
}
__device__ __forceinline__ void wait_ge(unsigned* cnt, unsigned target) {
    if (threadIdx.x == 0) {
        while (atomicAdd(cnt, 0u) < target) { __nanosleep(64); }
    }
    __syncthreads();
}
__device__ __forceinline__ void arrive(unsigned* cnt) {
    __threadfence();
    __syncthreads();
    if (threadIdx.x == 0) atomicAdd(cnt, 1u);
}
__device__ __forceinline__ float wredsum(float v) {
#pragma unroll
    for (int o = 16; o; o >>= 1) v += __shfl_xor_sync(0xffffffffu, v, o);
    return v;
}

// ---------------- MMA bodies ----------------
// precompute 64x64: warps 4(M)x2(N), warp tile 16x32
__device__ __forceinline__ void mma64q(const unsigned* As, const unsigned* Bs,
                                       float acc[4][4], int wm, int wn, int lane) {
#pragma unroll
    for (int ks = 0; ks < 8; ks++) {
        uint4 a = *(const uint4*)&As[((wm * 8 + ks) * 32 + lane) * 4];
        uint4 b0 = *(const uint4*)&Bs[(((wn * 2 + 0) * 8 + ks) * 32 + lane) * 4];
        uint4 b1 = *(const uint4*)&Bs[(((wn * 2 + 1) * 8 + ks) * 32 + lane) * 4];
        MMA(acc[0], a.x, a.y, a.z, a.w, b0.x, b0.y);
        MMA(acc[1], a.x, a.y, a.z, a.w, b0.z, b0.w);
        MMA(acc[2], a.x, a.y, a.z, a.w, b1.x, b1.y);
        MMA(acc[3], a.x, a.y, a.z, a.w, b1.z, b1.w);
    }
}
// team-A 64x16: warps 4(M)x2(N), warp tile 16x8
__device__ __forceinline__ void mma16q(const unsigned* As, const unsigned* Bs,
                                       float acc[4], int wm, int wn, int lane) {
#pragma unroll
    for (int ks = 0; ks < 8; ks++) {
        uint4 a = *(const uint4*)&As[((wm * 8 + ks) * 32 + lane) * 4];
        uint4 b = *(const uint4*)&Bs[(ks * 32 + lane) * 4];
        unsigned b0 = wn ? b.z : b.x;
        unsigned b1 = wn ? b.w : b.y;
        MMA(acc, a.x, a.y, a.z, a.w, b0, b1);
    }
}
// team-B 64x128: warps 2(M)x4(N), warp tile 32x32 (reduced B re-reads)
__device__ __forceinline__ void mma128r(const unsigned* As, const unsigned* Bs,
                                        float acc[2][4][4], int wm, int wn, int lane) {
    const unsigned* Bt = Bs + (wn >> 1) * 4096;    // which 64-n tile
    const int nb0 = (wn & 1) * 2;                  // first 16-n block in tile
#pragma unroll
    for (int ks = 0; ks < 8; ks++) {
        uint4 a0 = *(const uint4*)&As[(((wm * 2 + 0) * 8 + ks) * 32 + lane) * 4];
        uint4 a1 = *(const uint4*)&As[(((wm * 2 + 1) * 8 + ks) * 32 + lane) * 4];
        uint4 b0 = *(const uint4*)&Bt[(((nb0 + 0) * 8 + ks) * 32 + lane) * 4];
        uint4 b1 = *(const uint4*)&Bt[(((nb0 + 1) * 8 + ks) * 32 + lane) * 4];
        MMA(acc[0][0], a0.x, a0.y, a0.z, a0.w, b0.x, b0.y);
        MMA(acc[0][1], a0.x, a0.y, a0.z, a0.w, b0.z, b0.w);
        MMA(acc[0][2], a0.x, a0.y, a0.z, a0.w, b1.x, b1.y);
        MMA(acc[0][3], a0.x, a0.y, a0.z, a0.w, b1.z, b1.w);
        MMA(acc[1][0], a1.x, a1.y, a1.z, a1.w, b0.x, b0.y);
        MMA(acc[1][1], a1.x, a1.y, a1.z, a1.w, b0.z, b0.w);
        MMA(acc[1][2], a1.x, a1.y, a1.z, a1.w, b1.x, b1.y);
        MMA(acc[1][3], a1.x, a1.y, a1.z, a1.w, b1.z, b1.w);
    }
}

__device__ __forceinline__ const unsigned* pcA(int g, int t, int par, int kc) {
    if (kc < 4)  return g_ccq + ((size_t)g * 4 + kc) * 4096;
    if (kc < 8)  return g_mq + (((size_t)g * Tn + t) * 4 + (kc - 4)) * 4096;
    return g_hq + (((size_t)par * 4 + g) * 8 + (kc - 8)) * 4096;
}
__device__ __forceinline__ int pc_ord(int i) {
    return (i < 8) ? (8 + i) : ((i < 12) ? (i - 4) : (i - 12));
}

__global__ void __launch_bounds__(NT, 1) rits_kernel(
    const float* __restrict__ values, const float* __restrict__ masks,
    const float* __restrict__ deltas,
    const float* __restrict__ W_td_h, const float* __restrict__ b_td_h,
    const float* __restrict__ W_td_x, const float* __restrict__ b_td_x,
    const float* __restrict__ W_hist, const float* __restrict__ b_hist,
    const float* __restrict__ W_feat, const float* __restrict__ b_feat,
    const float* __restrict__ W_comb, const float* __restrict__ b_comb,
    const float* __restrict__ W_ih, const float* __restrict__ W_hh,
    const float* __restrict__ b_ih, const float* __restrict__ b_hh,
    float* __restrict__ out)
{
    extern __shared__ unsigned SHu[];
    float* RED = (float*)(SHu + NSTG * STW);
    unsigned sbase = (unsigned)__cvta_generic_to_shared(SHu);

    const int tid = threadIdx.x;
    const int cta = blockIdx.x;
    const int wid = tid >> 5;
    const int lane = tid & 31;
    const int gid = lane >> 2;
    const int tg = lane & 3;
    const int wm = wid & 3, wn = wid >> 2;     // precompute / team-A grid
    const int wmB = wid & 1, wnB = wid >> 1;   // team-B 2x4 grid

    const int g = cta >> 5;
    const int cg = cta & 31;
    const int b0 = g * 64;
    const int gtid = cta * NT + tid;

    unsigned sense = *((volatile unsigned*)&g_sense);

    // =================== init (R13-R15 vectorized, unchanged) ===================
    for (int i = gtid; i < Bn * Hn; i += NTH) g_cst[i] = 0.0f;
    for (int i = gtid; i < 2 * 4 * 8 * 4096; i += NTH) g_hq[i] = 0u;

    {
        float* DIAG = (float*)SHu;
        float* BTDX = (float*)SHu + 256;
        if (tid < 256) {
            DIAG[tid] = W_td_x[tid * Fn + tid];
            BTDX[tid] = b_td_x[tid];
        }
        __syncthreads();
        for (int task = gtid; task < 409600; task += NTH) {
            int u = task >> 10;
            int rem = task & 1023;
            int kc = rem >> 8;
            int w = rem & 255;
            int ko = w & 7, rp = w >> 3;
            int rblk = rp >> 3, r0 = rp & 7;
            int bt_lo = u * 64 + rblk * 16 + r0;
            int f0 = kc * 64 + ko * 8;
            float dlo[8], dhi[8], mlo[8], mhi[8], glo[8], ghi[8];
            load8(&deltas[(size_t)bt_lo * Fn + f0], dlo);
            load8(&deltas[(size_t)(bt_lo + 8) * Fn + f0], dhi);
            load8(&masks[(size_t)bt_lo * Fn + f0], mlo);
            load8(&masks[(size_t)(bt_lo + 8) * Fn + f0], mhi);
#pragma unroll
            for (int q = 0; q < 8; q++) {
                float dg = DIAG[f0 + q], bb = BTDX[f0 + q];
                glo[q] = expf(-fmaxf(fmaf(dlo[q], dg, bb), 0.f));
                ghi[q] = expf(-fmaxf(fmaf(dhi[q], dg, bb), 0.f));
            }
            storeA16(g_dtq + ((size_t)u * 4 + kc) * 4096, rblk, r0, ko, dlo, dhi);
            storeA16(g_gxmq + ((size_t)u * 8 + kc) * 4096, rblk, r0, ko, glo, ghi);
            storeA16(g_gxmq + ((size_t)u * 8 + 4 + kc) * 4096, rblk, r0, ko, mlo, mhi);
        }
        for (int task = gtid; task < 409600; task += NTH) {
            int gt = task >> 10;
            int rem = task & 1023;
            int kc = rem >> 8;
            int w = rem & 255;
            int ko = w & 7, rp = w >> 3;
            int rblk = rp >> 3, r0 = rp & 7;
            int g2 = gt / Tn, t = gt - g2 * Tn;
            int blo = g2 * 64 + rblk * 16 + r0;
            int f0 = kc * 64 + ko * 8;
            float mlo[8], mhi[8];
            load8(&masks[((size_t)blo * Tn + t) * Fn + f0], mlo);
            load8(&masks[((size_t)(blo + 8) * Tn + t) * Fn + f0], mhi);
            storeA16(g_mq + (((size_t)g2 * Tn + t) * 4 + kc) * 4096, rblk, r0, ko, mlo, mhi);
        }
        __syncthreads();
    }

    for (int task = gtid; task < 8192; task += NTH) {
        int tile = task >> 8;
        int w = task & 255, ko = w & 7, np = w >> 3;
        int nblk = np >> 3, n0 = np & 7;
        int nt = tile >> 2, kt = tile & 3;
        int n_lo = nt * 64 + nblk * 16 + n0;
        int kg = kt * 64 + ko * 8;
        float lo[8], hi[8];
        load8(&W_td_h[(size_t)n_lo * 256 + kg], lo);
        load8(&W_td_h[(size_t)(n_lo + 8) * 256 + kg], hi);
        storeB16(g_Wtdhq + (size_t)tile * 4096, nblk, n0, ko, lo, hi);
    }
    for (int task = gtid; task < 8192; task += NTH) {
        int tile = task >> 8;
        int w = task & 255, ko = w & 7, np = w >> 3;
        int nblk = np >> 3, n0 = np & 7;
        int nt = tile >> 3, kt = tile & 7;
        int n_lo = nt * 64 + nblk * 16 + n0;
        int kg = kt * 64 + ko * 8;
        float lo[8], hi[8];
        load8(&W_comb[(size_t)n_lo * 512 + kg], lo);
        load8(&W_comb[(size_t)(n_lo + 8) * 512 + kg], hi);
        storeB16(g_Wcombq + (size_t)tile * 4096, nblk, n0, ko, lo, hi);
    }
    for (int task = gtid; task < 8192; task += NTH) {
        int tile = task >> 6;
        int w = task & 63, ko = w & 7, np = w >> 3;
        int nt = tile >> 3, kt = tile & 7;
        int n_lo = nt * 16 + np;
        int kg = kt * 64 + ko * 8;
        float lo[8], hi[8];
        load8(&W_hist[(size_t)n_lo * 512 + kg], lo);
        load8(&W_hist[(size_t)(n_lo + 8) * 512 + kg], hi);
        storeB16(g_Whistq + (size_t)tile * 1024, 0, np, ko, lo, hi);
    }
    for (int task = gtid; task < 4096; task += NTH) {
        int tile = task >> 6;
        int w = task & 63, ko = w & 7, np = w >> 3;
        int nt = tile >> 2, kt = tile & 3;
        int n_lo = nt * 16 + np;
        int kg = kt * 64 + ko * 8;
        float lo[8], hi[8];
        load8(&W_feat[(size_t)n_lo * 256 + kg], lo);
        load8(&W_feat[(size_t)(n_lo + 8) * 256 + kg], hi);
#pragma unroll
        for (int q = 0; q < 8; q++) {
            if (n_lo == kg + q) lo[q] = 0.0f;
            if (n_lo + 8 == kg + q) hi[q] = 0.0f;
        }
        storeB16(g_Wfeatq + (size_t)tile * 1024, 0, np, ko, lo, hi);
    }
    for (int task = gtid; task < 131072; task += NTH) {
        int tile = task >> 8;
        int w = task & 255, ko = w & 7, np = w >> 3;
        int nblk = np >> 3, n0 = np & 7;
        int nt = tile >> 4, kt = tile & 15;
        int n_lo = nt * 64 + nblk * 16 + n0;
        int kg = kt * 64 + ko * 8;
        int j = n_lo >> 2, gate = n_lo & 3;
        const float* src_lo;
        const float* src_hi;
        if (kg < 512) {
            src_lo = &W_ih[(size_t)(gate * Hn + j) * 512 + kg];
            src_hi = &W_ih[(size_t)(gate * Hn + j + 2) * 512 + kg];
        } else {
            src_lo = &W_hh[(size_t)(gate * Hn + j) * 512 + (kg - 512)];
            src_hi = &W_hh[(size_t)(gate * Hn + j + 2) * 512 + (kg - 512)];
        }
        float lo[8], hi[8];
        load8(src_lo, lo);
        load8(src_hi, hi);
        storeB16(g_Wgq + (size_t)tile * 4096, nblk, n0, ko, lo, hi);
    }
    for (int i = gtid; i < 4 * Hn; i += NTH) {
        int j = i >> 2, gate = i & 3;
        g_bg[i] = b_ih[gate * Hn + j] + b_hh[gate * Hn + j];
    }
    gsync(sense);

    // =================== precompute gamma_h + alpha (unchanged) ===================
    for (int tt = cta; tt < 4800; tt += NB) {
        float acc[4][4];
#pragma unroll
        for (int nf = 0; nf < 4; nf++)
#pragma unroll
            for (int e = 0; e < 4; e++) acc[nf][e] = 0.0f;

        const bool isg = (tt < 3200);
        const int u = isg ? tt : tt - 3200;
        const int ut = isg ? (u >> 3) : (u >> 2);
        const int nt = isg ? (u & 7) : (u & 3);
        const int m0 = ut * 64, n0 = nt * 64;
        const int NI = isg ? 4 : 8;
        const unsigned* Asrc = isg ? (g_dtq + (size_t)ut * 4 * 4096)
                                   : (g_gxmq + (size_t)ut * 8 * 4096);
        const unsigned* Bsrc = isg ? (g_Wtdhq + (size_t)nt * 4 * 4096)
                                   : (g_Wcombq + (size_t)nt * 8 * 4096);

        LOADA(Asrc, 0); LOADB4K(Bsrc, 0); CMT;
        LOADA(Asrc + 4096, 1); LOADB4K(Bsrc + 4096, 1); CMT;
        for (int i = 0; i < NI; i++) {
            WAIT1;
            __syncthreads();
            if (i + 2 < NI) {
                LOADA(Asrc + (size_t)(i + 2) * 4096, (i + 2) % 3);
                LOADB4K(Bsrc + (size_t)(i + 2) * 4096, (i + 2) % 3);
            }
            CMT;
            int s = i % 3;
            mma64q(SHu + s * STW, SHu + s * STW + 4096, acc, wm, wn, lane);
        }
        __syncthreads();
#pragma unroll
        for (int nf = 0; nf < 4; nf++) {
#pragma unroll
            for (int ep = 0; ep < 2; ep++) {
                int bt = m0 + wm * 16 + gid + ep * 8;
                int n = n0 + wn * 32 + nf * 8 + 2 * tg;
                float v0 = acc[nf][2 * ep + 0], v1 = acc[nf][2 * ep + 1];
                float2 r;
                if (isg) {
                    r.x = expf(-fmaxf(v0 + b_td_h[n], 0.f));
                    r.y = expf(-fmaxf(v1 + b_td_h[n + 1], 0.f));
                    *(float2*)&g_gamma_h[(size_t)bt * Hn + n] = r;
                } else {
                    r.x = sigmoidf_(v0 + b_comb[n]);
                    r.y = sigmoidf_(v1 + b_comb[n + 1]);
                    *(float2*)&g_alpha[(size_t)bt * Fn + n] = r;
                }
            }
        }
    }
    gsync(sense);

    // ===== team-A: load resident weight slices ONCE (W_hist 8192w + W_feat 4096w) =====
    if (cg < 16) {
        const unsigned* Wh = g_Whistq + (size_t)cg * 8 * 1024;
        const unsigned* Wf = g_Wfeatq + (size_t)cg * 4 * 1024;
#pragma unroll
        for (int j = 0; j < 8; j++) {
            int c = tid + j * 256;
            CPA((unsigned)(RESOFF + c * 4) * 4u, Wh + c * 4);
        }
#pragma unroll
        for (int j = 0; j < 4; j++) {
            int c = tid + j * 256;
            CPA((unsigned)(RESOFF + 8192 + c * 4) * 4u, Wf + c * 4);
        }
        CMT; WAIT0;
        __syncthreads();
    }
    const unsigned* RESH = SHu + RESOFF;
    const unsigned* RESF = SHu + RESOFF + 8192;

    // =================== recurrence: team-split dataflow ===================
    for (int t = 0; t < Tn; t++) {
        const int par = t & 1, nxt = (t + 1) & 1;

        if (cg < 16) {
            // ===== team A: P_a then P_b; A-only 4-stage pipeline, resident B =====
            const int n0 = cg * 16;
            float xh_r[4], x_r[4], m_r[4];
            {   // P_a: K=512, 8 iters
                const unsigned* Ah = g_hq + (((size_t)par * 4 + g) * 8) * 4096;
#pragma unroll
                for (int hh = 0; hh < 2; hh++) {
                    int b = b0 + wm * 16 + gid + hh * 8;
                    int f0 = n0 + wn * 8 + 2 * tg;
                    size_t vi = ((size_t)b * Tn + t) * Fn + f0;
                    float2 xv = *(const float2*)&values[vi];
                    float2 mv = *(const float2*)&masks[vi];
                    x_r[hh * 2 + 0] = xv.x; x_r[hh * 2 + 1] = xv.y;
                    m_r[hh * 2 + 0] = mv.x; m_r[hh * 2 + 1] = mv.y;
                }
                wait_ge(&g_cnt_h[g], 16u * (unsigned)t);
                LOADA2(Ah, 0); CMT;
                LOADA2(Ah + 4096, 1); CMT;
                LOADA2(Ah + 8192, 2); CMT;
                float acc[4] = {0.f, 0.f, 0.f, 0.f};
                for (int i = 0; i < 8; i++) {
                    WAIT2;
                    __syncthreads();
                    if (i + 3 < 8) LOADA2(Ah + (size_t)(i + 3) * 4096, (i + 3) & 3);
                    CMT;
                    mma16q(SHu + (i & 3) * 4096, RESH + i * 1024, acc, wm, wn, lane);
                }
                float ls = 0.0f;
#pragma unroll
                for (int e = 0; e < 4; e++) {
                    int r = wm * 16 + gid + ((e >> 1) << 3);
                    int f = n0 + wn * 8 + 2 * tg + (e & 1);
                    float xh = acc[e] + b_hist[f];
                    float x = x_r[e], m = m_r[e];
                    xh_r[e] = xh;
                    ls += fabsf(xh - x) * m;
                    g_xcq[((size_t)g * 4 + (f >> 6)) * 4096 + o_A(r, f & 63)] =
                        f2tf(m * x + (1.0f - m) * xh);
                }
                arrive(&g_cnt_xh[g]);
                ls = wredsum(ls);
                if (lane == 0) RED[wid] = ls;
                __syncthreads();
                if (tid == 0) {
                    float s = 0.f;
#pragma unroll
                    for (int w = 0; w < 8; w++) s += RED[w];
                    g_l1[t * 64 + g * 16 + cg] = s;
                }
            }
            {   // P_b: K=256, 4 iters
                const unsigned* Ax = g_xcq + (size_t)g * 4 * 4096;
                float al_r[4];
#pragma unroll
                for (int hh = 0; hh < 2; hh++) {
                    int b = b0 + wm * 16 + gid + hh * 8;
                    int f0 = n0 + wn * 8 + 2 * tg;
                    size_t vi = ((size_t)b * Tn + t) * Fn + f0;
                    float2 av = *(const float2*)&g_alpha[vi];
                    al_r[hh * 2 + 0] = av.x; al_r[hh * 2 + 1] = av.y;
                }
                __syncthreads();   // all threads past P_a stage reads
                wait_ge(&g_cnt_xh[g], 16u * (unsigned)(t + 1));
                LOADA2(Ax, 0); CMT;
                LOADA2(Ax + 4096, 1); CMT;
                LOADA2(Ax + 8192, 2); CMT;
                float acc[4] = {0.f, 0.f, 0.f, 0.f};
                for (int i = 0; i < 4; i++) {
                    WAIT2;
                    __syncthreads();
                    if (i + 3 < 4) LOADA2(Ax + (size_t)(i + 3) * 4096, (i + 3) & 3);
                    CMT;
                    mma16q(SHu + (i & 3) * 4096, RESF + i * 1024, acc, wm, wn, lane);
                }
                float l2s = 0.f, l3s = 0.f, dns = 0.f;
#pragma unroll
                for (int e = 0; e < 4; e++) {
                    int r = wm * 16 + gid + ((e >> 1) << 3);
                    int b = b0 + r;
                    int f = n0 + wn * 8 + 2 * tg + (e & 1);
                    size_t vi = ((size_t)b * Tn + t) * Fn + f;
                    float z = fmaxf(acc[e] + b_feat[f], 0.0f);
                    float al = al_r[e];
                    float x = x_r[e], m = m_r[e];
                    float ch = al * z + (1.0f - al) * xh_r[e];
                    float cc = m * x + (1.0f - m) * ch;
                    out[vi] = cc;
                    g_ccq[((size_t)g * 4 + (f >> 6)) * 4096 + o_A(r, f & 63)] = f2tf(cc);
                    l2s += fabsf(z - x) * m;
                    l3s += fabsf(ch - x) * m;
                    dns += m;
                }
                arrive(&g_cnt_cc[g]);
                l2s = wredsum(l2s); l3s = wredsum(l3s); dns = wredsum(dns);
                if (lane == 0) { RED[wid] = l2s; RED[8 + wid] = l3s; RED[16 + wid] = dns; }
                __syncthreads();
                if (tid == 0) {
                    float s2 = 0.f, s3 = 0.f, sd = 0.f;
#pragma unroll
                    for (int w = 0; w < 8; w++) { s2 += RED[w]; s3 += RED[8 + w]; sd += RED[16 + w]; }
                    int slot = t * 64 + g * 16 + cg;
                    g_l2[slot] = s2; g_l3[slot] = s3; g_den[slot] = sd;
                }
            }
        } else {
            // ===== team B: P_c (64x128, K=1024, h-first, 32x32 warp tiles) + LSTM =====
            const int cg16 = cg - 16;
            const int j0 = cg16 * 32;
            const unsigned* Bt0 = g_Wgq + ((size_t)(cg16 * 2 + 0) * 16) * 4096;
            const unsigned* Bt1 = g_Wgq + ((size_t)(cg16 * 2 + 1) * 16) * 4096;
            LOADBPC(Bt0 + (size_t)pc_ord(0) * 4096, Bt1 + (size_t)pc_ord(0) * 4096, 0);
            LOADBPC(Bt0 + (size_t)pc_ord(1) * 4096, Bt1 + (size_t)pc_ord(1) * 4096, 1);
            CMT;
            float cst_r[8], gam_r[8];
#pragma unroll
            for (int q = 0; q < 8; q++) {
                int idx = tid + q * 256;
                int r = idx >> 5, jl = idx & 31;
                int b = b0 + r;
                int j = j0 + jl;
                cst_r[q] = g_cst[b * Hn + j];
                gam_r[q] = (t + 1 < Tn)
                         ? g_gamma_h[((size_t)b * Tn + t + 1) * Hn + j] : 0.0f;
            }
            wait_ge(&g_cnt_h[g], 16u * (unsigned)t);
            LOADA(pcA(g, t, par, pc_ord(0)), 0); CMT;
            LOADA(pcA(g, t, par, pc_ord(1)), 1); CMT;
            float acc[2][4][4];
#pragma unroll
            for (int mi = 0; mi < 2; mi++)
#pragma unroll
                for (int nf = 0; nf < 4; nf++)
#pragma unroll
                    for (int e = 0; e < 4; e++) acc[mi][nf][e] = 0.0f;
            for (int i = 0; i < 16; i++) {
                WAIT1;
                __syncthreads();
                if (i == 10) wait_ge(&g_cnt_cc[g], 16u * (unsigned)(t + 1));
                if (i + 2 < 16) {
                    int kc = pc_ord(i + 2);
                    LOADA(pcA(g, t, par, kc), (i + 2) % 3);
                    LOADBPC(Bt0 + (size_t)kc * 4096, Bt1 + (size_t)kc * 4096, (i + 2) % 3);
                }
                CMT;
                int s = i % 3;
                mma128r(SHu + s * STW, SHu + s * STW + 4096, acc, wmB, wnB, lane);
            }
            __syncthreads();
            float* EP = (float*)SHu;
#pragma unroll
            for (int mi = 0; mi < 2; mi++)
#pragma unroll
                for (int nf = 0; nf < 4; nf++)
#pragma unroll
                    for (int e = 0; e < 4; e++) {
                        int r = wmB * 32 + mi * 16 + gid + ((e >> 1) << 3);
                        int v = wnB * 32 + nf * 8 + 2 * tg + (e & 1);
                        EP[r * EPIT + v] = acc[mi][nf][e];
                    }
            __syncthreads();
#pragma unroll
            for (int q = 0; q < 8; q++) {
                int idx = tid + q * 256;
                int r = idx >> 5, jl = idx & 31;
                int b = b0 + r;
                int j = j0 + jl;
                float ia = EP[r * EPIT + jl * 4 + 0] + g_bg[j * 4 + 0];
                float fa = EP[r * EPIT + jl * 4 + 1] + g_bg[j * 4 + 1];
                float ga = EP[r * EPIT + jl * 4 + 2] + g_bg[j * 4 + 2];
                float oa = EP[r * EPIT + jl * 4 + 3] + g_bg[j * 4 + 3];
                int ci = b * Hn + j;
                float cn = sigmoidf_(fa) * cst_r[q] + sigmoidf_(ia) * tanhf(ga);
                float hn = sigmoidf_(oa) * tanhf(cn);
                g_cst[ci] = cn;
                if (t + 1 < Tn) {
                    g_hq[(((size_t)nxt * 4 + g) * 8 + (j >> 6)) * 4096 + o_A(r, j & 63)] =
                        f2tf(hn * gam_r[q]);
                } else {
                    out[BTF + ci] = hn;
                }
            }
            arrive(&g_cnt_h[g]);
        }
    }

    gsync(sense);

    // =================== final loss reduction + counter reset ===================
    if (cta == 0) {
        float v = 0.0f;
        if (tid < Tn) {
            float den = 1e-9f, n1 = 0.f, n2 = 0.f, n3 = 0.f;
            for (int c2 = 0; c2 < 64; c2++) {
                den += g_den[tid * 64 + c2];
                n1 += g_l1[tid * 64 + c2];
                n2 += g_l2[tid * 64 + c2];
                n3 += g_l3[tid * 64 + c2];
            }
            v = (n1 + n2 + n3) / den;
        }
        __syncthreads();
        RED[tid] = v;
        __syncthreads();
#pragma unroll
        for (int s = 128; s > 0; s >>= 1) {
            if (tid < s) RED[tid] += RED[tid + s];
            __syncthreads();
        }
        if (tid == 0) {
            out[BTF + Bn * Hn] = RED[0] / (3.0f * Tn);
#pragma unroll
            for (int i = 0; i < 4; i++) { g_cnt_h[i] = 0u; g_cnt_xh[i] = 0u; g_cnt_cc[i] = 0u; }
            __threadfence();
        }
    }
}

extern "C" void kernel_launch(void* const* d_in, const int* in_sizes, int n_in,
                              void* d_out, int out_size) {
    (void)in_sizes; (void)n_in; (void)out_size;
    static int configured = 0;
    if (!configured) {
        cudaFuncSetAttribute(rits_kernel, cudaFuncAttributeMaxDynamicSharedMemorySize,
                             SMEM_BYTES);
        configured = 1;
    }
    rits_kernel<<<NB, NT, SMEM_BYTES>>>(
        (const float*)d_in[0],  (const float*)d_in[1],  (const float*)d_in[2],
        (const float*)d_in[3],  (const float*)d_in[4],  (const float*)d_in[5],
        (const float*)d_in[6],  (const float*)d_in[7],  (const float*)d_in[8],
        (const float*)d_in[9],  (const float*)d_in[10], (const float*)d_in[11],
        (const float*)d_in[12], (const float*)d_in[13], (const float*)d_in[14],
        (const float*)d_in[15], (const float*)d_in[16],
        (float*)d_out);
}